// round 12
// baseline (speedup 1.0000x reference)
#include <cuda_runtime.h>

#define KNN   20
#define BB    8
#define NN    4096
#define PT    (BB * NN)          /* 32768  points */
#define ET    (PT * KNN)         /* 655360 edges  */
#define EPSBN 1e-5f
#define NBANK 16

// ---------------------------------------------------------------------------
// Static device scratch (no allocations anywhere)
// ---------------------------------------------------------------------------
static __device__ float  g_feat3[PT * 3];
static __device__ float  g_xx[PT];
static __device__ float  g_dist[(size_t)PT * NN];        // 512 MB
static __device__ int    g_idx[ET];
static __device__ float  g_hA[(size_t)ET * 64];          // 160 MB
static __device__ float  g_hB[(size_t)ET * 64];          // 160 MB
static __device__ float  g_x1[PT * 64];
static __device__ float  g_x2[PT * 64];
static __device__ float  g_x3[PT * 64];
static __device__ float  g_h7[(size_t)PT * 512];
static __device__ float  g_h8[(size_t)PT * 256];
static __device__ unsigned g_hmaxU[BB * 1024];
static __device__ unsigned g_hminU[BB * 1024];
static __device__ float  g_gmax[BB * 1024];
static __device__ float  g_gcorr[BB * 512];
static __device__ double g_sumB[NBANK * 8 * 1024];       // banked stats
static __device__ double g_sumsqB[NBANK * 8 * 1024];
static __device__ float  g_scale[8 * 1024];
static __device__ float  g_bias[8 * 1024];

__device__ __forceinline__ float lrelu(float v) { return v > 0.f ? v : 0.2f * v; }

// monotone float -> unsigned transform (preserves total order)
__device__ __forceinline__ unsigned ford(float f) {
    unsigned u = __float_as_uint(f);
    return (u & 0x80000000u) ? ~u : (u | 0x80000000u);
}
__device__ __forceinline__ float unford(unsigned u) {
    return (u & 0x80000000u) ? __uint_as_float(u & 0x7FFFFFFFu)
                             : __uint_as_float(~u);
}

// ---------------------------------------------------------------------------
// Zero BN statistic accumulators + minmax accumulators (graph-replay safe)
// ---------------------------------------------------------------------------
__global__ void k_zero() {
    int t = blockIdx.x * 256 + threadIdx.x;
    if (t < NBANK * 8 * 1024) { g_sumB[t] = 0.0; g_sumsqB[t] = 0.0; }
    if (t < BB * 1024) { g_hmaxU[t] = 0u; g_hminU[t] = 0xFFFFFFFFu; }
}

// ---------------------------------------------------------------------------
// Transpose x [B,3,N] -> feat3 [P,3] and squared norms
// ---------------------------------------------------------------------------
__global__ void k_prep3(const float* __restrict__ x) {
    int p = blockIdx.x * 256 + threadIdx.x;
    if (p >= PT) return;
    int b = p >> 12, n = p & (NN - 1);
    const float* xb = x + (size_t)b * 3 * NN;
    float a0 = xb[n], a1 = xb[NN + n], a2 = xb[2 * NN + n];
    g_feat3[p * 3 + 0] = a0;
    g_feat3[p * 3 + 1] = a1;
    g_feat3[p * 3 + 2] = a2;
    g_xx[p] = a0 * a0 + a1 * a1 + a2 * a2;
}

// squared norms of [P,64] feature arrays; warp per row
__global__ void k_xx64(int sel) {
    const float* f = (sel == 1) ? g_x1 : g_x2;
    int gt = blockIdx.x * 256 + threadIdx.x;
    int w = gt >> 5, lane = gt & 31;
    if (w >= PT) return;
    const float* r = f + ((size_t)w << 6);
    float v0 = r[lane], v1 = r[lane + 32];
    float s = v0 * v0 + v1 * v1;
#pragma unroll
    for (int o = 16; o; o >>= 1) s += __shfl_down_sync(0xffffffffu, s, o);
    if (lane == 0) g_xx[w] = s;
}

// ---------------------------------------------------------------------------
// Pairwise neg. squared distance, C=64, SYMMETRIC upper-triangle tiles.
// One batch per launch (param b) for dist->topk L2 reuse.
// grid (528), 256 threads, 8x8 per thread, k-sliced 16
// ---------------------------------------------------------------------------
__global__ __launch_bounds__(256) void k_dist128sym(int sel, int b) {
    __shared__ __align__(16) float As[16][132];
    __shared__ __align__(16) float Bs[16][132];
    __shared__ float sxi[128], sxj[128];
    const float* f = (sel == 1) ? g_x1 : g_x2;
    int rem = blockIdx.x, ti = 0;
    while (rem >= 32 - ti) { rem -= 32 - ti; ti++; }
    int tj = ti + rem;
    int i0 = ti << 7, j0 = tj << 7;
    int tid = threadIdx.x, tx = tid & 15, ty = tid >> 4;
    int r8 = ty << 3, c8 = tx << 3;
    int bi = b * NN + i0, bj = b * NN + j0;
    if (tid < 128) sxi[tid] = g_xx[bi + tid];
    else           sxj[tid - 128] = g_xx[bj + tid - 128];
    float acc[8][8] = {};
    for (int k0 = 0; k0 < 64; k0 += 16) {
        __syncthreads();
#pragma unroll
        for (int l = tid; l < 512; l += 256) {
            int r = l >> 2, kq = (l & 3) << 2;
            float4 av = *(const float4*)&f[(size_t)(bi + r) * 64 + k0 + kq];
            As[kq + 0][r] = av.x; As[kq + 1][r] = av.y;
            As[kq + 2][r] = av.z; As[kq + 3][r] = av.w;
            float4 bv = *(const float4*)&f[(size_t)(bj + r) * 64 + k0 + kq];
            Bs[kq + 0][r] = bv.x; Bs[kq + 1][r] = bv.y;
            Bs[kq + 2][r] = bv.z; Bs[kq + 3][r] = bv.w;
        }
        __syncthreads();
#pragma unroll
        for (int k = 0; k < 16; k++) {
            float a[8], bb[8];
            *(float4*)&a[0]  = *(const float4*)&As[k][r8];
            *(float4*)&a[4]  = *(const float4*)&As[k][r8 + 4];
            *(float4*)&bb[0] = *(const float4*)&Bs[k][c8];
            *(float4*)&bb[4] = *(const float4*)&Bs[k][c8 + 4];
#pragma unroll
            for (int ii = 0; ii < 8; ii++)
#pragma unroll
                for (int jj = 0; jj < 8; jj++)
                    acc[ii][jj] = fmaf(a[ii], bb[jj], acc[ii][jj]);
        }
    }
    // i-rows: dist[i,j] = (2*acc - xxi) - xxj
#pragma unroll
    for (int ii = 0; ii < 8; ii++) {
        float xi = sxi[r8 + ii];
        float o[8];
#pragma unroll
        for (int jj = 0; jj < 8; jj++)
            o[jj] = 2.f * acc[ii][jj] - xi - sxj[c8 + jj];
        float* dst = &g_dist[(size_t)(b * NN + i0 + r8 + ii) * NN + j0 + c8];
        *(float4*)&dst[0] = *(float4*)&o[0];
        *(float4*)&dst[4] = *(float4*)&o[4];
    }
    // j-rows (transposed): dist[j,i] = (2*acc - xxj) - xxi  (row norm FIRST)
    if (ti != tj) {
#pragma unroll
        for (int jj = 0; jj < 8; jj++) {
            float xj = sxj[c8 + jj];
            float o[8];
#pragma unroll
            for (int ii = 0; ii < 8; ii++)
                o[ii] = 2.f * acc[ii][jj] - xj - sxi[r8 + ii];
            float* dst = &g_dist[(size_t)(b * NN + j0 + c8 + jj) * NN + i0 + r8];
            *(float4*)&dst[0] = *(float4*)&o[0];
            *(float4*)&dst[4] = *(float4*)&o[4];
        }
    }
}

// ---------------------------------------------------------------------------
// Top-K: warp-local tournaments + single-warp merge (exact selection).
// ---------------------------------------------------------------------------
__device__ __forceinline__ void topk_phase1(float (&v)[32], int lane, int w,
                                            int wb, unsigned* cvu, int* ci) {
    float curv = v[0];
    int   curp = 0;
#pragma unroll
    for (int i = 1; i < 32; i++)
        if (v[i] > curv) { curv = v[i]; curp = i; }
    unsigned mask = 0u;
    for (int r = 0; r < KNN; r++) {
        unsigned long long key =
            ((unsigned long long)ford(curv) << 32) | (unsigned)(lane * 32 + curp);
#pragma unroll
        for (int o = 16; o; o >>= 1) {
            unsigned long long ok = __shfl_xor_sync(0xffffffffu, key, o);
            if (ok > key) key = ok;
        }
        int ws = (int)(key & 1023u);
        int wlane = ws >> 5, wpos = ws & 31;
        if (lane == r) {
            cvu[w * 20 + r] = (unsigned)(key >> 32);
            ci[w * 20 + r]  = wb + ((wpos >> 2) << 7) + (wlane << 2) + (wpos & 3);
        }
        if (lane == wlane) {
            mask |= 1u << wpos;
            curv = -3.0e38f; curp = 0;
#pragma unroll
            for (int i = 0; i < 32; i++) {
                bool ok = !((mask >> i) & 1u) && (v[i] > curv);
                if (ok) { curv = v[i]; curp = i; }
            }
        }
    }
}

__device__ __forceinline__ void topk_phase2(int row, int lane, unsigned* cvu, int* ci) {
    unsigned uv[3];
#pragma unroll
    for (int u = 0; u < 3; u++) {
        int s = lane + 32 * u;
        uv[u] = (s < 80) ? cvu[s] : 0u;
    }
    unsigned bcur = uv[0]; int bu = 0;
    if (uv[1] > bcur) { bcur = uv[1]; bu = 1; }
    if (uv[2] > bcur) { bcur = uv[2]; bu = 2; }
    for (int r = 0; r < KNN; r++) {
        unsigned long long key =
            ((unsigned long long)bcur << 32) | (unsigned)(lane + 32 * bu);
#pragma unroll
        for (int o = 16; o; o >>= 1) {
            unsigned long long ok = __shfl_xor_sync(0xffffffffu, key, o);
            if (ok > key) key = ok;
        }
        int ws = (int)(key & 127u);
        if (lane == 0) g_idx[(size_t)row * KNN + r] = ci[ws];
        if (lane == (ws & 31)) {
            uv[ws >> 5] = 0u;
            bcur = uv[0]; bu = 0;
            if (uv[1] > bcur) { bcur = uv[1]; bu = 1; }
            if (uv[2] > bcur) { bcur = uv[2]; bu = 2; }
        }
    }
}

// stages 2/3: read precomputed g_dist; one batch per launch (rowbase)
__global__ __launch_bounds__(128) void k_topk(int rowbase) {
    __shared__ unsigned cvu[80];
    __shared__ int      ci[80];
    int row = rowbase + blockIdx.x;
    int tid = threadIdx.x, lane = tid & 31, w = tid >> 5;
    int wb = w * 1024;
    const float4* base = (const float4*)(g_dist + (size_t)row * NN + wb);
    float v[32];
#pragma unroll
    for (int q = 0; q < 8; q++) {
        float4 t4 = base[q * 32 + lane];
        v[4 * q + 0] = t4.x; v[4 * q + 1] = t4.y;
        v[4 * q + 2] = t4.z; v[4 * q + 3] = t4.w;
    }
    topk_phase1(v, lane, w, wb, cvu, ci);
    __syncthreads();
    if (w == 0) topk_phase2(row, lane, cvu, ci);
}

// stage 1: compute 3-D distances inline (no dist matrix round-trip)
__global__ __launch_bounds__(128) void k_topk3() {
    __shared__ unsigned cvu[80];
    __shared__ int      ci[80];
    int row = blockIdx.x;
    int tid = threadIdx.x, lane = tid & 31, w = tid >> 5;
    int b = row >> 12;
    int wb = w * 1024;
    float xi0 = g_feat3[row * 3], xi1 = g_feat3[row * 3 + 1], xi2 = g_feat3[row * 3 + 2];
    float xxi = g_xx[row];
    float v[32];
#pragma unroll
    for (int q = 0; q < 8; q++) {
        int j0 = wb + q * 128 + lane * 4;
        const float4* fp = (const float4*)(g_feat3 + ((size_t)(b * NN) + j0) * 3);
        float4 f0 = fp[0], f1 = fp[1], f2 = fp[2];
        float arr[12] = {f0.x, f0.y, f0.z, f0.w, f1.x, f1.y, f1.z, f1.w,
                         f2.x, f2.y, f2.z, f2.w};
#pragma unroll
        for (int t = 0; t < 4; t++) {
            float a0 = arr[t * 3], a1 = arr[t * 3 + 1], a2 = arr[t * 3 + 2];
            float dot = fmaf(a0, xi0, fmaf(a1, xi1, a2 * xi2));
            float xxj = fmaf(a0, a0, fmaf(a1, a1, a2 * a2));
            v[4 * q + t] = 2.f * dot - xxi - xxj;
        }
    }
    topk_phase1(v, lane, w, wb, cvu, ci);
    __syncthreads();
    if (w == 0) topk_phase2(row, lane, cvu, ci);
}

// ---------------------------------------------------------------------------
// Edge layer 1: gather [xj-xi, xi] (6 dims) @ W1^T -> raw hA [E,64] + stats(0)
// 4 tiles of 64 edges per CTA (amortize weights + stats epilogue)
// ---------------------------------------------------------------------------
__global__ __launch_bounds__(256) void k_edge1(const float* __restrict__ W1) {
    __shared__ __align__(16) float Af[6][68];
    __shared__ __align__(16) float Bw[6][68];
    __shared__ double ssum[64], ssq[64];
    int e00 = blockIdx.x << 8, tid = threadIdx.x;
    if (tid < 64) { ssum[tid] = 0.0; ssq[tid] = 0.0; }
    else if (tid < 128) {
        int o = tid - 64;
#pragma unroll
        for (int c = 0; c < 6; c++) Bw[c][o] = W1[o * 6 + c];
    }
    int tx = tid & 15, ty = tid >> 4;
    int r4 = ty << 2, c4 = tx << 2;
    float tps[4] = {}, tpq[4] = {};
    for (int t = 0; t < 4; t++) {
        int e0 = e00 + (t << 6);
        __syncthreads();
        if (tid < 64) {
            int e = e0 + tid;
            int p = e / KNN;
            int q = (p >> 12) * NN + g_idx[e];
            float p0 = g_feat3[p * 3], p1 = g_feat3[p * 3 + 1], p2 = g_feat3[p * 3 + 2];
            float q0 = g_feat3[q * 3], q1 = g_feat3[q * 3 + 1], q2 = g_feat3[q * 3 + 2];
            Af[0][tid] = q0 - p0; Af[1][tid] = q1 - p1; Af[2][tid] = q2 - p2;
            Af[3][tid] = p0;      Af[4][tid] = p1;      Af[5][tid] = p2;
        }
        __syncthreads();
        float acc[4][4] = {};
#pragma unroll
        for (int k = 0; k < 6; k++) {
            float4 a4 = *(const float4*)&Af[k][r4];
            float4 b4 = *(const float4*)&Bw[k][c4];
            float av[4] = {a4.x, a4.y, a4.z, a4.w};
            float bv[4] = {b4.x, b4.y, b4.z, b4.w};
#pragma unroll
            for (int ii = 0; ii < 4; ii++)
#pragma unroll
                for (int jj = 0; jj < 4; jj++)
                    acc[ii][jj] = fmaf(av[ii], bv[jj], acc[ii][jj]);
        }
#pragma unroll
        for (int ii = 0; ii < 4; ii++)
#pragma unroll
            for (int jj = 0; jj < 4; jj++)
                g_hA[(size_t)(e0 + r4 + ii) * 64 + c4 + jj] = acc[ii][jj];
#pragma unroll
        for (int jj = 0; jj < 4; jj++) {
            float s = 0.f, q = 0.f;
#pragma unroll
            for (int ii = 0; ii < 4; ii++) { float v = acc[ii][jj]; s += v; q = fmaf(v, v, q); }
            tps[jj] += s; tpq[jj] += q;
        }
    }
#pragma unroll
    for (int jj = 0; jj < 4; jj++) {
        tps[jj] += __shfl_down_sync(0xffffffffu, tps[jj], 16);
        tpq[jj] += __shfl_down_sync(0xffffffffu, tpq[jj], 16);
    }
    if ((tid & 31) < 16) {
#pragma unroll
        for (int jj = 0; jj < 4; jj++) {
            atomicAdd(&ssum[c4 + jj], (double)tps[jj]);
            atomicAdd(&ssq[c4 + jj], (double)tpq[jj]);
        }
    }
    __syncthreads();
    if (tid < 64) {
        int bank = (blockIdx.x & (NBANK - 1)) * 8192;
        atomicAdd(&g_sumB[bank + tid], ssum[tid]);
        atomicAdd(&g_sumsqB[bank + tid], ssq[tid]);
    }
}

// ---------------------------------------------------------------------------
// Edge layers 2/4: act_aslot(hA)[E,64] @ W^T[64,64] -> hB + stats(oslot)
// 128-row tile, 8x4 per thread, k-sliced 16
// ---------------------------------------------------------------------------
__global__ __launch_bounds__(256) void k_edge128(const float* __restrict__ W,
                                                 int aslot, int oslot) {
    __shared__ __align__(16) float As[16][132];
    __shared__ __align__(16) float Bs[16][68];
    __shared__ float sS[64], sB[64];
    __shared__ double ssum[64], ssq[64];
    int e0 = blockIdx.x << 7, tid = threadIdx.x;
    if (tid < 64) {
        sS[tid] = g_scale[aslot * 1024 + tid];
        sB[tid] = g_bias[aslot * 1024 + tid];
        ssum[tid] = 0.0; ssq[tid] = 0.0;
    }
    int tx = tid & 15, ty = tid >> 4;
    int r8 = ty << 3, c4 = tx << 2;
    float acc[8][4] = {};
    for (int k0 = 0; k0 < 64; k0 += 16) {
        __syncthreads();
#pragma unroll
        for (int l = tid; l < 512; l += 256) {
            int r = l >> 2, kq = (l & 3) << 2;
            int c = k0 + kq;
            float4 av = *(const float4*)&g_hA[(size_t)(e0 + r) * 64 + c];
            As[kq + 0][r] = lrelu(av.x * sS[c + 0] + sB[c + 0]);
            As[kq + 1][r] = lrelu(av.y * sS[c + 1] + sB[c + 1]);
            As[kq + 2][r] = lrelu(av.z * sS[c + 2] + sB[c + 2]);
            As[kq + 3][r] = lrelu(av.w * sS[c + 3] + sB[c + 3]);
        }
        {
            int r = tid >> 2, kq = (tid & 3) << 2;
            float4 bv = *(const float4*)&W[(size_t)r * 64 + k0 + kq];
            Bs[kq + 0][r] = bv.x; Bs[kq + 1][r] = bv.y;
            Bs[kq + 2][r] = bv.z; Bs[kq + 3][r] = bv.w;
        }
        __syncthreads();
#pragma unroll
        for (int k = 0; k < 16; k++) {
            float a[8], bb[4];
            *(float4*)&a[0]  = *(const float4*)&As[k][r8];
            *(float4*)&a[4]  = *(const float4*)&As[k][r8 + 4];
            *(float4*)&bb[0] = *(const float4*)&Bs[k][c4];
#pragma unroll
            for (int ii = 0; ii < 8; ii++)
#pragma unroll
                for (int jj = 0; jj < 4; jj++)
                    acc[ii][jj] = fmaf(a[ii], bb[jj], acc[ii][jj]);
        }
    }
#pragma unroll
    for (int ii = 0; ii < 8; ii++)
        *(float4*)&g_hB[(size_t)(e0 + r8 + ii) * 64 + c4] = *(float4*)&acc[ii][0];
    float ps[4], pq[4];
#pragma unroll
    for (int jj = 0; jj < 4; jj++) {
        float s = 0.f, q = 0.f;
#pragma unroll
        for (int ii = 0; ii < 8; ii++) { float v = acc[ii][jj]; s += v; q = fmaf(v, v, q); }
        ps[jj] = s; pq[jj] = q;
    }
#pragma unroll
    for (int jj = 0; jj < 4; jj++) {
        ps[jj] += __shfl_down_sync(0xffffffffu, ps[jj], 16);
        pq[jj] += __shfl_down_sync(0xffffffffu, pq[jj], 16);
    }
    if ((tid & 31) < 16) {
#pragma unroll
        for (int jj = 0; jj < 4; jj++) {
            atomicAdd(&ssum[c4 + jj], (double)ps[jj]);
            atomicAdd(&ssq[c4 + jj], (double)pq[jj]);
        }
    }
    __syncthreads();
    if (tid < 64) {
        int bank = (blockIdx.x & (NBANK - 1)) * 8192;
        atomicAdd(&g_sumB[bank + oslot * 1024 + tid], ssum[tid]);
        atomicAdd(&g_sumsqB[bank + oslot * 1024 + tid], ssq[tid]);
    }
}

// ---------------------------------------------------------------------------
// Edge layers 3/5: gathered 128-dim edge feature @ W^T [64,128] -> hA + stats
// 128-row tile, 8x4 per thread, k-sliced 16
// ---------------------------------------------------------------------------
__global__ __launch_bounds__(256) void k_edgeG128(const float* __restrict__ W,
                                                  int srcSel, int oslot) {
    __shared__ __align__(16) float As[16][132];
    __shared__ __align__(16) float Bs[16][68];
    __shared__ int sP[128], sQ[128];
    __shared__ double ssum[64], ssq[64];
    const float* src = (srcSel == 1) ? g_x1 : g_x2;
    int e0 = blockIdx.x << 7, tid = threadIdx.x;
    if (tid < 64) { ssum[tid] = 0.0; ssq[tid] = 0.0; }
    if (tid < 128) {
        int e = e0 + tid;
        int p = e / KNN;
        sP[tid] = p;
        sQ[tid] = (p >> 12) * NN + g_idx[e];
    }
    int tx = tid & 15, ty = tid >> 4;
    int r8 = ty << 3, c4 = tx << 2;
    float acc[8][4] = {};
    for (int k0 = 0; k0 < 128; k0 += 16) {
        __syncthreads();
#pragma unroll
        for (int l = tid; l < 512; l += 256) {
            int r = l >> 2, kq = (l & 3) << 2;
            int c = k0 + kq;
            float4 av;
            if (c < 64) {
                float4 aq = *(const float4*)&src[(size_t)sQ[r] * 64 + c];
                float4 ap = *(const float4*)&src[(size_t)sP[r] * 64 + c];
                av.x = aq.x - ap.x; av.y = aq.y - ap.y;
                av.z = aq.z - ap.z; av.w = aq.w - ap.w;
            } else {
                av = *(const float4*)&src[(size_t)sP[r] * 64 + (c - 64)];
            }
            As[kq + 0][r] = av.x; As[kq + 1][r] = av.y;
            As[kq + 2][r] = av.z; As[kq + 3][r] = av.w;
        }
        {
            int r = tid >> 2, kq = (tid & 3) << 2;
            float4 bv = *(const float4*)&W[(size_t)r * 128 + k0 + kq];
            Bs[kq + 0][r] = bv.x; Bs[kq + 1][r] = bv.y;
            Bs[kq + 2][r] = bv.z; Bs[kq + 3][r] = bv.w;
        }
        __syncthreads();
#pragma unroll
        for (int k = 0; k < 16; k++) {
            float a[8], bb[4];
            *(float4*)&a[0]  = *(const float4*)&As[k][r8];
            *(float4*)&a[4]  = *(const float4*)&As[k][r8 + 4];
            *(float4*)&bb[0] = *(const float4*)&Bs[k][c4];
#pragma unroll
            for (int ii = 0; ii < 8; ii++)
#pragma unroll
                for (int jj = 0; jj < 4; jj++)
                    acc[ii][jj] = fmaf(a[ii], bb[jj], acc[ii][jj]);
        }
    }
#pragma unroll
    for (int ii = 0; ii < 8; ii++)
        *(float4*)&g_hA[(size_t)(e0 + r8 + ii) * 64 + c4] = *(float4*)&acc[ii][0];
    float ps[4], pq[4];
#pragma unroll
    for (int jj = 0; jj < 4; jj++) {
        float s = 0.f, q = 0.f;
#pragma unroll
        for (int ii = 0; ii < 8; ii++) { float v = acc[ii][jj]; s += v; q = fmaf(v, v, q); }
        ps[jj] = s; pq[jj] = q;
    }
#pragma unroll
    for (int jj = 0; jj < 4; jj++) {
        ps[jj] += __shfl_down_sync(0xffffffffu, ps[jj], 16);
        pq[jj] += __shfl_down_sync(0xffffffffu, pq[jj], 16);
    }
    if ((tid & 31) < 16) {
#pragma unroll
        for (int jj = 0; jj < 4; jj++) {
            atomicAdd(&ssum[c4 + jj], (double)ps[jj]);
            atomicAdd(&ssq[c4 + jj], (double)pq[jj]);
        }
    }
    __syncthreads();
    if (tid < 64) {
        int bank = (blockIdx.x & (NBANK - 1)) * 8192;
        atomicAdd(&g_sumB[bank + oslot * 1024 + tid], ssum[tid]);
        atomicAdd(&g_sumsqB[bank + oslot * 1024 + tid], ssq[tid]);
    }
}

// ---------------------------------------------------------------------------
// Point GEMMs, 128x128 tile, 8x8/thread, k-sliced 16. Modes:
//   0: A=[x1,x2,x3](192) @ W6 -> NO store; per-(b,c) raw max/min + stats(5)
//   1: A=[x1,x2,x3](192) @ W7[:,1024:] + gcorr -> h7 (stats slot 6)
//   2: A=act6(h7)(512)   @ W8                  -> h8 (stats slot 7)
// ---------------------------------------------------------------------------
__global__ __launch_bounds__(256) void k_point128(const float* __restrict__ W,
                                                  int Cin, int Cout, int wstride,
                                                  int woff, int mode, int aslot,
                                                  int outSel) {
    __shared__ __align__(16) float As[16][132];
    __shared__ __align__(16) float Bs[16][132];
    __shared__ double ssum[128], ssq[128];
    __shared__ unsigned sMaxU[128], sMinU[128];
    int c0 = blockIdx.x << 7, r0 = blockIdx.y << 7;
    int tid = threadIdx.x, tx = tid & 15, ty = tid >> 4;
    int r8 = ty << 3, c8 = tx << 3;
    int b = r0 >> 12;
    if (tid < 128) {
        ssum[tid] = 0.0; ssq[tid] = 0.0;
        sMaxU[tid] = 0u; sMinU[tid] = 0xFFFFFFFFu;
    }
    float acc[8][8] = {};
    for (int k0 = 0; k0 < Cin; k0 += 16) {
        __syncthreads();
#pragma unroll
        for (int l = tid; l < 512; l += 256) {
            int r = l >> 2, kq = (l & 3) << 2;
            int c = k0 + kq, row = r0 + r;
            float4 av;
            if (mode != 2) {
                const float* sp = (c < 64) ? &g_x1[(size_t)row * 64 + c]
                               : (c < 128) ? &g_x2[(size_t)row * 64 + (c - 64)]
                                           : &g_x3[(size_t)row * 64 + (c - 128)];
                av = *(const float4*)sp;
            } else {
                av = *(const float4*)&g_h7[(size_t)row * 512 + c];
                av.x = lrelu(av.x * g_scale[aslot * 1024 + c + 0] + g_bias[aslot * 1024 + c + 0]);
                av.y = lrelu(av.y * g_scale[aslot * 1024 + c + 1] + g_bias[aslot * 1024 + c + 1]);
                av.z = lrelu(av.z * g_scale[aslot * 1024 + c + 2] + g_bias[aslot * 1024 + c + 2]);
                av.w = lrelu(av.w * g_scale[aslot * 1024 + c + 3] + g_bias[aslot * 1024 + c + 3]);
            }
            As[kq + 0][r] = av.x; As[kq + 1][r] = av.y;
            As[kq + 2][r] = av.z; As[kq + 3][r] = av.w;
            float4 bv = *(const float4*)&W[(size_t)(c0 + r) * wstride + woff + k0 + kq];
            Bs[kq + 0][r] = bv.x; Bs[kq + 1][r] = bv.y;
            Bs[kq + 2][r] = bv.z; Bs[kq + 3][r] = bv.w;
        }
        __syncthreads();
#pragma unroll
        for (int k = 0; k < 16; k++) {
            float a[8], bb[8];
            *(float4*)&a[0]  = *(const float4*)&As[k][r8];
            *(float4*)&a[4]  = *(const float4*)&As[k][r8 + 4];
            *(float4*)&bb[0] = *(const float4*)&Bs[k][c8];
            *(float4*)&bb[4] = *(const float4*)&Bs[k][c8 + 4];
#pragma unroll
            for (int ii = 0; ii < 8; ii++)
#pragma unroll
                for (int jj = 0; jj < 8; jj++)
                    acc[ii][jj] = fmaf(a[ii], bb[jj], acc[ii][jj]);
        }
    }
    if (mode == 1) {
#pragma unroll
        for (int jj = 0; jj < 8; jj++) {
            float gc = g_gcorr[b * 512 + c0 + c8 + jj];
#pragma unroll
            for (int ii = 0; ii < 8; ii++) acc[ii][jj] += gc;
        }
    }
    if (outSel != 0) {
        float* out = (outSel == 1) ? g_h7 : g_h8;
#pragma unroll
        for (int ii = 0; ii < 8; ii++) {
            float* dst = &out[(size_t)(r0 + r8 + ii) * Cout + c0 + c8];
            *(float4*)&dst[0] = *(float4*)&acc[ii][0];
            *(float4*)&dst[4] = *(float4*)&acc[ii][4];
        }
    }
    int slot = 5 + outSel;
    float ps[8], pq[8];
#pragma unroll
    for (int jj = 0; jj < 8; jj++) {
        float s = 0.f, q = 0.f;
#pragma unroll
        for (int ii = 0; ii < 8; ii++) { float v = acc[ii][jj]; s += v; q = fmaf(v, v, q); }
        ps[jj] = s; pq[jj] = q;
    }
#pragma unroll
    for (int jj = 0; jj < 8; jj++) {
        ps[jj] += __shfl_down_sync(0xffffffffu, ps[jj], 16);
        pq[jj] += __shfl_down_sync(0xffffffffu, pq[jj], 16);
    }
    if ((tid & 31) < 16) {
#pragma unroll
        for (int jj = 0; jj < 8; jj++) {
            atomicAdd(&ssum[c8 + jj], (double)ps[jj]);
            atomicAdd(&ssq[c8 + jj], (double)pq[jj]);
        }
    }
    if (outSel == 0) {
        float mx[8], mn[8];
#pragma unroll
        for (int jj = 0; jj < 8; jj++) {
            float a = acc[0][jj], c = acc[0][jj];
#pragma unroll
            for (int ii = 1; ii < 8; ii++) {
                a = fmaxf(a, acc[ii][jj]);
                c = fminf(c, acc[ii][jj]);
            }
            mx[jj] = a; mn[jj] = c;
        }
#pragma unroll
        for (int jj = 0; jj < 8; jj++) {
            mx[jj] = fmaxf(mx[jj], __shfl_down_sync(0xffffffffu, mx[jj], 16));
            mn[jj] = fminf(mn[jj], __shfl_down_sync(0xffffffffu, mn[jj], 16));
        }
        if ((tid & 31) < 16) {
#pragma unroll
            for (int jj = 0; jj < 8; jj++) {
                atomicMax(&sMaxU[c8 + jj], ford(mx[jj]));
                atomicMin(&sMinU[c8 + jj], ford(mn[jj]));
            }
        }
    }
    __syncthreads();
    if (tid < 128) {
        int bank = (blockIdx.y & (NBANK - 1)) * 8192;
        atomicAdd(&g_sumB[bank + slot * 1024 + c0 + tid], ssum[tid]);
        atomicAdd(&g_sumsqB[bank + slot * 1024 + c0 + tid], ssq[tid]);
        if (outSel == 0) {
            atomicMax(&g_hmaxU[b * 1024 + c0 + tid], sMaxU[tid]);
            atomicMin(&g_hminU[b * 1024 + c0 + tid], sMinU[tid]);
        }
    }
}

// gmax[b,c] = lrelu(sc * (sc>=0 ? hmax : hmin) + bi)   (monotone pooling)
__global__ void k_gmaxfin() {
    int t = blockIdx.x * 256 + threadIdx.x;
    if (t >= BB * 1024) return;
    int c = t & 1023;
    float sc = g_scale[5 * 1024 + c], bi = g_bias[5 * 1024 + c];
    unsigned u = (sc >= 0.f) ? g_hmaxU[t] : g_hminU[t];
    g_gmax[t] = lrelu(sc * unford(u) + bi);
}

// gcorr[b,o] = sum_c gmax[b,c] * W7[o,c]  (c < 1024); warp per output
__global__ void k_gcorr(const float* __restrict__ W7) {
    int b = blockIdx.y;
    int o = blockIdx.x * 8 + (threadIdx.x >> 5);
    int lane = threadIdx.x & 31;
    const float* gm = g_gmax + b * 1024;
    const float* w  = W7 + (size_t)o * 1216;
    float s = 0.f;
#pragma unroll 8
    for (int k = lane; k < 1024; k += 32) s = fmaf(gm[k], w[k], s);
#pragma unroll
    for (int off = 16; off; off >>= 1) s += __shfl_down_sync(0xffffffffu, s, off);
    if (lane == 0) g_gcorr[b * 512 + o] = s;
}

// fold (gamma, beta, mean, var) -> per-channel scale/bias (sums 16 banks)
__global__ void k_fin(int slot, int C, double invM,
                      const float* __restrict__ g, const float* __restrict__ b) {
    int c = blockIdx.x * 256 + threadIdx.x;
    if (c >= C) return;
    double sm = 0.0, sq = 0.0;
#pragma unroll
    for (int k = 0; k < NBANK; k++) {
        sm += g_sumB[k * 8192 + slot * 1024 + c];
        sq += g_sumsqB[k * 8192 + slot * 1024 + c];
    }
    double mean = sm * invM;
    double var  = sq * invM - mean * mean;
    float sc    = g[c] * rsqrtf((float)var + EPSBN);
    g_scale[slot * 1024 + c] = sc;
    g_bias[slot * 1024 + c]  = b[c] - (float)mean * sc;
}

// ---------------------------------------------------------------------------
// Max over k edges of act_slot(h) -> x{1,2,3}[P,64]
// ---------------------------------------------------------------------------
__global__ void k_maxe(int inSel, int slot, int outSel) {
    const float* h = (inSel == 0) ? g_hA : g_hB;
    float* out = (outSel == 1) ? g_x1 : (outSel == 2 ? g_x2 : g_x3);
    int t = blockIdx.x * 256 + threadIdx.x;
    if (t >= PT * 64) return;
    int p = t >> 6, c = t & 63;
    float sc = g_scale[slot * 1024 + c], bi = g_bias[slot * 1024 + c];
    const float* base = h + ((size_t)p * KNN) * 64 + c;
    float m = -3.0e38f;
#pragma unroll
    for (int j = 0; j < KNN; j++) {
        float v = lrelu(base[j * 64] * sc + bi);
        m = fmaxf(m, v);
    }
    out[t] = m;
}

// ---------------------------------------------------------------------------
// Final: out[P,9] = act7(h8) @ W9^T
// ---------------------------------------------------------------------------
__global__ void k_out9(const float* __restrict__ W9, float* __restrict__ out) {
    int t = blockIdx.x * 256 + threadIdx.x;
    if (t >= PT * 9) return;
    int p = t / 9, o = t - p * 9;
    const float* row = g_h8 + (size_t)p * 256;
    const float* w   = W9 + o * 256;
    float acc = 0.f;
#pragma unroll 4
    for (int k = 0; k < 256; k++) {
        float v = lrelu(row[k] * g_scale[7 * 1024 + k] + g_bias[7 * 1024 + k]);
        acc = fmaf(v, w[k], acc);
    }
    out[t] = acc;
}

// ---------------------------------------------------------------------------
// Host launcher
// ---------------------------------------------------------------------------
extern "C" void kernel_launch(void* const* d_in, const int* in_sizes, int n_in,
                              void* d_out, int out_size) {
    int base = (in_sizes[1] == 1) ? 2 : 1;
    const float* x = (const float*)d_in[0];
    const float* W[9];
    const float* G[8];
    const float* Bt[8];
    for (int i = 0; i < 9; i++) W[i] = (const float*)d_in[base + i];
    for (int i = 0; i < 8; i++) {
        G[i]  = (const float*)d_in[base + 9 + 2 * i];
        Bt[i] = (const float*)d_in[base + 10 + 2 * i];
    }
    float* out = (float*)d_out;

    const double invE = 1.0 / (double)ET;
    const double invP = 1.0 / (double)PT;

    k_zero<<<(NBANK * 8 * 1024) / 256, 256>>>();
    k_prep3<<<PT / 256, 256>>>(x);

    // ---- stage 1: fused knn on xyz, edge layers 1-2, maxpool -> x1 ----
    k_topk3<<<PT, 128>>>();
    k_edge1<<<ET / 256, 256>>>(W[0]);
    k_fin<<<1, 256>>>(0, 64, invE, G[0], Bt[0]);
    k_edge128<<<ET / 128, 256>>>(W[1], 0, 1);
    k_fin<<<1, 256>>>(1, 64, invE, G[1], Bt[1]);
    k_maxe<<<PT * 64 / 256, 256>>>(1, 1, 1);

    // ---- stage 2: knn on x1 (per-batch dist->topk for L2 reuse) ----
    k_xx64<<<PT * 32 / 256, 256>>>(1);
    for (int b = 0; b < BB; b++) {
        k_dist128sym<<<528, 256>>>(1, b);
        k_topk<<<NN, 128>>>(b * NN);
    }
    k_edgeG128<<<ET / 128, 256>>>(W[2], 1, 2);
    k_fin<<<1, 256>>>(2, 64, invE, G[2], Bt[2]);
    k_edge128<<<ET / 128, 256>>>(W[3], 2, 3);
    k_fin<<<1, 256>>>(3, 64, invE, G[3], Bt[3]);
    k_maxe<<<PT * 64 / 256, 256>>>(1, 3, 2);

    // ---- stage 3: knn on x2 (per-batch), edge layer 5, maxpool -> x3 ----
    k_xx64<<<PT * 32 / 256, 256>>>(2);
    for (int b = 0; b < BB; b++) {
        k_dist128sym<<<528, 256>>>(2, b);
        k_topk<<<NN, 128>>>(b * NN);
    }
    k_edgeG128<<<ET / 128, 256>>>(W[4], 2, 4);
    k_fin<<<1, 256>>>(4, 64, invE, G[4], Bt[4]);
    k_maxe<<<PT * 64 / 256, 256>>>(0, 4, 3);

    // ---- point layers 6-9 ----
    k_point128<<<dim3(8, PT / 128), 256>>>(W[5], 192, 1024, 192, 0, 0, 0, 0);
    k_fin<<<4, 256>>>(5, 1024, invP, G[5], Bt[5]);
    k_gmaxfin<<<32, 256>>>();
    k_gcorr<<<dim3(64, BB), 256>>>(W[6]);
    k_point128<<<dim3(4, PT / 128), 256>>>(W[6], 192, 512, 1216, 1024, 1, 0, 1);
    k_fin<<<2, 256>>>(6, 512, invP, G[6], Bt[6]);
    k_point128<<<dim3(2, PT / 128), 256>>>(W[7], 512, 256, 512, 0, 2, 6, 2);
    k_fin<<<1, 256>>>(7, 256, invP, G[7], Bt[7]);
    k_out9<<<(PT * 9 + 255) / 256, 256>>>(W[8], out);
}

// round 13
// speedup vs baseline: 1.0482x; 1.0482x over previous
#include <cuda_runtime.h>

#define KNN   20
#define BB    8
#define NN    4096
#define PT    (BB * NN)          /* 32768  points */
#define ET    (PT * KNN)         /* 655360 edges  */
#define EPSBN 1e-5f
#define NBANK 16

// ---------------------------------------------------------------------------
// Static device scratch (no allocations anywhere)
// ---------------------------------------------------------------------------
static __device__ float  g_feat3[PT * 3];
static __device__ float  g_xx[PT];
static __device__ float  g_dist[(size_t)PT * NN];        // 512 MB
static __device__ int    g_idx[ET];
static __device__ float  g_hA[(size_t)ET * 64];          // 160 MB
static __device__ float  g_hB[(size_t)ET * 64];          // 160 MB
static __device__ float  g_x1[PT * 64];
static __device__ float  g_x2[PT * 64];
static __device__ float  g_x3[PT * 64];
static __device__ float  g_h7[(size_t)PT * 512];
static __device__ float  g_h8[(size_t)PT * 256];
static __device__ unsigned g_hmaxU[BB * 1024];
static __device__ unsigned g_hminU[BB * 1024];
static __device__ float  g_gmax[BB * 1024];
static __device__ float  g_gcorr[BB * 512];
static __device__ double g_sumB[NBANK * 8 * 1024];       // banked stats
static __device__ double g_sumsqB[NBANK * 8 * 1024];
static __device__ float  g_scale[8 * 1024];
static __device__ float  g_bias[8 * 1024];

__device__ __forceinline__ float lrelu(float v) { return v > 0.f ? v : 0.2f * v; }

// monotone float -> unsigned transform (preserves total order)
__device__ __forceinline__ unsigned ford(float f) {
    unsigned u = __float_as_uint(f);
    return (u & 0x80000000u) ? ~u : (u | 0x80000000u);
}
__device__ __forceinline__ float unford(unsigned u) {
    return (u & 0x80000000u) ? __uint_as_float(u & 0x7FFFFFFFu)
                             : __uint_as_float(~u);
}

// ---------------------------------------------------------------------------
// Zero BN statistic accumulators + minmax accumulators (graph-replay safe)
// ---------------------------------------------------------------------------
__global__ void k_zero() {
    int t = blockIdx.x * 256 + threadIdx.x;
    if (t < NBANK * 8 * 1024) { g_sumB[t] = 0.0; g_sumsqB[t] = 0.0; }
    if (t < BB * 1024) { g_hmaxU[t] = 0u; g_hminU[t] = 0xFFFFFFFFu; }
}

// ---------------------------------------------------------------------------
// Transpose x [B,3,N] -> feat3 [P,3] and squared norms
// ---------------------------------------------------------------------------
__global__ void k_prep3(const float* __restrict__ x) {
    int p = blockIdx.x * 256 + threadIdx.x;
    if (p >= PT) return;
    int b = p >> 12, n = p & (NN - 1);
    const float* xb = x + (size_t)b * 3 * NN;
    float a0 = xb[n], a1 = xb[NN + n], a2 = xb[2 * NN + n];
    g_feat3[p * 3 + 0] = a0;
    g_feat3[p * 3 + 1] = a1;
    g_feat3[p * 3 + 2] = a2;
    g_xx[p] = a0 * a0 + a1 * a1 + a2 * a2;
}

// squared norms of [P,64] feature arrays; warp per row
__global__ void k_xx64(int sel) {
    const float* f = (sel == 1) ? g_x1 : g_x2;
    int gt = blockIdx.x * 256 + threadIdx.x;
    int w = gt >> 5, lane = gt & 31;
    if (w >= PT) return;
    const float* r = f + ((size_t)w << 6);
    float v0 = r[lane], v1 = r[lane + 32];
    float s = v0 * v0 + v1 * v1;
#pragma unroll
    for (int o = 16; o; o >>= 1) s += __shfl_down_sync(0xffffffffu, s, o);
    if (lane == 0) g_xx[w] = s;
}

// ---------------------------------------------------------------------------
// Pairwise neg. squared distance, C=64, SYMMETRIC upper-triangle tiles.
// grid (528, B), 256 threads, 8x8 per thread, k-sliced 16
// ---------------------------------------------------------------------------
__global__ __launch_bounds__(256) void k_dist128sym(int sel) {
    __shared__ __align__(16) float As[16][132];
    __shared__ __align__(16) float Bs[16][132];
    __shared__ float sxi[128], sxj[128];
    const float* f = (sel == 1) ? g_x1 : g_x2;
    int b = blockIdx.y;
    int rem = blockIdx.x, ti = 0;
    while (rem >= 32 - ti) { rem -= 32 - ti; ti++; }
    int tj = ti + rem;
    int i0 = ti << 7, j0 = tj << 7;
    int tid = threadIdx.x, tx = tid & 15, ty = tid >> 4;
    int r8 = ty << 3, c8 = tx << 3;
    int bi = b * NN + i0, bj = b * NN + j0;
    if (tid < 128) sxi[tid] = g_xx[bi + tid];
    else           sxj[tid - 128] = g_xx[bj + tid - 128];
    float acc[8][8] = {};
    for (int k0 = 0; k0 < 64; k0 += 16) {
        __syncthreads();
#pragma unroll
        for (int l = tid; l < 512; l += 256) {
            int r = l >> 2, kq = (l & 3) << 2;
            float4 av = *(const float4*)&f[(size_t)(bi + r) * 64 + k0 + kq];
            As[kq + 0][r] = av.x; As[kq + 1][r] = av.y;
            As[kq + 2][r] = av.z; As[kq + 3][r] = av.w;
            float4 bv = *(const float4*)&f[(size_t)(bj + r) * 64 + k0 + kq];
            Bs[kq + 0][r] = bv.x; Bs[kq + 1][r] = bv.y;
            Bs[kq + 2][r] = bv.z; Bs[kq + 3][r] = bv.w;
        }
        __syncthreads();
#pragma unroll
        for (int k = 0; k < 16; k++) {
            float a[8], bb[8];
            *(float4*)&a[0]  = *(const float4*)&As[k][r8];
            *(float4*)&a[4]  = *(const float4*)&As[k][r8 + 4];
            *(float4*)&bb[0] = *(const float4*)&Bs[k][c8];
            *(float4*)&bb[4] = *(const float4*)&Bs[k][c8 + 4];
#pragma unroll
            for (int ii = 0; ii < 8; ii++)
#pragma unroll
                for (int jj = 0; jj < 8; jj++)
                    acc[ii][jj] = fmaf(a[ii], bb[jj], acc[ii][jj]);
        }
    }
    // i-rows: dist[i,j] = (2*acc - xxi) - xxj
#pragma unroll
    for (int ii = 0; ii < 8; ii++) {
        float xi = sxi[r8 + ii];
        float o[8];
#pragma unroll
        for (int jj = 0; jj < 8; jj++)
            o[jj] = 2.f * acc[ii][jj] - xi - sxj[c8 + jj];
        float* dst = &g_dist[(size_t)(b * NN + i0 + r8 + ii) * NN + j0 + c8];
        *(float4*)&dst[0] = *(float4*)&o[0];
        *(float4*)&dst[4] = *(float4*)&o[4];
    }
    // j-rows (transposed): dist[j,i] = (2*acc - xxj) - xxi  (row norm FIRST)
    if (ti != tj) {
#pragma unroll
        for (int jj = 0; jj < 8; jj++) {
            float xj = sxj[c8 + jj];
            float o[8];
#pragma unroll
            for (int ii = 0; ii < 8; ii++)
                o[ii] = 2.f * acc[ii][jj] - xj - sxi[r8 + ii];
            float* dst = &g_dist[(size_t)(b * NN + j0 + c8 + jj) * NN + i0 + r8];
            *(float4*)&dst[0] = *(float4*)&o[0];
            *(float4*)&dst[4] = *(float4*)&o[4];
        }
    }
}

// ---------------------------------------------------------------------------
// Top-K: warp-local tournaments + single-warp merge (exact selection).
// ---------------------------------------------------------------------------
__device__ __forceinline__ void topk_phase1(float (&v)[32], int lane, int w,
                                            int wb, unsigned* cvu, int* ci) {
    float curv = v[0];
    int   curp = 0;
#pragma unroll
    for (int i = 1; i < 32; i++)
        if (v[i] > curv) { curv = v[i]; curp = i; }
    unsigned mask = 0u;
    for (int r = 0; r < KNN; r++) {
        unsigned long long key =
            ((unsigned long long)ford(curv) << 32) | (unsigned)(lane * 32 + curp);
#pragma unroll
        for (int o = 16; o; o >>= 1) {
            unsigned long long ok = __shfl_xor_sync(0xffffffffu, key, o);
            if (ok > key) key = ok;
        }
        int ws = (int)(key & 1023u);
        int wlane = ws >> 5, wpos = ws & 31;
        if (lane == r) {
            cvu[w * 20 + r] = (unsigned)(key >> 32);
            ci[w * 20 + r]  = wb + ((wpos >> 2) << 7) + (wlane << 2) + (wpos & 3);
        }
        if (lane == wlane) {
            mask |= 1u << wpos;
            curv = -3.0e38f; curp = 0;
#pragma unroll
            for (int i = 0; i < 32; i++) {
                bool ok = !((mask >> i) & 1u) && (v[i] > curv);
                if (ok) { curv = v[i]; curp = i; }
            }
        }
    }
}

__device__ __forceinline__ void topk_phase2(int row, int lane, unsigned* cvu, int* ci) {
    unsigned uv[3];
#pragma unroll
    for (int u = 0; u < 3; u++) {
        int s = lane + 32 * u;
        uv[u] = (s < 80) ? cvu[s] : 0u;
    }
    unsigned bcur = uv[0]; int bu = 0;
    if (uv[1] > bcur) { bcur = uv[1]; bu = 1; }
    if (uv[2] > bcur) { bcur = uv[2]; bu = 2; }
    for (int r = 0; r < KNN; r++) {
        unsigned long long key =
            ((unsigned long long)bcur << 32) | (unsigned)(lane + 32 * bu);
#pragma unroll
        for (int o = 16; o; o >>= 1) {
            unsigned long long ok = __shfl_xor_sync(0xffffffffu, key, o);
            if (ok > key) key = ok;
        }
        int ws = (int)(key & 127u);
        if (lane == 0) g_idx[(size_t)row * KNN + r] = ci[ws];
        if (lane == (ws & 31)) {
            uv[ws >> 5] = 0u;
            bcur = uv[0]; bu = 0;
            if (uv[1] > bcur) { bcur = uv[1]; bu = 1; }
            if (uv[2] > bcur) { bcur = uv[2]; bu = 2; }
        }
    }
}

// stages 2/3: read precomputed g_dist
__global__ __launch_bounds__(128) void k_topk() {
    __shared__ unsigned cvu[80];
    __shared__ int      ci[80];
    int row = blockIdx.x;
    int tid = threadIdx.x, lane = tid & 31, w = tid >> 5;
    int wb = w * 1024;
    const float4* base = (const float4*)(g_dist + (size_t)row * NN + wb);
    float v[32];
#pragma unroll
    for (int q = 0; q < 8; q++) {
        float4 t4 = base[q * 32 + lane];
        v[4 * q + 0] = t4.x; v[4 * q + 1] = t4.y;
        v[4 * q + 2] = t4.z; v[4 * q + 3] = t4.w;
    }
    topk_phase1(v, lane, w, wb, cvu, ci);
    __syncthreads();
    if (w == 0) topk_phase2(row, lane, cvu, ci);
}

// stage 1: compute 3-D distances inline (no dist matrix round-trip)
__global__ __launch_bounds__(128) void k_topk3() {
    __shared__ unsigned cvu[80];
    __shared__ int      ci[80];
    int row = blockIdx.x;
    int tid = threadIdx.x, lane = tid & 31, w = tid >> 5;
    int b = row >> 12;
    int wb = w * 1024;
    float xi0 = g_feat3[row * 3], xi1 = g_feat3[row * 3 + 1], xi2 = g_feat3[row * 3 + 2];
    float xxi = g_xx[row];
    float v[32];
#pragma unroll
    for (int q = 0; q < 8; q++) {
        int j0 = wb + q * 128 + lane * 4;
        const float4* fp = (const float4*)(g_feat3 + ((size_t)(b * NN) + j0) * 3);
        float4 f0 = fp[0], f1 = fp[1], f2 = fp[2];
        float arr[12] = {f0.x, f0.y, f0.z, f0.w, f1.x, f1.y, f1.z, f1.w,
                         f2.x, f2.y, f2.z, f2.w};
#pragma unroll
        for (int t = 0; t < 4; t++) {
            float a0 = arr[t * 3], a1 = arr[t * 3 + 1], a2 = arr[t * 3 + 2];
            float dot = fmaf(a0, xi0, fmaf(a1, xi1, a2 * xi2));
            float xxj = fmaf(a0, a0, fmaf(a1, a1, a2 * a2));
            v[4 * q + t] = 2.f * dot - xxi - xxj;
        }
    }
    topk_phase1(v, lane, w, wb, cvu, ci);
    __syncthreads();
    if (w == 0) topk_phase2(row, lane, cvu, ci);
}

// ---------------------------------------------------------------------------
// Edge layer 1: gather [xj-xi, xi] (6 dims) @ W1^T -> raw hA [E,64] + stats(0)
// 4 tiles of 64 edges per CTA (amortize weights + stats epilogue)
// ---------------------------------------------------------------------------
__global__ __launch_bounds__(256) void k_edge1(const float* __restrict__ W1) {
    __shared__ __align__(16) float Af[6][68];
    __shared__ __align__(16) float Bw[6][68];
    __shared__ double ssum[64], ssq[64];
    int e00 = blockIdx.x << 8, tid = threadIdx.x;
    if (tid < 64) { ssum[tid] = 0.0; ssq[tid] = 0.0; }
    else if (tid < 128) {
        int o = tid - 64;
#pragma unroll
        for (int c = 0; c < 6; c++) Bw[c][o] = W1[o * 6 + c];
    }
    int tx = tid & 15, ty = tid >> 4;
    int r4 = ty << 2, c4 = tx << 2;
    float tps[4] = {}, tpq[4] = {};
    for (int t = 0; t < 4; t++) {
        int e0 = e00 + (t << 6);
        __syncthreads();
        if (tid < 64) {
            int e = e0 + tid;
            int p = e / KNN;
            int q = (p >> 12) * NN + g_idx[e];
            float p0 = g_feat3[p * 3], p1 = g_feat3[p * 3 + 1], p2 = g_feat3[p * 3 + 2];
            float q0 = g_feat3[q * 3], q1 = g_feat3[q * 3 + 1], q2 = g_feat3[q * 3 + 2];
            Af[0][tid] = q0 - p0; Af[1][tid] = q1 - p1; Af[2][tid] = q2 - p2;
            Af[3][tid] = p0;      Af[4][tid] = p1;      Af[5][tid] = p2;
        }
        __syncthreads();
        float acc[4][4] = {};
#pragma unroll
        for (int k = 0; k < 6; k++) {
            float4 a4 = *(const float4*)&Af[k][r4];
            float4 b4 = *(const float4*)&Bw[k][c4];
            float av[4] = {a4.x, a4.y, a4.z, a4.w};
            float bv[4] = {b4.x, b4.y, b4.z, b4.w};
#pragma unroll
            for (int ii = 0; ii < 4; ii++)
#pragma unroll
                for (int jj = 0; jj < 4; jj++)
                    acc[ii][jj] = fmaf(av[ii], bv[jj], acc[ii][jj]);
        }
#pragma unroll
        for (int ii = 0; ii < 4; ii++)
#pragma unroll
            for (int jj = 0; jj < 4; jj++)
                g_hA[(size_t)(e0 + r4 + ii) * 64 + c4 + jj] = acc[ii][jj];
#pragma unroll
        for (int jj = 0; jj < 4; jj++) {
            float s = 0.f, q = 0.f;
#pragma unroll
            for (int ii = 0; ii < 4; ii++) { float v = acc[ii][jj]; s += v; q = fmaf(v, v, q); }
            tps[jj] += s; tpq[jj] += q;
        }
    }
#pragma unroll
    for (int jj = 0; jj < 4; jj++) {
        tps[jj] += __shfl_down_sync(0xffffffffu, tps[jj], 16);
        tpq[jj] += __shfl_down_sync(0xffffffffu, tpq[jj], 16);
    }
    if ((tid & 31) < 16) {
#pragma unroll
        for (int jj = 0; jj < 4; jj++) {
            atomicAdd(&ssum[c4 + jj], (double)tps[jj]);
            atomicAdd(&ssq[c4 + jj], (double)tpq[jj]);
        }
    }
    __syncthreads();
    if (tid < 64) {
        int bank = (blockIdx.x & (NBANK - 1)) * 8192;
        atomicAdd(&g_sumB[bank + tid], ssum[tid]);
        atomicAdd(&g_sumsqB[bank + tid], ssq[tid]);
    }
}

// ---------------------------------------------------------------------------
// Edge layers 2/4: act_aslot(hA)[E,64] @ W^T[64,64] -> hB + stats(oslot)
// 128-row tile, 8x4 per thread, k-sliced 16
// ---------------------------------------------------------------------------
__global__ __launch_bounds__(256) void k_edge128(const float* __restrict__ W,
                                                 int aslot, int oslot) {
    __shared__ __align__(16) float As[16][132];
    __shared__ __align__(16) float Bs[16][68];
    __shared__ float sS[64], sB[64];
    __shared__ double ssum[64], ssq[64];
    int e0 = blockIdx.x << 7, tid = threadIdx.x;
    if (tid < 64) {
        sS[tid] = g_scale[aslot * 1024 + tid];
        sB[tid] = g_bias[aslot * 1024 + tid];
        ssum[tid] = 0.0; ssq[tid] = 0.0;
    }
    int tx = tid & 15, ty = tid >> 4;
    int r8 = ty << 3, c4 = tx << 2;
    float acc[8][4] = {};
    for (int k0 = 0; k0 < 64; k0 += 16) {
        __syncthreads();
#pragma unroll
        for (int l = tid; l < 512; l += 256) {
            int r = l >> 2, kq = (l & 3) << 2;
            int c = k0 + kq;
            float4 av = *(const float4*)&g_hA[(size_t)(e0 + r) * 64 + c];
            As[kq + 0][r] = lrelu(av.x * sS[c + 0] + sB[c + 0]);
            As[kq + 1][r] = lrelu(av.y * sS[c + 1] + sB[c + 1]);
            As[kq + 2][r] = lrelu(av.z * sS[c + 2] + sB[c + 2]);
            As[kq + 3][r] = lrelu(av.w * sS[c + 3] + sB[c + 3]);
        }
        {
            int r = tid >> 2, kq = (tid & 3) << 2;
            float4 bv = *(const float4*)&W[(size_t)r * 64 + k0 + kq];
            Bs[kq + 0][r] = bv.x; Bs[kq + 1][r] = bv.y;
            Bs[kq + 2][r] = bv.z; Bs[kq + 3][r] = bv.w;
        }
        __syncthreads();
#pragma unroll
        for (int k = 0; k < 16; k++) {
            float a[8], bb[4];
            *(float4*)&a[0]  = *(const float4*)&As[k][r8];
            *(float4*)&a[4]  = *(const float4*)&As[k][r8 + 4];
            *(float4*)&bb[0] = *(const float4*)&Bs[k][c4];
#pragma unroll
            for (int ii = 0; ii < 8; ii++)
#pragma unroll
                for (int jj = 0; jj < 4; jj++)
                    acc[ii][jj] = fmaf(a[ii], bb[jj], acc[ii][jj]);
        }
    }
#pragma unroll
    for (int ii = 0; ii < 8; ii++)
        *(float4*)&g_hB[(size_t)(e0 + r8 + ii) * 64 + c4] = *(float4*)&acc[ii][0];
    float ps[4], pq[4];
#pragma unroll
    for (int jj = 0; jj < 4; jj++) {
        float s = 0.f, q = 0.f;
#pragma unroll
        for (int ii = 0; ii < 8; ii++) { float v = acc[ii][jj]; s += v; q = fmaf(v, v, q); }
        ps[jj] = s; pq[jj] = q;
    }
#pragma unroll
    for (int jj = 0; jj < 4; jj++) {
        ps[jj] += __shfl_down_sync(0xffffffffu, ps[jj], 16);
        pq[jj] += __shfl_down_sync(0xffffffffu, pq[jj], 16);
    }
    if ((tid & 31) < 16) {
#pragma unroll
        for (int jj = 0; jj < 4; jj++) {
            atomicAdd(&ssum[c4 + jj], (double)ps[jj]);
            atomicAdd(&ssq[c4 + jj], (double)pq[jj]);
        }
    }
    __syncthreads();
    if (tid < 64) {
        int bank = (blockIdx.x & (NBANK - 1)) * 8192;
        atomicAdd(&g_sumB[bank + oslot * 1024 + tid], ssum[tid]);
        atomicAdd(&g_sumsqB[bank + oslot * 1024 + tid], ssq[tid]);
    }
}

// ---------------------------------------------------------------------------
// Edge layers 3/5: gathered 128-dim edge feature @ W^T [64,128] -> hA + stats
// 128-row tile, 8x4 per thread, k-sliced 16
// ---------------------------------------------------------------------------
__global__ __launch_bounds__(256) void k_edgeG128(const float* __restrict__ W,
                                                  int srcSel, int oslot) {
    __shared__ __align__(16) float As[16][132];
    __shared__ __align__(16) float Bs[16][68];
    __shared__ int sP[128], sQ[128];
    __shared__ double ssum[64], ssq[64];
    const float* src = (srcSel == 1) ? g_x1 : g_x2;
    int e0 = blockIdx.x << 7, tid = threadIdx.x;
    if (tid < 64) { ssum[tid] = 0.0; ssq[tid] = 0.0; }
    if (tid < 128) {
        int e = e0 + tid;
        int p = e / KNN;
        sP[tid] = p;
        sQ[tid] = (p >> 12) * NN + g_idx[e];
    }
    int tx = tid & 15, ty = tid >> 4;
    int r8 = ty << 3, c4 = tx << 2;
    float acc[8][4] = {};
    for (int k0 = 0; k0 < 128; k0 += 16) {
        __syncthreads();
#pragma unroll
        for (int l = tid; l < 512; l += 256) {
            int r = l >> 2, kq = (l & 3) << 2;
            int c = k0 + kq;
            float4 av;
            if (c < 64) {
                float4 aq = *(const float4*)&src[(size_t)sQ[r] * 64 + c];
                float4 ap = *(const float4*)&src[(size_t)sP[r] * 64 + c];
                av.x = aq.x - ap.x; av.y = aq.y - ap.y;
                av.z = aq.z - ap.z; av.w = aq.w - ap.w;
            } else {
                av = *(const float4*)&src[(size_t)sP[r] * 64 + (c - 64)];
            }
            As[kq + 0][r] = av.x; As[kq + 1][r] = av.y;
            As[kq + 2][r] = av.z; As[kq + 3][r] = av.w;
        }
        {
            int r = tid >> 2, kq = (tid & 3) << 2;
            float4 bv = *(const float4*)&W[(size_t)r * 128 + k0 + kq];
            Bs[kq + 0][r] = bv.x; Bs[kq + 1][r] = bv.y;
            Bs[kq + 2][r] = bv.z; Bs[kq + 3][r] = bv.w;
        }
        __syncthreads();
#pragma unroll
        for (int k = 0; k < 16; k++) {
            float a[8], bb[4];
            *(float4*)&a[0]  = *(const float4*)&As[k][r8];
            *(float4*)&a[4]  = *(const float4*)&As[k][r8 + 4];
            *(float4*)&bb[0] = *(const float4*)&Bs[k][c4];
#pragma unroll
            for (int ii = 0; ii < 8; ii++)
#pragma unroll
                for (int jj = 0; jj < 4; jj++)
                    acc[ii][jj] = fmaf(a[ii], bb[jj], acc[ii][jj]);
        }
    }
#pragma unroll
    for (int ii = 0; ii < 8; ii++)
        *(float4*)&g_hA[(size_t)(e0 + r8 + ii) * 64 + c4] = *(float4*)&acc[ii][0];
    float ps[4], pq[4];
#pragma unroll
    for (int jj = 0; jj < 4; jj++) {
        float s = 0.f, q = 0.f;
#pragma unroll
        for (int ii = 0; ii < 8; ii++) { float v = acc[ii][jj]; s += v; q = fmaf(v, v, q); }
        ps[jj] = s; pq[jj] = q;
    }
#pragma unroll
    for (int jj = 0; jj < 4; jj++) {
        ps[jj] += __shfl_down_sync(0xffffffffu, ps[jj], 16);
        pq[jj] += __shfl_down_sync(0xffffffffu, pq[jj], 16);
    }
    if ((tid & 31) < 16) {
#pragma unroll
        for (int jj = 0; jj < 4; jj++) {
            atomicAdd(&ssum[c4 + jj], (double)ps[jj]);
            atomicAdd(&ssq[c4 + jj], (double)pq[jj]);
        }
    }
    __syncthreads();
    if (tid < 64) {
        int bank = (blockIdx.x & (NBANK - 1)) * 8192;
        atomicAdd(&g_sumB[bank + oslot * 1024 + tid], ssum[tid]);
        atomicAdd(&g_sumsqB[bank + oslot * 1024 + tid], ssq[tid]);
    }
}

// ---------------------------------------------------------------------------
// Point GEMMs, 128x128 tile, 8x8/thread, k-sliced 16. Modes:
//   0: A=[x1,x2,x3](192) @ W6 -> NO store; per-(b,c) raw max/min + stats(5)
//   1: A=[x1,x2,x3](192) @ W7[:,1024:] + gcorr -> h7 (stats slot 6)
//   2: A=act6(h7)(512)   @ W8                  -> h8 (stats slot 7)
// ---------------------------------------------------------------------------
__global__ __launch_bounds__(256) void k_point128(const float* __restrict__ W,
                                                  int Cin, int Cout, int wstride,
                                                  int woff, int mode, int aslot,
                                                  int outSel) {
    __shared__ __align__(16) float As[16][132];
    __shared__ __align__(16) float Bs[16][132];
    __shared__ double ssum[128], ssq[128];
    __shared__ unsigned sMaxU[128], sMinU[128];
    int c0 = blockIdx.x << 7, r0 = blockIdx.y << 7;
    int tid = threadIdx.x, tx = tid & 15, ty = tid >> 4;
    int r8 = ty << 3, c8 = tx << 3;
    int b = r0 >> 12;
    if (tid < 128) {
        ssum[tid] = 0.0; ssq[tid] = 0.0;
        sMaxU[tid] = 0u; sMinU[tid] = 0xFFFFFFFFu;
    }
    float acc[8][8] = {};
    for (int k0 = 0; k0 < Cin; k0 += 16) {
        __syncthreads();
#pragma unroll
        for (int l = tid; l < 512; l += 256) {
            int r = l >> 2, kq = (l & 3) << 2;
            int c = k0 + kq, row = r0 + r;
            float4 av;
            if (mode != 2) {
                const float* sp = (c < 64) ? &g_x1[(size_t)row * 64 + c]
                               : (c < 128) ? &g_x2[(size_t)row * 64 + (c - 64)]
                                           : &g_x3[(size_t)row * 64 + (c - 128)];
                av = *(const float4*)sp;
            } else {
                av = *(const float4*)&g_h7[(size_t)row * 512 + c];
                av.x = lrelu(av.x * g_scale[aslot * 1024 + c + 0] + g_bias[aslot * 1024 + c + 0]);
                av.y = lrelu(av.y * g_scale[aslot * 1024 + c + 1] + g_bias[aslot * 1024 + c + 1]);
                av.z = lrelu(av.z * g_scale[aslot * 1024 + c + 2] + g_bias[aslot * 1024 + c + 2]);
                av.w = lrelu(av.w * g_scale[aslot * 1024 + c + 3] + g_bias[aslot * 1024 + c + 3]);
            }
            As[kq + 0][r] = av.x; As[kq + 1][r] = av.y;
            As[kq + 2][r] = av.z; As[kq + 3][r] = av.w;
            float4 bv = *(const float4*)&W[(size_t)(c0 + r) * wstride + woff + k0 + kq];
            Bs[kq + 0][r] = bv.x; Bs[kq + 1][r] = bv.y;
            Bs[kq + 2][r] = bv.z; Bs[kq + 3][r] = bv.w;
        }
        __syncthreads();
#pragma unroll
        for (int k = 0; k < 16; k++) {
            float a[8], bb[8];
            *(float4*)&a[0]  = *(const float4*)&As[k][r8];
            *(float4*)&a[4]  = *(const float4*)&As[k][r8 + 4];
            *(float4*)&bb[0] = *(const float4*)&Bs[k][c8];
            *(float4*)&bb[4] = *(const float4*)&Bs[k][c8 + 4];
#pragma unroll
            for (int ii = 0; ii < 8; ii++)
#pragma unroll
                for (int jj = 0; jj < 8; jj++)
                    acc[ii][jj] = fmaf(a[ii], bb[jj], acc[ii][jj]);
        }
    }
    if (mode == 1) {
#pragma unroll
        for (int jj = 0; jj < 8; jj++) {
            float gc = g_gcorr[b * 512 + c0 + c8 + jj];
#pragma unroll
            for (int ii = 0; ii < 8; ii++) acc[ii][jj] += gc;
        }
    }
    if (outSel != 0) {
        float* out = (outSel == 1) ? g_h7 : g_h8;
#pragma unroll
        for (int ii = 0; ii < 8; ii++) {
            float* dst = &out[(size_t)(r0 + r8 + ii) * Cout + c0 + c8];
            *(float4*)&dst[0] = *(float4*)&acc[ii][0];
            *(float4*)&dst[4] = *(float4*)&acc[ii][4];
        }
    }
    int slot = 5 + outSel;
    float ps[8], pq[8];
#pragma unroll
    for (int jj = 0; jj < 8; jj++) {
        float s = 0.f, q = 0.f;
#pragma unroll
        for (int ii = 0; ii < 8; ii++) { float v = acc[ii][jj]; s += v; q = fmaf(v, v, q); }
        ps[jj] = s; pq[jj] = q;
    }
#pragma unroll
    for (int jj = 0; jj < 8; jj++) {
        ps[jj] += __shfl_down_sync(0xffffffffu, ps[jj], 16);
        pq[jj] += __shfl_down_sync(0xffffffffu, pq[jj], 16);
    }
    if ((tid & 31) < 16) {
#pragma unroll
        for (int jj = 0; jj < 8; jj++) {
            atomicAdd(&ssum[c8 + jj], (double)ps[jj]);
            atomicAdd(&ssq[c8 + jj], (double)pq[jj]);
        }
    }
    if (outSel == 0) {
        float mx[8], mn[8];
#pragma unroll
        for (int jj = 0; jj < 8; jj++) {
            float a = acc[0][jj], c = acc[0][jj];
#pragma unroll
            for (int ii = 1; ii < 8; ii++) {
                a = fmaxf(a, acc[ii][jj]);
                c = fminf(c, acc[ii][jj]);
            }
            mx[jj] = a; mn[jj] = c;
        }
#pragma unroll
        for (int jj = 0; jj < 8; jj++) {
            mx[jj] = fmaxf(mx[jj], __shfl_down_sync(0xffffffffu, mx[jj], 16));
            mn[jj] = fminf(mn[jj], __shfl_down_sync(0xffffffffu, mn[jj], 16));
        }
        if ((tid & 31) < 16) {
#pragma unroll
            for (int jj = 0; jj < 8; jj++) {
                atomicMax(&sMaxU[c8 + jj], ford(mx[jj]));
                atomicMin(&sMinU[c8 + jj], ford(mn[jj]));
            }
        }
    }
    __syncthreads();
    if (tid < 128) {
        int bank = (blockIdx.y & (NBANK - 1)) * 8192;
        atomicAdd(&g_sumB[bank + slot * 1024 + c0 + tid], ssum[tid]);
        atomicAdd(&g_sumsqB[bank + slot * 1024 + c0 + tid], ssq[tid]);
        if (outSel == 0) {
            atomicMax(&g_hmaxU[b * 1024 + c0 + tid], sMaxU[tid]);
            atomicMin(&g_hminU[b * 1024 + c0 + tid], sMinU[tid]);
        }
    }
}

// gmax[b,c] = lrelu(sc * (sc>=0 ? hmax : hmin) + bi)   (monotone pooling)
__global__ void k_gmaxfin() {
    int t = blockIdx.x * 256 + threadIdx.x;
    if (t >= BB * 1024) return;
    int c = t & 1023;
    float sc = g_scale[5 * 1024 + c], bi = g_bias[5 * 1024 + c];
    unsigned u = (sc >= 0.f) ? g_hmaxU[t] : g_hminU[t];
    g_gmax[t] = lrelu(sc * unford(u) + bi);
}

// gcorr[b,o] = sum_c gmax[b,c] * W7[o,c]  (c < 1024); warp per output
__global__ void k_gcorr(const float* __restrict__ W7) {
    int b = blockIdx.y;
    int o = blockIdx.x * 8 + (threadIdx.x >> 5);
    int lane = threadIdx.x & 31;
    const float* gm = g_gmax + b * 1024;
    const float* w  = W7 + (size_t)o * 1216;
    float s = 0.f;
#pragma unroll 8
    for (int k = lane; k < 1024; k += 32) s = fmaf(gm[k], w[k], s);
#pragma unroll
    for (int off = 16; off; off >>= 1) s += __shfl_down_sync(0xffffffffu, s, off);
    if (lane == 0) g_gcorr[b * 512 + o] = s;
}

// fold (gamma, beta, mean, var) -> per-channel scale/bias (sums 16 banks)
__global__ void k_fin(int slot, int C, double invM,
                      const float* __restrict__ g, const float* __restrict__ b) {
    int c = blockIdx.x * 256 + threadIdx.x;
    if (c >= C) return;
    double sm = 0.0, sq = 0.0;
#pragma unroll
    for (int k = 0; k < NBANK; k++) {
        sm += g_sumB[k * 8192 + slot * 1024 + c];
        sq += g_sumsqB[k * 8192 + slot * 1024 + c];
    }
    double mean = sm * invM;
    double var  = sq * invM - mean * mean;
    float sc    = g[c] * rsqrtf((float)var + EPSBN);
    g_scale[slot * 1024 + c] = sc;
    g_bias[slot * 1024 + c]  = b[c] - (float)mean * sc;
}

// ---------------------------------------------------------------------------
// Max over k edges of act_slot(h) -> x{1,2,3}[P,64]
// ---------------------------------------------------------------------------
__global__ void k_maxe(int inSel, int slot, int outSel) {
    const float* h = (inSel == 0) ? g_hA : g_hB;
    float* out = (outSel == 1) ? g_x1 : (outSel == 2 ? g_x2 : g_x3);
    int t = blockIdx.x * 256 + threadIdx.x;
    if (t >= PT * 64) return;
    int p = t >> 6, c = t & 63;
    float sc = g_scale[slot * 1024 + c], bi = g_bias[slot * 1024 + c];
    const float* base = h + ((size_t)p * KNN) * 64 + c;
    float m = -3.0e38f;
#pragma unroll
    for (int j = 0; j < KNN; j++) {
        float v = lrelu(base[j * 64] * sc + bi);
        m = fmaxf(m, v);
    }
    out[t] = m;
}

// ---------------------------------------------------------------------------
// Final: out[P,9] = act7(h8) @ W9^T
// ---------------------------------------------------------------------------
__global__ void k_out9(const float* __restrict__ W9, float* __restrict__ out) {
    int t = blockIdx.x * 256 + threadIdx.x;
    if (t >= PT * 9) return;
    int p = t / 9, o = t - p * 9;
    const float* row = g_h8 + (size_t)p * 256;
    const float* w   = W9 + o * 256;
    float acc = 0.f;
#pragma unroll 4
    for (int k = 0; k < 256; k++) {
        float v = lrelu(row[k] * g_scale[7 * 1024 + k] + g_bias[7 * 1024 + k]);
        acc = fmaf(v, w[k], acc);
    }
    out[t] = acc;
}

// ---------------------------------------------------------------------------
// Host launcher
// ---------------------------------------------------------------------------
extern "C" void kernel_launch(void* const* d_in, const int* in_sizes, int n_in,
                              void* d_out, int out_size) {
    int base = (in_sizes[1] == 1) ? 2 : 1;
    const float* x = (const float*)d_in[0];
    const float* W[9];
    const float* G[8];
    const float* Bt[8];
    for (int i = 0; i < 9; i++) W[i] = (const float*)d_in[base + i];
    for (int i = 0; i < 8; i++) {
        G[i]  = (const float*)d_in[base + 9 + 2 * i];
        Bt[i] = (const float*)d_in[base + 10 + 2 * i];
    }
    float* out = (float*)d_out;

    const double invE = 1.0 / (double)ET;
    const double invP = 1.0 / (double)PT;

    k_zero<<<(NBANK * 8 * 1024) / 256, 256>>>();
    k_prep3<<<PT / 256, 256>>>(x);

    // ---- stage 1: fused knn on xyz, edge layers 1-2, maxpool -> x1 ----
    k_topk3<<<PT, 128>>>();
    k_edge1<<<ET / 256, 256>>>(W[0]);
    k_fin<<<1, 256>>>(0, 64, invE, G[0], Bt[0]);
    k_edge128<<<ET / 128, 256>>>(W[1], 0, 1);
    k_fin<<<1, 256>>>(1, 64, invE, G[1], Bt[1]);
    k_maxe<<<PT * 64 / 256, 256>>>(1, 1, 1);

    // ---- stage 2: knn on x1, edge layers 3-4, maxpool -> x2 ----
    k_xx64<<<PT * 32 / 256, 256>>>(1);
    k_dist128sym<<<dim3(528, BB), 256>>>(1);
    k_topk<<<PT, 128>>>();
    k_edgeG128<<<ET / 128, 256>>>(W[2], 1, 2);
    k_fin<<<1, 256>>>(2, 64, invE, G[2], Bt[2]);
    k_edge128<<<ET / 128, 256>>>(W[3], 2, 3);
    k_fin<<<1, 256>>>(3, 64, invE, G[3], Bt[3]);
    k_maxe<<<PT * 64 / 256, 256>>>(1, 3, 2);

    // ---- stage 3: knn on x2, edge layer 5, maxpool -> x3 ----
    k_xx64<<<PT * 32 / 256, 256>>>(2);
    k_dist128sym<<<dim3(528, BB), 256>>>(2);
    k_topk<<<PT, 128>>>();
    k_edgeG128<<<ET / 128, 256>>>(W[4], 2, 4);
    k_fin<<<1, 256>>>(4, 64, invE, G[4], Bt[4]);
    k_maxe<<<PT * 64 / 256, 256>>>(0, 4, 3);

    // ---- point layers 6-9 ----
    k_point128<<<dim3(8, PT / 128), 256>>>(W[5], 192, 1024, 192, 0, 0, 0, 0);
    k_fin<<<4, 256>>>(5, 1024, invP, G[5], Bt[5]);
    k_gmaxfin<<<32, 256>>>();
    k_gcorr<<<dim3(64, BB), 256>>>(W[6]);
    k_point128<<<dim3(4, PT / 128), 256>>>(W[6], 192, 512, 1216, 1024, 1, 0, 1);
    k_fin<<<2, 256>>>(6, 512, invP, G[6], Bt[6]);
    k_point128<<<dim3(2, PT / 128), 256>>>(W[7], 512, 256, 512, 0, 2, 6, 2);
    k_fin<<<1, 256>>>(7, 256, invP, G[7], Bt[7]);
    k_out9<<<(PT * 9 + 255) / 256, 256>>>(W[8], out);
}

// round 14
// speedup vs baseline: 1.0538x; 1.0053x over previous
#include <cuda_runtime.h>

#define KNN   20
#define BB    8
#define NN    4096
#define PT    (BB * NN)          /* 32768  points */
#define ET    (PT * KNN)         /* 655360 edges  */
#define EPSBN 1e-5f
#define NBANK 16

// ---------------------------------------------------------------------------
// Static device scratch (no allocations anywhere)
// ---------------------------------------------------------------------------
static __device__ float  g_feat3[PT * 3];
static __device__ float  g_xx[PT];
static __device__ float  g_dist[(size_t)PT * NN];        // 512 MB
static __device__ int    g_idx[ET];
static __device__ float  g_hA[(size_t)ET * 64];          // 160 MB
static __device__ float  g_x1[PT * 64];
static __device__ float  g_x2[PT * 64];
static __device__ float  g_x3[PT * 64];
static __device__ float  g_h7[(size_t)PT * 512];
static __device__ float  g_h8[(size_t)PT * 256];
static __device__ unsigned g_emaxU[3 * (size_t)PT * 64]; // raw max per (p,c), 3 pools
static __device__ unsigned g_eminU[3 * (size_t)PT * 64]; // raw min per (p,c)
static __device__ unsigned g_hmaxU[BB * 1024];
static __device__ unsigned g_hminU[BB * 1024];
static __device__ float  g_gmax[BB * 1024];
static __device__ float  g_gcorr[BB * 512];
static __device__ double g_sumB[NBANK * 8 * 1024];       // banked stats
static __device__ double g_sumsqB[NBANK * 8 * 1024];
static __device__ float  g_scale[8 * 1024];
static __device__ float  g_bias[8 * 1024];

__device__ __forceinline__ float lrelu(float v) { return v > 0.f ? v : 0.2f * v; }

// monotone float -> unsigned transform (preserves total order)
__device__ __forceinline__ unsigned ford(float f) {
    unsigned u = __float_as_uint(f);
    return (u & 0x80000000u) ? ~u : (u | 0x80000000u);
}
__device__ __forceinline__ float unford(unsigned u) {
    return (u & 0x80000000u) ? __uint_as_float(u & 0x7FFFFFFFu)
                             : __uint_as_float(~u);
}

// ---------------------------------------------------------------------------
// Zero BN statistic accumulators + minmax accumulators (graph-replay safe)
// ---------------------------------------------------------------------------
__global__ void k_zero() {
    int t = blockIdx.x * 256 + threadIdx.x;
    if (t < NBANK * 8 * 1024) { g_sumB[t] = 0.0; g_sumsqB[t] = 0.0; }
    if (t < BB * 1024) { g_hmaxU[t] = 0u; g_hminU[t] = 0xFFFFFFFFu; }
}

// zero the 3 edge-pool max/min arrays (uint4 vectorized)
__global__ void k_zmm() {
    size_t t = (size_t)(blockIdx.x * 256 + threadIdx.x) * 4;
    if (t < 3 * (size_t)PT * 64) {
        *(uint4*)&g_emaxU[t] = make_uint4(0u, 0u, 0u, 0u);
        *(uint4*)&g_eminU[t] = make_uint4(0xFFFFFFFFu, 0xFFFFFFFFu, 0xFFFFFFFFu, 0xFFFFFFFFu);
    }
}

// ---------------------------------------------------------------------------
// Transpose x [B,3,N] -> feat3 [P,3] and squared norms
// ---------------------------------------------------------------------------
__global__ void k_prep3(const float* __restrict__ x) {
    int p = blockIdx.x * 256 + threadIdx.x;
    if (p >= PT) return;
    int b = p >> 12, n = p & (NN - 1);
    const float* xb = x + (size_t)b * 3 * NN;
    float a0 = xb[n], a1 = xb[NN + n], a2 = xb[2 * NN + n];
    g_feat3[p * 3 + 0] = a0;
    g_feat3[p * 3 + 1] = a1;
    g_feat3[p * 3 + 2] = a2;
    g_xx[p] = a0 * a0 + a1 * a1 + a2 * a2;
}

// squared norms of [P,64] feature arrays; warp per row
__global__ void k_xx64(int sel) {
    const float* f = (sel == 1) ? g_x1 : g_x2;
    int gt = blockIdx.x * 256 + threadIdx.x;
    int w = gt >> 5, lane = gt & 31;
    if (w >= PT) return;
    const float* r = f + ((size_t)w << 6);
    float v0 = r[lane], v1 = r[lane + 32];
    float s = v0 * v0 + v1 * v1;
#pragma unroll
    for (int o = 16; o; o >>= 1) s += __shfl_down_sync(0xffffffffu, s, o);
    if (lane == 0) g_xx[w] = s;
}

// ---------------------------------------------------------------------------
// Pairwise neg. squared distance, C=64, SYMMETRIC upper-triangle tiles.
// grid (528, B), 256 threads, 8x8 per thread, k-sliced 16
// ---------------------------------------------------------------------------
__global__ __launch_bounds__(256) void k_dist128sym(int sel) {
    __shared__ __align__(16) float As[16][132];
    __shared__ __align__(16) float Bs[16][132];
    __shared__ float sxi[128], sxj[128];
    const float* f = (sel == 1) ? g_x1 : g_x2;
    int b = blockIdx.y;
    int rem = blockIdx.x, ti = 0;
    while (rem >= 32 - ti) { rem -= 32 - ti; ti++; }
    int tj = ti + rem;
    int i0 = ti << 7, j0 = tj << 7;
    int tid = threadIdx.x, tx = tid & 15, ty = tid >> 4;
    int r8 = ty << 3, c8 = tx << 3;
    int bi = b * NN + i0, bj = b * NN + j0;
    if (tid < 128) sxi[tid] = g_xx[bi + tid];
    else           sxj[tid - 128] = g_xx[bj + tid - 128];
    float acc[8][8] = {};
    for (int k0 = 0; k0 < 64; k0 += 16) {
        __syncthreads();
#pragma unroll
        for (int l = tid; l < 512; l += 256) {
            int r = l >> 2, kq = (l & 3) << 2;
            float4 av = *(const float4*)&f[(size_t)(bi + r) * 64 + k0 + kq];
            As[kq + 0][r] = av.x; As[kq + 1][r] = av.y;
            As[kq + 2][r] = av.z; As[kq + 3][r] = av.w;
            float4 bv = *(const float4*)&f[(size_t)(bj + r) * 64 + k0 + kq];
            Bs[kq + 0][r] = bv.x; Bs[kq + 1][r] = bv.y;
            Bs[kq + 2][r] = bv.z; Bs[kq + 3][r] = bv.w;
        }
        __syncthreads();
#pragma unroll
        for (int k = 0; k < 16; k++) {
            float a[8], bb[8];
            *(float4*)&a[0]  = *(const float4*)&As[k][r8];
            *(float4*)&a[4]  = *(const float4*)&As[k][r8 + 4];
            *(float4*)&bb[0] = *(const float4*)&Bs[k][c8];
            *(float4*)&bb[4] = *(const float4*)&Bs[k][c8 + 4];
#pragma unroll
            for (int ii = 0; ii < 8; ii++)
#pragma unroll
                for (int jj = 0; jj < 8; jj++)
                    acc[ii][jj] = fmaf(a[ii], bb[jj], acc[ii][jj]);
        }
    }
    // i-rows: dist[i,j] = (2*acc - xxi) - xxj
#pragma unroll
    for (int ii = 0; ii < 8; ii++) {
        float xi = sxi[r8 + ii];
        float o[8];
#pragma unroll
        for (int jj = 0; jj < 8; jj++)
            o[jj] = 2.f * acc[ii][jj] - xi - sxj[c8 + jj];
        float* dst = &g_dist[(size_t)(b * NN + i0 + r8 + ii) * NN + j0 + c8];
        *(float4*)&dst[0] = *(float4*)&o[0];
        *(float4*)&dst[4] = *(float4*)&o[4];
    }
    // j-rows (transposed): dist[j,i] = (2*acc - xxj) - xxi  (row norm FIRST)
    if (ti != tj) {
#pragma unroll
        for (int jj = 0; jj < 8; jj++) {
            float xj = sxj[c8 + jj];
            float o[8];
#pragma unroll
            for (int ii = 0; ii < 8; ii++)
                o[ii] = 2.f * acc[ii][jj] - xj - sxi[r8 + ii];
            float* dst = &g_dist[(size_t)(b * NN + j0 + c8 + jj) * NN + i0 + r8];
            *(float4*)&dst[0] = *(float4*)&o[0];
            *(float4*)&dst[4] = *(float4*)&o[4];
        }
    }
}

// ---------------------------------------------------------------------------
// Top-K: warp-local tournaments + single-warp merge (exact selection).
// ---------------------------------------------------------------------------
__device__ __forceinline__ void topk_phase1(float (&v)[32], int lane, int w,
                                            int wb, unsigned* cvu, int* ci) {
    float curv = v[0];
    int   curp = 0;
#pragma unroll
    for (int i = 1; i < 32; i++)
        if (v[i] > curv) { curv = v[i]; curp = i; }
    unsigned mask = 0u;
    for (int r = 0; r < KNN; r++) {
        unsigned long long key =
            ((unsigned long long)ford(curv) << 32) | (unsigned)(lane * 32 + curp);
#pragma unroll
        for (int o = 16; o; o >>= 1) {
            unsigned long long ok = __shfl_xor_sync(0xffffffffu, key, o);
            if (ok > key) key = ok;
        }
        int ws = (int)(key & 1023u);
        int wlane = ws >> 5, wpos = ws & 31;
        if (lane == r) {
            cvu[w * 20 + r] = (unsigned)(key >> 32);
            ci[w * 20 + r]  = wb + ((wpos >> 2) << 7) + (wlane << 2) + (wpos & 3);
        }
        if (lane == wlane) {
            mask |= 1u << wpos;
            curv = -3.0e38f; curp = 0;
#pragma unroll
            for (int i = 0; i < 32; i++) {
                bool ok = !((mask >> i) & 1u) && (v[i] > curv);
                if (ok) { curv = v[i]; curp = i; }
            }
        }
    }
}

__device__ __forceinline__ void topk_phase2(int row, int lane, unsigned* cvu, int* ci) {
    unsigned uv[3];
#pragma unroll
    for (int u = 0; u < 3; u++) {
        int s = lane + 32 * u;
        uv[u] = (s < 80) ? cvu[s] : 0u;
    }
    unsigned bcur = uv[0]; int bu = 0;
    if (uv[1] > bcur) { bcur = uv[1]; bu = 1; }
    if (uv[2] > bcur) { bcur = uv[2]; bu = 2; }
    for (int r = 0; r < KNN; r++) {
        unsigned long long key =
            ((unsigned long long)bcur << 32) | (unsigned)(lane + 32 * bu);
#pragma unroll
        for (int o = 16; o; o >>= 1) {
            unsigned long long ok = __shfl_xor_sync(0xffffffffu, key, o);
            if (ok > key) key = ok;
        }
        int ws = (int)(key & 127u);
        if (lane == 0) g_idx[(size_t)row * KNN + r] = ci[ws];
        if (lane == (ws & 31)) {
            uv[ws >> 5] = 0u;
            bcur = uv[0]; bu = 0;
            if (uv[1] > bcur) { bcur = uv[1]; bu = 1; }
            if (uv[2] > bcur) { bcur = uv[2]; bu = 2; }
        }
    }
}

// stages 2/3: read precomputed g_dist
__global__ __launch_bounds__(128) void k_topk() {
    __shared__ unsigned cvu[80];
    __shared__ int      ci[80];
    int row = blockIdx.x;
    int tid = threadIdx.x, lane = tid & 31, w = tid >> 5;
    int wb = w * 1024;
    const float4* base = (const float4*)(g_dist + (size_t)row * NN + wb);
    float v[32];
#pragma unroll
    for (int q = 0; q < 8; q++) {
        float4 t4 = base[q * 32 + lane];
        v[4 * q + 0] = t4.x; v[4 * q + 1] = t4.y;
        v[4 * q + 2] = t4.z; v[4 * q + 3] = t4.w;
    }
    topk_phase1(v, lane, w, wb, cvu, ci);
    __syncthreads();
    if (w == 0) topk_phase2(row, lane, cvu, ci);
}

// stage 1: compute 3-D distances inline (no dist matrix round-trip)
__global__ __launch_bounds__(128) void k_topk3() {
    __shared__ unsigned cvu[80];
    __shared__ int      ci[80];
    int row = blockIdx.x;
    int tid = threadIdx.x, lane = tid & 31, w = tid >> 5;
    int b = row >> 12;
    int wb = w * 1024;
    float xi0 = g_feat3[row * 3], xi1 = g_feat3[row * 3 + 1], xi2 = g_feat3[row * 3 + 2];
    float xxi = g_xx[row];
    float v[32];
#pragma unroll
    for (int q = 0; q < 8; q++) {
        int j0 = wb + q * 128 + lane * 4;
        const float4* fp = (const float4*)(g_feat3 + ((size_t)(b * NN) + j0) * 3);
        float4 f0 = fp[0], f1 = fp[1], f2 = fp[2];
        float arr[12] = {f0.x, f0.y, f0.z, f0.w, f1.x, f1.y, f1.z, f1.w,
                         f2.x, f2.y, f2.z, f2.w};
#pragma unroll
        for (int t = 0; t < 4; t++) {
            float a0 = arr[t * 3], a1 = arr[t * 3 + 1], a2 = arr[t * 3 + 2];
            float dot = fmaf(a0, xi0, fmaf(a1, xi1, a2 * xi2));
            float xxj = fmaf(a0, a0, fmaf(a1, a1, a2 * a2));
            v[4 * q + t] = 2.f * dot - xxi - xxj;
        }
    }
    topk_phase1(v, lane, w, wb, cvu, ci);
    __syncthreads();
    if (w == 0) topk_phase2(row, lane, cvu, ci);
}

// ---------------------------------------------------------------------------
// Max/min pooling epilogue helper: thread holds acc[8][4] for 8 consecutive
// edges (<=2 point groups) x 4 channels. Exact, order-independent.
// sMx/sMn: smem [8*64] tables for the <=8 points this CTA covers.
// ---------------------------------------------------------------------------
__device__ __forceinline__ void edge_pool_epilogue(const float acc[8][4],
                                                   int e0, int r8, int c4,
                                                   int tid, int pair,
                                                   unsigned* sMx, unsigned* sMn) {
    int eA = e0 + r8;
    int pA = eA / KNN;
    int split = (pA + 1) * KNN - eA; if (split > 8) split = 8;
    int p0 = e0 / KNN;
    float mxA[4], mnA[4], mxB[4], mnB[4];
#pragma unroll
    for (int jj = 0; jj < 4; jj++) {
        mxA[jj] = -3.0e38f; mnA[jj] = 3.0e38f;
        mxB[jj] = -3.0e38f; mnB[jj] = 3.0e38f;
    }
#pragma unroll
    for (int ii = 0; ii < 8; ii++) {
        bool inA = ii < split;
#pragma unroll
        for (int jj = 0; jj < 4; jj++) {
            float v = acc[ii][jj];
            if (inA) { mxA[jj] = fmaxf(mxA[jj], v); mnA[jj] = fminf(mnA[jj], v); }
            else     { mxB[jj] = fmaxf(mxB[jj], v); mnB[jj] = fminf(mnB[jj], v); }
        }
    }
    int lpA = pA - p0;
#pragma unroll
    for (int jj = 0; jj < 4; jj++) {
        atomicMax(&sMx[lpA * 64 + c4 + jj], ford(mxA[jj]));
        atomicMin(&sMn[lpA * 64 + c4 + jj], ford(mnA[jj]));
    }
    if (split < 8) {
        int lpB = lpA + 1;
#pragma unroll
        for (int jj = 0; jj < 4; jj++) {
            atomicMax(&sMx[lpB * 64 + c4 + jj], ford(mxB[jj]));
            atomicMin(&sMn[lpB * 64 + c4 + jj], ford(mnB[jj]));
        }
    }
    __syncthreads();
    unsigned* gMx = g_emaxU + (size_t)pair * PT * 64;
    unsigned* gMn = g_eminU + (size_t)pair * PT * 64;
    for (int idx = tid; idx < 512; idx += 256) {
        int lp = idx >> 6, c = idx & 63;
        int p = p0 + lp;
        if (p < PT) {
            unsigned mx = sMx[idx], mn = sMn[idx];
            if (mx) atomicMax(&gMx[(size_t)p * 64 + c], mx);
            if (mn != 0xFFFFFFFFu) atomicMin(&gMn[(size_t)p * 64 + c], mn);
        }
    }
}

// ---------------------------------------------------------------------------
// Edge layer 1: gather [xj-xi, xi] (6 dims) @ W1^T -> raw hA [E,64] + stats(0)
// 4 tiles of 64 edges per CTA
// ---------------------------------------------------------------------------
__global__ __launch_bounds__(256) void k_edge1(const float* __restrict__ W1) {
    __shared__ __align__(16) float Af[6][68];
    __shared__ __align__(16) float Bw[6][68];
    __shared__ double ssum[64], ssq[64];
    int e00 = blockIdx.x << 8, tid = threadIdx.x;
    if (tid < 64) { ssum[tid] = 0.0; ssq[tid] = 0.0; }
    else if (tid < 128) {
        int o = tid - 64;
#pragma unroll
        for (int c = 0; c < 6; c++) Bw[c][o] = W1[o * 6 + c];
    }
    int tx = tid & 15, ty = tid >> 4;
    int r4 = ty << 2, c4 = tx << 2;
    float tps[4] = {}, tpq[4] = {};
    for (int t = 0; t < 4; t++) {
        int e0 = e00 + (t << 6);
        __syncthreads();
        if (tid < 64) {
            int e = e0 + tid;
            int p = e / KNN;
            int q = (p >> 12) * NN + g_idx[e];
            float p0 = g_feat3[p * 3], p1 = g_feat3[p * 3 + 1], p2 = g_feat3[p * 3 + 2];
            float q0 = g_feat3[q * 3], q1 = g_feat3[q * 3 + 1], q2 = g_feat3[q * 3 + 2];
            Af[0][tid] = q0 - p0; Af[1][tid] = q1 - p1; Af[2][tid] = q2 - p2;
            Af[3][tid] = p0;      Af[4][tid] = p1;      Af[5][tid] = p2;
        }
        __syncthreads();
        float acc[4][4] = {};
#pragma unroll
        for (int k = 0; k < 6; k++) {
            float4 a4 = *(const float4*)&Af[k][r4];
            float4 b4 = *(const float4*)&Bw[k][c4];
            float av[4] = {a4.x, a4.y, a4.z, a4.w};
            float bv[4] = {b4.x, b4.y, b4.z, b4.w};
#pragma unroll
            for (int ii = 0; ii < 4; ii++)
#pragma unroll
                for (int jj = 0; jj < 4; jj++)
                    acc[ii][jj] = fmaf(av[ii], bv[jj], acc[ii][jj]);
        }
#pragma unroll
        for (int ii = 0; ii < 4; ii++)
#pragma unroll
            for (int jj = 0; jj < 4; jj++)
                g_hA[(size_t)(e0 + r4 + ii) * 64 + c4 + jj] = acc[ii][jj];
#pragma unroll
        for (int jj = 0; jj < 4; jj++) {
            float s = 0.f, q = 0.f;
#pragma unroll
            for (int ii = 0; ii < 4; ii++) { float v = acc[ii][jj]; s += v; q = fmaf(v, v, q); }
            tps[jj] += s; tpq[jj] += q;
        }
    }
#pragma unroll
    for (int jj = 0; jj < 4; jj++) {
        tps[jj] += __shfl_down_sync(0xffffffffu, tps[jj], 16);
        tpq[jj] += __shfl_down_sync(0xffffffffu, tpq[jj], 16);
    }
    if ((tid & 31) < 16) {
#pragma unroll
        for (int jj = 0; jj < 4; jj++) {
            atomicAdd(&ssum[c4 + jj], (double)tps[jj]);
            atomicAdd(&ssq[c4 + jj], (double)tpq[jj]);
        }
    }
    __syncthreads();
    if (tid < 64) {
        int bank = (blockIdx.x & (NBANK - 1)) * 8192;
        atomicAdd(&g_sumB[bank + tid], ssum[tid]);
        atomicAdd(&g_sumsqB[bank + tid], ssq[tid]);
    }
}

// ---------------------------------------------------------------------------
// Edge layers 2/4: act_aslot(hA)[E,64] @ W^T[64,64] -> raw max/min pool(pair)
// + stats(oslot). No output tensor store. 128-row tile, 8x4/thread, k16.
// ---------------------------------------------------------------------------
__global__ __launch_bounds__(256) void k_edge128(const float* __restrict__ W,
                                                 int aslot, int oslot, int pair) {
    __shared__ __align__(16) float As[16][132];
    __shared__ __align__(16) float Bs[16][68];
    __shared__ float sS[64], sB[64];
    __shared__ double ssum[64], ssq[64];
    __shared__ unsigned sMx[512], sMn[512];
    int e0 = blockIdx.x << 7, tid = threadIdx.x;
    if (tid < 64) {
        sS[tid] = g_scale[aslot * 1024 + tid];
        sB[tid] = g_bias[aslot * 1024 + tid];
        ssum[tid] = 0.0; ssq[tid] = 0.0;
    }
    for (int l = tid; l < 512; l += 256) { sMx[l] = 0u; sMn[l] = 0xFFFFFFFFu; }
    int tx = tid & 15, ty = tid >> 4;
    int r8 = ty << 3, c4 = tx << 2;
    float acc[8][4] = {};
    for (int k0 = 0; k0 < 64; k0 += 16) {
        __syncthreads();
#pragma unroll
        for (int l = tid; l < 512; l += 256) {
            int r = l >> 2, kq = (l & 3) << 2;
            int c = k0 + kq;
            float4 av = *(const float4*)&g_hA[(size_t)(e0 + r) * 64 + c];
            As[kq + 0][r] = lrelu(av.x * sS[c + 0] + sB[c + 0]);
            As[kq + 1][r] = lrelu(av.y * sS[c + 1] + sB[c + 1]);
            As[kq + 2][r] = lrelu(av.z * sS[c + 2] + sB[c + 2]);
            As[kq + 3][r] = lrelu(av.w * sS[c + 3] + sB[c + 3]);
        }
        {
            int r = tid >> 2, kq = (tid & 3) << 2;
            float4 bv = *(const float4*)&W[(size_t)r * 64 + k0 + kq];
            Bs[kq + 0][r] = bv.x; Bs[kq + 1][r] = bv.y;
            Bs[kq + 2][r] = bv.z; Bs[kq + 3][r] = bv.w;
        }
        __syncthreads();
#pragma unroll
        for (int k = 0; k < 16; k++) {
            float a[8], bb[4];
            *(float4*)&a[0]  = *(const float4*)&As[k][r8];
            *(float4*)&a[4]  = *(const float4*)&As[k][r8 + 4];
            *(float4*)&bb[0] = *(const float4*)&Bs[k][c4];
#pragma unroll
            for (int ii = 0; ii < 8; ii++)
#pragma unroll
                for (int jj = 0; jj < 4; jj++)
                    acc[ii][jj] = fmaf(a[ii], bb[jj], acc[ii][jj]);
        }
    }
    // stats
    float ps[4], pq[4];
#pragma unroll
    for (int jj = 0; jj < 4; jj++) {
        float s = 0.f, q = 0.f;
#pragma unroll
        for (int ii = 0; ii < 8; ii++) { float v = acc[ii][jj]; s += v; q = fmaf(v, v, q); }
        ps[jj] = s; pq[jj] = q;
    }
#pragma unroll
    for (int jj = 0; jj < 4; jj++) {
        ps[jj] += __shfl_down_sync(0xffffffffu, ps[jj], 16);
        pq[jj] += __shfl_down_sync(0xffffffffu, pq[jj], 16);
    }
    if ((tid & 31) < 16) {
#pragma unroll
        for (int jj = 0; jj < 4; jj++) {
            atomicAdd(&ssum[c4 + jj], (double)ps[jj]);
            atomicAdd(&ssq[c4 + jj], (double)pq[jj]);
        }
    }
    // raw max/min pool accumulation (replaces hB store + maxe)
    edge_pool_epilogue(acc, e0, r8, c4, tid, pair, sMx, sMn);
    if (tid < 64) {
        int bank = (blockIdx.x & (NBANK - 1)) * 8192;
        atomicAdd(&g_sumB[bank + oslot * 1024 + tid], ssum[tid]);
        atomicAdd(&g_sumsqB[bank + oslot * 1024 + tid], ssq[tid]);
    }
}

// ---------------------------------------------------------------------------
// Edge layers 3/5: gathered 128-dim edge feature @ W^T [64,128] + stats.
// doStore=1: write raw hA (L3). doStore=0: max/min pool to pair (L5).
// ---------------------------------------------------------------------------
__global__ __launch_bounds__(256) void k_edgeG128(const float* __restrict__ W,
                                                  int srcSel, int oslot,
                                                  int doStore, int pair) {
    __shared__ __align__(16) float As[16][132];
    __shared__ __align__(16) float Bs[16][68];
    __shared__ int sP[128], sQ[128];
    __shared__ double ssum[64], ssq[64];
    __shared__ unsigned sMx[512], sMn[512];
    const float* src = (srcSel == 1) ? g_x1 : g_x2;
    int e0 = blockIdx.x << 7, tid = threadIdx.x;
    if (tid < 64) { ssum[tid] = 0.0; ssq[tid] = 0.0; }
    for (int l = tid; l < 512; l += 256) { sMx[l] = 0u; sMn[l] = 0xFFFFFFFFu; }
    if (tid < 128) {
        int e = e0 + tid;
        int p = e / KNN;
        sP[tid] = p;
        sQ[tid] = (p >> 12) * NN + g_idx[e];
    }
    int tx = tid & 15, ty = tid >> 4;
    int r8 = ty << 3, c4 = tx << 2;
    float acc[8][4] = {};
    for (int k0 = 0; k0 < 128; k0 += 16) {
        __syncthreads();
#pragma unroll
        for (int l = tid; l < 512; l += 256) {
            int r = l >> 2, kq = (l & 3) << 2;
            int c = k0 + kq;
            float4 av;
            if (c < 64) {
                float4 aq = *(const float4*)&src[(size_t)sQ[r] * 64 + c];
                float4 ap = *(const float4*)&src[(size_t)sP[r] * 64 + c];
                av.x = aq.x - ap.x; av.y = aq.y - ap.y;
                av.z = aq.z - ap.z; av.w = aq.w - ap.w;
            } else {
                av = *(const float4*)&src[(size_t)sP[r] * 64 + (c - 64)];
            }
            As[kq + 0][r] = av.x; As[kq + 1][r] = av.y;
            As[kq + 2][r] = av.z; As[kq + 3][r] = av.w;
        }
        {
            int r = tid >> 2, kq = (tid & 3) << 2;
            float4 bv = *(const float4*)&W[(size_t)r * 128 + k0 + kq];
            Bs[kq + 0][r] = bv.x; Bs[kq + 1][r] = bv.y;
            Bs[kq + 2][r] = bv.z; Bs[kq + 3][r] = bv.w;
        }
        __syncthreads();
#pragma unroll
        for (int k = 0; k < 16; k++) {
            float a[8], bb[4];
            *(float4*)&a[0]  = *(const float4*)&As[k][r8];
            *(float4*)&a[4]  = *(const float4*)&As[k][r8 + 4];
            *(float4*)&bb[0] = *(const float4*)&Bs[k][c4];
#pragma unroll
            for (int ii = 0; ii < 8; ii++)
#pragma unroll
                for (int jj = 0; jj < 4; jj++)
                    acc[ii][jj] = fmaf(a[ii], bb[jj], acc[ii][jj]);
        }
    }
    if (doStore) {
#pragma unroll
        for (int ii = 0; ii < 8; ii++)
            *(float4*)&g_hA[(size_t)(e0 + r8 + ii) * 64 + c4] = *(float4*)&acc[ii][0];
    }
    float ps[4], pq[4];
#pragma unroll
    for (int jj = 0; jj < 4; jj++) {
        float s = 0.f, q = 0.f;
#pragma unroll
        for (int ii = 0; ii < 8; ii++) { float v = acc[ii][jj]; s += v; q = fmaf(v, v, q); }
        ps[jj] = s; pq[jj] = q;
    }
#pragma unroll
    for (int jj = 0; jj < 4; jj++) {
        ps[jj] += __shfl_down_sync(0xffffffffu, ps[jj], 16);
        pq[jj] += __shfl_down_sync(0xffffffffu, pq[jj], 16);
    }
    if ((tid & 31) < 16) {
#pragma unroll
        for (int jj = 0; jj < 4; jj++) {
            atomicAdd(&ssum[c4 + jj], (double)ps[jj]);
            atomicAdd(&ssq[c4 + jj], (double)pq[jj]);
        }
    }
    if (!doStore) {
        edge_pool_epilogue(acc, e0, r8, c4, tid, pair, sMx, sMn);
    } else {
        __syncthreads();
    }
    if (tid < 64) {
        int bank = (blockIdx.x & (NBANK - 1)) * 8192;
        atomicAdd(&g_sumB[bank + oslot * 1024 + tid], ssum[tid]);
        atomicAdd(&g_sumsqB[bank + oslot * 1024 + tid], ssq[tid]);
    }
}

// x{1,2,3}[p,c] = lrelu(sc * (sc>=0 ? rawmax : rawmin) + bi)
__global__ void k_maxfin(int pair, int slot, int outSel) {
    int t = blockIdx.x * 256 + threadIdx.x;
    if (t >= PT * 64) return;
    int c = t & 63;
    float sc = g_scale[slot * 1024 + c], bi = g_bias[slot * 1024 + c];
    unsigned u = (sc >= 0.f) ? g_emaxU[(size_t)pair * PT * 64 + t]
                             : g_eminU[(size_t)pair * PT * 64 + t];
    float* out = (outSel == 1) ? g_x1 : (outSel == 2 ? g_x2 : g_x3);
    out[t] = lrelu(sc * unford(u) + bi);
}

// ---------------------------------------------------------------------------
// Point GEMMs, 128x128 tile, 8x8/thread, k-sliced 16. Modes:
//   0: A=[x1,x2,x3](192) @ W6 -> NO store; per-(b,c) raw max/min + stats(5)
//   1: A=[x1,x2,x3](192) @ W7[:,1024:] + gcorr -> h7 (stats slot 6)
//   2: A=act6(h7)(512)   @ W8                  -> h8 (stats slot 7)
// ---------------------------------------------------------------------------
__global__ __launch_bounds__(256) void k_point128(const float* __restrict__ W,
                                                  int Cin, int Cout, int wstride,
                                                  int woff, int mode, int aslot,
                                                  int outSel) {
    __shared__ __align__(16) float As[16][132];
    __shared__ __align__(16) float Bs[16][132];
    __shared__ double ssum[128], ssq[128];
    __shared__ unsigned sMaxU[128], sMinU[128];
    int c0 = blockIdx.x << 7, r0 = blockIdx.y << 7;
    int tid = threadIdx.x, tx = tid & 15, ty = tid >> 4;
    int r8 = ty << 3, c8 = tx << 3;
    int b = r0 >> 12;
    if (tid < 128) {
        ssum[tid] = 0.0; ssq[tid] = 0.0;
        sMaxU[tid] = 0u; sMinU[tid] = 0xFFFFFFFFu;
    }
    float acc[8][8] = {};
    for (int k0 = 0; k0 < Cin; k0 += 16) {
        __syncthreads();
#pragma unroll
        for (int l = tid; l < 512; l += 256) {
            int r = l >> 2, kq = (l & 3) << 2;
            int c = k0 + kq, row = r0 + r;
            float4 av;
            if (mode != 2) {
                const float* sp = (c < 64) ? &g_x1[(size_t)row * 64 + c]
                               : (c < 128) ? &g_x2[(size_t)row * 64 + (c - 64)]
                                           : &g_x3[(size_t)row * 64 + (c - 128)];
                av = *(const float4*)sp;
            } else {
                av = *(const float4*)&g_h7[(size_t)row * 512 + c];
                av.x = lrelu(av.x * g_scale[aslot * 1024 + c + 0] + g_bias[aslot * 1024 + c + 0]);
                av.y = lrelu(av.y * g_scale[aslot * 1024 + c + 1] + g_bias[aslot * 1024 + c + 1]);
                av.z = lrelu(av.z * g_scale[aslot * 1024 + c + 2] + g_bias[aslot * 1024 + c + 2]);
                av.w = lrelu(av.w * g_scale[aslot * 1024 + c + 3] + g_bias[aslot * 1024 + c + 3]);
            }
            As[kq + 0][r] = av.x; As[kq + 1][r] = av.y;
            As[kq + 2][r] = av.z; As[kq + 3][r] = av.w;
            float4 bv = *(const float4*)&W[(size_t)(c0 + r) * wstride + woff + k0 + kq];
            Bs[kq + 0][r] = bv.x; Bs[kq + 1][r] = bv.y;
            Bs[kq + 2][r] = bv.z; Bs[kq + 3][r] = bv.w;
        }
        __syncthreads();
#pragma unroll
        for (int k = 0; k < 16; k++) {
            float a[8], bb[8];
            *(float4*)&a[0]  = *(const float4*)&As[k][r8];
            *(float4*)&a[4]  = *(const float4*)&As[k][r8 + 4];
            *(float4*)&bb[0] = *(const float4*)&Bs[k][c8];
            *(float4*)&bb[4] = *(const float4*)&Bs[k][c8 + 4];
#pragma unroll
            for (int ii = 0; ii < 8; ii++)
#pragma unroll
                for (int jj = 0; jj < 8; jj++)
                    acc[ii][jj] = fmaf(a[ii], bb[jj], acc[ii][jj]);
        }
    }
    if (mode == 1) {
#pragma unroll
        for (int jj = 0; jj < 8; jj++) {
            float gc = g_gcorr[b * 512 + c0 + c8 + jj];
#pragma unroll
            for (int ii = 0; ii < 8; ii++) acc[ii][jj] += gc;
        }
    }
    if (outSel != 0) {
        float* out = (outSel == 1) ? g_h7 : g_h8;
#pragma unroll
        for (int ii = 0; ii < 8; ii++) {
            float* dst = &out[(size_t)(r0 + r8 + ii) * Cout + c0 + c8];
            *(float4*)&dst[0] = *(float4*)&acc[ii][0];
            *(float4*)&dst[4] = *(float4*)&acc[ii][4];
        }
    }
    int slot = 5 + outSel;
    float ps[8], pq[8];
#pragma unroll
    for (int jj = 0; jj < 8; jj++) {
        float s = 0.f, q = 0.f;
#pragma unroll
        for (int ii = 0; ii < 8; ii++) { float v = acc[ii][jj]; s += v; q = fmaf(v, v, q); }
        ps[jj] = s; pq[jj] = q;
    }
#pragma unroll
    for (int jj = 0; jj < 8; jj++) {
        ps[jj] += __shfl_down_sync(0xffffffffu, ps[jj], 16);
        pq[jj] += __shfl_down_sync(0xffffffffu, pq[jj], 16);
    }
    if ((tid & 31) < 16) {
#pragma unroll
        for (int jj = 0; jj < 8; jj++) {
            atomicAdd(&ssum[c8 + jj], (double)ps[jj]);
            atomicAdd(&ssq[c8 + jj], (double)pq[jj]);
        }
    }
    if (outSel == 0) {
        float mx[8], mn[8];
#pragma unroll
        for (int jj = 0; jj < 8; jj++) {
            float a = acc[0][jj], c = acc[0][jj];
#pragma unroll
            for (int ii = 1; ii < 8; ii++) {
                a = fmaxf(a, acc[ii][jj]);
                c = fminf(c, acc[ii][jj]);
            }
            mx[jj] = a; mn[jj] = c;
        }
#pragma unroll
        for (int jj = 0; jj < 8; jj++) {
            mx[jj] = fmaxf(mx[jj], __shfl_down_sync(0xffffffffu, mx[jj], 16));
            mn[jj] = fminf(mn[jj], __shfl_down_sync(0xffffffffu, mn[jj], 16));
        }
        if ((tid & 31) < 16) {
#pragma unroll
            for (int jj = 0; jj < 8; jj++) {
                atomicMax(&sMaxU[c8 + jj], ford(mx[jj]));
                atomicMin(&sMinU[c8 + jj], ford(mn[jj]));
            }
        }
    }
    __syncthreads();
    if (tid < 128) {
        int bank = (blockIdx.y & (NBANK - 1)) * 8192;
        atomicAdd(&g_sumB[bank + slot * 1024 + c0 + tid], ssum[tid]);
        atomicAdd(&g_sumsqB[bank + slot * 1024 + c0 + tid], ssq[tid]);
        if (outSel == 0) {
            atomicMax(&g_hmaxU[b * 1024 + c0 + tid], sMaxU[tid]);
            atomicMin(&g_hminU[b * 1024 + c0 + tid], sMinU[tid]);
        }
    }
}

// gmax[b,c] = lrelu(sc * (sc>=0 ? hmax : hmin) + bi)   (monotone pooling)
__global__ void k_gmaxfin() {
    int t = blockIdx.x * 256 + threadIdx.x;
    if (t >= BB * 1024) return;
    int c = t & 1023;
    float sc = g_scale[5 * 1024 + c], bi = g_bias[5 * 1024 + c];
    unsigned u = (sc >= 0.f) ? g_hmaxU[t] : g_hminU[t];
    g_gmax[t] = lrelu(sc * unford(u) + bi);
}

// gcorr[b,o] = sum_c gmax[b,c] * W7[o,c]  (c < 1024); warp per output
__global__ void k_gcorr(const float* __restrict__ W7) {
    int b = blockIdx.y;
    int o = blockIdx.x * 8 + (threadIdx.x >> 5);
    int lane = threadIdx.x & 31;
    const float* gm = g_gmax + b * 1024;
    const float* w  = W7 + (size_t)o * 1216;
    float s = 0.f;
#pragma unroll 8
    for (int k = lane; k < 1024; k += 32) s = fmaf(gm[k], w[k], s);
#pragma unroll
    for (int off = 16; off; off >>= 1) s += __shfl_down_sync(0xffffffffu, s, off);
    if (lane == 0) g_gcorr[b * 512 + o] = s;
}

// fold (gamma, beta, mean, var) -> per-channel scale/bias (sums 16 banks)
__global__ void k_fin(int slot, int C, double invM,
                      const float* __restrict__ g, const float* __restrict__ b) {
    int c = blockIdx.x * 256 + threadIdx.x;
    if (c >= C) return;
    double sm = 0.0, sq = 0.0;
#pragma unroll
    for (int k = 0; k < NBANK; k++) {
        sm += g_sumB[k * 8192 + slot * 1024 + c];
        sq += g_sumsqB[k * 8192 + slot * 1024 + c];
    }
    double mean = sm * invM;
    double var  = sq * invM - mean * mean;
    float sc    = g[c] * rsqrtf((float)var + EPSBN);
    g_scale[slot * 1024 + c] = sc;
    g_bias[slot * 1024 + c]  = b[c] - (float)mean * sc;
}

// ---------------------------------------------------------------------------
// Final: out[P,9] = act7(h8) @ W9^T
// ---------------------------------------------------------------------------
__global__ void k_out9(const float* __restrict__ W9, float* __restrict__ out) {
    int t = blockIdx.x * 256 + threadIdx.x;
    if (t >= PT * 9) return;
    int p = t / 9, o = t - p * 9;
    const float* row = g_h8 + (size_t)p * 256;
    const float* w   = W9 + o * 256;
    float acc = 0.f;
#pragma unroll 4
    for (int k = 0; k < 256; k++) {
        float v = lrelu(row[k] * g_scale[7 * 1024 + k] + g_bias[7 * 1024 + k]);
        acc = fmaf(v, w[k], acc);
    }
    out[t] = acc;
}

// ---------------------------------------------------------------------------
// Host launcher
// ---------------------------------------------------------------------------
extern "C" void kernel_launch(void* const* d_in, const int* in_sizes, int n_in,
                              void* d_out, int out_size) {
    int base = (in_sizes[1] == 1) ? 2 : 1;
    const float* x = (const float*)d_in[0];
    const float* W[9];
    const float* G[8];
    const float* Bt[8];
    for (int i = 0; i < 9; i++) W[i] = (const float*)d_in[base + i];
    for (int i = 0; i < 8; i++) {
        G[i]  = (const float*)d_in[base + 9 + 2 * i];
        Bt[i] = (const float*)d_in[base + 10 + 2 * i];
    }
    float* out = (float*)d_out;

    const double invE = 1.0 / (double)ET;
    const double invP = 1.0 / (double)PT;

    k_zero<<<(NBANK * 8 * 1024) / 256, 256>>>();
    k_zmm<<<(3 * PT * 64 / 4 + 255) / 256, 256>>>();
    k_prep3<<<PT / 256, 256>>>(x);

    // ---- stage 1: fused knn on xyz, edge layers 1-2, maxpool -> x1 ----
    k_topk3<<<PT, 128>>>();
    k_edge1<<<ET / 256, 256>>>(W[0]);
    k_fin<<<1, 256>>>(0, 64, invE, G[0], Bt[0]);
    k_edge128<<<ET / 128, 256>>>(W[1], 0, 1, 0);
    k_fin<<<1, 256>>>(1, 64, invE, G[1], Bt[1]);
    k_maxfin<<<PT * 64 / 256, 256>>>(0, 1, 1);

    // ---- stage 2: knn on x1, edge layers 3-4, maxpool -> x2 ----
    k_xx64<<<PT * 32 / 256, 256>>>(1);
    k_dist128sym<<<dim3(528, BB), 256>>>(1);
    k_topk<<<PT, 128>>>();
    k_edgeG128<<<ET / 128, 256>>>(W[2], 1, 2, 1, 0);
    k_fin<<<1, 256>>>(2, 64, invE, G[2], Bt[2]);
    k_edge128<<<ET / 128, 256>>>(W[3], 2, 3, 1);
    k_fin<<<1, 256>>>(3, 64, invE, G[3], Bt[3]);
    k_maxfin<<<PT * 64 / 256, 256>>>(1, 3, 2);

    // ---- stage 3: knn on x2, edge layer 5, maxpool -> x3 ----
    k_xx64<<<PT * 32 / 256, 256>>>(2);
    k_dist128sym<<<dim3(528, BB), 256>>>(2);
    k_topk<<<PT, 128>>>();
    k_edgeG128<<<ET / 128, 256>>>(W[4], 2, 4, 0, 2);
    k_fin<<<1, 256>>>(4, 64, invE, G[4], Bt[4]);
    k_maxfin<<<PT * 64 / 256, 256>>>(2, 4, 3);

    // ---- point layers 6-9 ----
    k_point128<<<dim3(8, PT / 128), 256>>>(W[5], 192, 1024, 192, 0, 0, 0, 0);
    k_fin<<<4, 256>>>(5, 1024, invP, G[5], Bt[5]);
    k_gmaxfin<<<32, 256>>>();
    k_gcorr<<<dim3(64, BB), 256>>>(W[6]);
    k_point128<<<dim3(4, PT / 128), 256>>>(W[6], 192, 512, 1216, 1024, 1, 0, 1);
    k_fin<<<2, 256>>>(6, 512, invP, G[6], Bt[6]);
    k_point128<<<dim3(2, PT / 128), 256>>>(W[7], 512, 256, 512, 0, 2, 6, 2);
    k_fin<<<1, 256>>>(7, 256, invP, G[7], Bt[7]);
    k_out9<<<(PT * 9 + 255) / 256, 256>>>(W[8], out);
}

// round 16
// speedup vs baseline: 1.0926x; 1.0369x over previous
#include <cuda_runtime.h>

#define KNN   20
#define BB    8
#define NN    4096
#define PT    (BB * NN)          /* 32768  points */
#define ET    (PT * KNN)         /* 655360 edges  */
#define EPSBN 1e-5f
#define NBANK 16

// ---------------------------------------------------------------------------
// Static device scratch (no allocations anywhere)
// ---------------------------------------------------------------------------
static __device__ float  g_feat3[PT * 3];
static __device__ float  g_xx[PT];
static __device__ float  g_dist[(size_t)PT * NN];        // 512 MB
static __device__ int    g_idx[ET];
static __device__ float  g_hA[(size_t)ET * 64];          // 160 MB
static __device__ float  g_x1[PT * 64];
static __device__ float  g_x2[PT * 64];
static __device__ float  g_x3[PT * 64];
static __device__ float  g_h7[(size_t)PT * 512];
static __device__ float  g_h8[(size_t)PT * 256];
static __device__ unsigned g_emaxU[3 * (size_t)PT * 64]; // raw max per (p,c), 3 pools
static __device__ unsigned g_eminU[3 * (size_t)PT * 64]; // raw min per (p,c)
static __device__ unsigned g_hmaxU[BB * 1024];
static __device__ unsigned g_hminU[BB * 1024];
static __device__ float  g_gmax[BB * 1024];
static __device__ float  g_gcorr[BB * 512];
static __device__ double g_sumB[NBANK * 8 * 1024];       // banked stats
static __device__ double g_sumsqB[NBANK * 8 * 1024];
static __device__ float  g_scale[8 * 1024];
static __device__ float  g_bias[8 * 1024];

__device__ __forceinline__ float lrelu(float v) { return v > 0.f ? v : 0.2f * v; }

// monotone float -> unsigned transform (preserves total order)
__device__ __forceinline__ unsigned ford(float f) {
    unsigned u = __float_as_uint(f);
    return (u & 0x80000000u) ? ~u : (u | 0x80000000u);
}
__device__ __forceinline__ float unford(unsigned u) {
    return (u & 0x80000000u) ? __uint_as_float(u & 0x7FFFFFFFu)
                             : __uint_as_float(~u);
}

// ---------------------------------------------------------------------------
// Zero BN statistic accumulators + minmax accumulators (graph-replay safe)
// ---------------------------------------------------------------------------
__global__ void k_zero() {
    int t = blockIdx.x * 256 + threadIdx.x;
    if (t < NBANK * 8 * 1024) { g_sumB[t] = 0.0; g_sumsqB[t] = 0.0; }
    if (t < BB * 1024) { g_hmaxU[t] = 0u; g_hminU[t] = 0xFFFFFFFFu; }
}

// zero the 3 edge-pool max/min arrays (uint4 vectorized)
__global__ void k_zmm() {
    size_t t = (size_t)(blockIdx.x * 256 + threadIdx.x) * 4;
    if (t < 3 * (size_t)PT * 64) {
        *(uint4*)&g_emaxU[t] = make_uint4(0u, 0u, 0u, 0u);
        *(uint4*)&g_eminU[t] = make_uint4(0xFFFFFFFFu, 0xFFFFFFFFu, 0xFFFFFFFFu, 0xFFFFFFFFu);
    }
}

// ---------------------------------------------------------------------------
// Transpose x [B,3,N] -> feat3 [P,3] and squared norms
// ---------------------------------------------------------------------------
__global__ void k_prep3(const float* __restrict__ x) {
    int p = blockIdx.x * 256 + threadIdx.x;
    if (p >= PT) return;
    int b = p >> 12, n = p & (NN - 1);
    const float* xb = x + (size_t)b * 3 * NN;
    float a0 = xb[n], a1 = xb[NN + n], a2 = xb[2 * NN + n];
    g_feat3[p * 3 + 0] = a0;
    g_feat3[p * 3 + 1] = a1;
    g_feat3[p * 3 + 2] = a2;
    g_xx[p] = a0 * a0 + a1 * a1 + a2 * a2;
}

// squared norms of [P,64] feature arrays; warp per row
__global__ void k_xx64(int sel) {
    const float* f = (sel == 1) ? g_x1 : g_x2;
    int gt = blockIdx.x * 256 + threadIdx.x;
    int w = gt >> 5, lane = gt & 31;
    if (w >= PT) return;
    const float* r = f + ((size_t)w << 6);
    float v0 = r[lane], v1 = r[lane + 32];
    float s = v0 * v0 + v1 * v1;
#pragma unroll
    for (int o = 16; o; o >>= 1) s += __shfl_down_sync(0xffffffffu, s, o);
    if (lane == 0) g_xx[w] = s;
}

// ---------------------------------------------------------------------------
// Pairwise neg. squared distance, C=64, SYMMETRIC upper-triangle tiles.
// grid (528, B), 256 threads, 8x8 per thread, k-sliced 16
// ---------------------------------------------------------------------------
__global__ __launch_bounds__(256) void k_dist128sym(int sel) {
    __shared__ __align__(16) float As[16][132];
    __shared__ __align__(16) float Bs[16][132];
    __shared__ float sxi[128], sxj[128];
    const float* f = (sel == 1) ? g_x1 : g_x2;
    int b = blockIdx.y;
    int rem = blockIdx.x, ti = 0;
    while (rem >= 32 - ti) { rem -= 32 - ti; ti++; }
    int tj = ti + rem;
    int i0 = ti << 7, j0 = tj << 7;
    int tid = threadIdx.x, tx = tid & 15, ty = tid >> 4;
    int r8 = ty << 3, c8 = tx << 3;
    int bi = b * NN + i0, bj = b * NN + j0;
    if (tid < 128) sxi[tid] = g_xx[bi + tid];
    else           sxj[tid - 128] = g_xx[bj + tid - 128];
    float acc[8][8] = {};
    for (int k0 = 0; k0 < 64; k0 += 16) {
        __syncthreads();
#pragma unroll
        for (int l = tid; l < 512; l += 256) {
            int r = l >> 2, kq = (l & 3) << 2;
            float4 av = *(const float4*)&f[(size_t)(bi + r) * 64 + k0 + kq];
            As[kq + 0][r] = av.x; As[kq + 1][r] = av.y;
            As[kq + 2][r] = av.z; As[kq + 3][r] = av.w;
            float4 bv = *(const float4*)&f[(size_t)(bj + r) * 64 + k0 + kq];
            Bs[kq + 0][r] = bv.x; Bs[kq + 1][r] = bv.y;
            Bs[kq + 2][r] = bv.z; Bs[kq + 3][r] = bv.w;
        }
        __syncthreads();
#pragma unroll
        for (int k = 0; k < 16; k++) {
            float a[8], bb[8];
            *(float4*)&a[0]  = *(const float4*)&As[k][r8];
            *(float4*)&a[4]  = *(const float4*)&As[k][r8 + 4];
            *(float4*)&bb[0] = *(const float4*)&Bs[k][c8];
            *(float4*)&bb[4] = *(const float4*)&Bs[k][c8 + 4];
#pragma unroll
            for (int ii = 0; ii < 8; ii++)
#pragma unroll
                for (int jj = 0; jj < 8; jj++)
                    acc[ii][jj] = fmaf(a[ii], bb[jj], acc[ii][jj]);
        }
    }
    // i-rows: dist[i,j] = (2*acc - xxi) - xxj
#pragma unroll
    for (int ii = 0; ii < 8; ii++) {
        float xi = sxi[r8 + ii];
        float o[8];
#pragma unroll
        for (int jj = 0; jj < 8; jj++)
            o[jj] = 2.f * acc[ii][jj] - xi - sxj[c8 + jj];
        float* dst = &g_dist[(size_t)(b * NN + i0 + r8 + ii) * NN + j0 + c8];
        *(float4*)&dst[0] = *(float4*)&o[0];
        *(float4*)&dst[4] = *(float4*)&o[4];
    }
    // j-rows (transposed): dist[j,i] = (2*acc - xxj) - xxi  (row norm FIRST)
    if (ti != tj) {
#pragma unroll
        for (int jj = 0; jj < 8; jj++) {
            float xj = sxj[c8 + jj];
            float o[8];
#pragma unroll
            for (int ii = 0; ii < 8; ii++)
                o[ii] = 2.f * acc[ii][jj] - xj - sxi[r8 + ii];
            float* dst = &g_dist[(size_t)(b * NN + j0 + c8 + jj) * NN + i0 + r8];
            *(float4*)&dst[0] = *(float4*)&o[0];
            *(float4*)&dst[4] = *(float4*)&o[4];
        }
    }
}

// ---------------------------------------------------------------------------
// Top-K: 8 warps/row, 16 elems/lane, REDUX argmax tournaments.
// Phase1: each warp extracts its top-20 of its 512 cols (exact).
// Phase2: warp 0 merges 160 candidates -> global top-20 (exact).
// Layout: warp w owns cols [w*512, w*512+512); (q,lane,t) -> wb + q*128 + lane*4 + t
// ---------------------------------------------------------------------------
__device__ __forceinline__ void topk_p1(float (&v)[16], int lane, int w,
                                        int wb, unsigned* cvu, int* ci) {
    float curv = v[0];
    int   curp = 0;
#pragma unroll
    for (int i = 1; i < 16; i++)
        if (v[i] > curv) { curv = v[i]; curp = i; }
    unsigned mask = 0u;
    for (int r = 0; r < KNN; r++) {
        unsigned fu = ford(curv);
        unsigned best = __reduce_max_sync(0xffffffffu, fu);
        unsigned bal  = __ballot_sync(0xffffffffu, fu == best);
        int wlane = __ffs(bal) - 1;
        int wpos  = __shfl_sync(0xffffffffu, curp, wlane);
        if (lane == r) {
            cvu[w * 20 + r] = best;
            ci[w * 20 + r]  = wb + ((wpos >> 2) << 7) + (wlane << 2) + (wpos & 3);
        }
        if (lane == wlane) {
            mask |= 1u << curp;
            curv = -3.0e38f; curp = 0;
#pragma unroll
            for (int i = 0; i < 16; i++) {
                bool ok = !((mask >> i) & 1u) && (v[i] > curv);
                if (ok) { curv = v[i]; curp = i; }
            }
        }
    }
}

__device__ __forceinline__ void topk_p2(int row, int lane, unsigned* cvu, int* ci) {
    unsigned uv[5];
#pragma unroll
    for (int u = 0; u < 5; u++)
        uv[u] = cvu[lane + 32 * u];
    unsigned bcur = uv[0]; int bu = 0;
#pragma unroll
    for (int u = 1; u < 5; u++)
        if (uv[u] > bcur) { bcur = uv[u]; bu = u; }
    for (int r = 0; r < KNN; r++) {
        unsigned best = __reduce_max_sync(0xffffffffu, bcur);
        unsigned bal  = __ballot_sync(0xffffffffu, bcur == best);
        int wl = __ffs(bal) - 1;
        int wu = __shfl_sync(0xffffffffu, bu, wl);
        if (lane == 0) g_idx[(size_t)row * KNN + r] = ci[wl + 32 * wu];
        if (lane == wl) {
            uv[bu] = 0u;
            bcur = uv[0]; bu = 0;
#pragma unroll
            for (int u = 1; u < 5; u++)
                if (uv[u] > bcur) { bcur = uv[u]; bu = u; }
        }
    }
}

// stages 2/3: read precomputed g_dist
__global__ __launch_bounds__(256) void k_topk() {
    __shared__ unsigned cvu[160];
    __shared__ int      ci[160];
    int row = blockIdx.x;
    int tid = threadIdx.x, lane = tid & 31, w = tid >> 5;
    int wb = w * 512;
    const float4* base = (const float4*)(g_dist + (size_t)row * NN + wb);
    float v[16];
#pragma unroll
    for (int q = 0; q < 4; q++) {
        float4 t4 = base[q * 32 + lane];
        v[4 * q + 0] = t4.x; v[4 * q + 1] = t4.y;
        v[4 * q + 2] = t4.z; v[4 * q + 3] = t4.w;
    }
    topk_p1(v, lane, w, wb, cvu, ci);
    __syncthreads();
    if (w == 0) topk_p2(row, lane, cvu, ci);
}

// stage 1: compute 3-D distances inline (no dist matrix round-trip)
__global__ __launch_bounds__(256) void k_topk3() {
    __shared__ unsigned cvu[160];
    __shared__ int      ci[160];
    int row = blockIdx.x;
    int tid = threadIdx.x, lane = tid & 31, w = tid >> 5;
    int b = row >> 12;
    int wb = w * 512;
    float xi0 = g_feat3[row * 3], xi1 = g_feat3[row * 3 + 1], xi2 = g_feat3[row * 3 + 2];
    float xxi = g_xx[row];
    float v[16];
#pragma unroll
    for (int q = 0; q < 4; q++) {
        int j0 = wb + q * 128 + lane * 4;
        const float4* fp = (const float4*)(g_feat3 + ((size_t)(b * NN) + j0) * 3);
        float4 f0 = fp[0], f1 = fp[1], f2 = fp[2];
        float arr[12] = {f0.x, f0.y, f0.z, f0.w, f1.x, f1.y, f1.z, f1.w,
                         f2.x, f2.y, f2.z, f2.w};
#pragma unroll
        for (int t = 0; t < 4; t++) {
            float a0 = arr[t * 3], a1 = arr[t * 3 + 1], a2 = arr[t * 3 + 2];
            float dot = fmaf(a0, xi0, fmaf(a1, xi1, a2 * xi2));
            float xxj = fmaf(a0, a0, fmaf(a1, a1, a2 * a2));
            v[4 * q + t] = 2.f * dot - xxi - xxj;
        }
    }
    topk_p1(v, lane, w, wb, cvu, ci);
    __syncthreads();
    if (w == 0) topk_p2(row, lane, cvu, ci);
}

// ---------------------------------------------------------------------------
// Max/min pooling epilogue helper: thread holds acc[8][4] for 8 consecutive
// edges (<=2 point groups) x 4 channels. Exact, order-independent.
// ---------------------------------------------------------------------------
__device__ __forceinline__ void edge_pool_epilogue(const float acc[8][4],
                                                   int e0, int r8, int c4,
                                                   int tid, int pair,
                                                   unsigned* sMx, unsigned* sMn) {
    int eA = e0 + r8;
    int pA = eA / KNN;
    int split = (pA + 1) * KNN - eA; if (split > 8) split = 8;
    int p0 = e0 / KNN;
    float mxA[4], mnA[4], mxB[4], mnB[4];
#pragma unroll
    for (int jj = 0; jj < 4; jj++) {
        mxA[jj] = -3.0e38f; mnA[jj] = 3.0e38f;
        mxB[jj] = -3.0e38f; mnB[jj] = 3.0e38f;
    }
#pragma unroll
    for (int ii = 0; ii < 8; ii++) {
        bool inA = ii < split;
#pragma unroll
        for (int jj = 0; jj < 4; jj++) {
            float v = acc[ii][jj];
            if (inA) { mxA[jj] = fmaxf(mxA[jj], v); mnA[jj] = fminf(mnA[jj], v); }
            else     { mxB[jj] = fmaxf(mxB[jj], v); mnB[jj] = fminf(mnB[jj], v); }
        }
    }
    int lpA = pA - p0;
#pragma unroll
    for (int jj = 0; jj < 4; jj++) {
        atomicMax(&sMx[lpA * 64 + c4 + jj], ford(mxA[jj]));
        atomicMin(&sMn[lpA * 64 + c4 + jj], ford(mnA[jj]));
    }
    if (split < 8) {
        int lpB = lpA + 1;
#pragma unroll
        for (int jj = 0; jj < 4; jj++) {
            atomicMax(&sMx[lpB * 64 + c4 + jj], ford(mxB[jj]));
            atomicMin(&sMn[lpB * 64 + c4 + jj], ford(mnB[jj]));
        }
    }
    __syncthreads();
    unsigned* gMx = g_emaxU + (size_t)pair * PT * 64;
    unsigned* gMn = g_eminU + (size_t)pair * PT * 64;
    for (int idx = tid; idx < 512; idx += 256) {
        int lp = idx >> 6, c = idx & 63;
        int p = p0 + lp;
        if (p < PT) {
            unsigned mx = sMx[idx], mn = sMn[idx];
            if (mx) atomicMax(&gMx[(size_t)p * 64 + c], mx);
            if (mn != 0xFFFFFFFFu) atomicMin(&gMn[(size_t)p * 64 + c], mn);
        }
    }
}

// ---------------------------------------------------------------------------
// Edge layer 1: gather [xj-xi, xi] (6 dims) @ W1^T -> raw hA [E,64] + stats(0)
// ---------------------------------------------------------------------------
__global__ __launch_bounds__(256) void k_edge1(const float* __restrict__ W1) {
    __shared__ __align__(16) float Af[6][68];
    __shared__ __align__(16) float Bw[6][68];
    __shared__ double ssum[64], ssq[64];
    int e00 = blockIdx.x << 8, tid = threadIdx.x;
    if (tid < 64) { ssum[tid] = 0.0; ssq[tid] = 0.0; }
    else if (tid < 128) {
        int o = tid - 64;
#pragma unroll
        for (int c = 0; c < 6; c++) Bw[c][o] = W1[o * 6 + c];
    }
    int tx = tid & 15, ty = tid >> 4;
    int r4 = ty << 2, c4 = tx << 2;
    float tps[4] = {}, tpq[4] = {};
    for (int t = 0; t < 4; t++) {
        int e0 = e00 + (t << 6);
        __syncthreads();
        if (tid < 64) {
            int e = e0 + tid;
            int p = e / KNN;
            int q = (p >> 12) * NN + g_idx[e];
            float p0 = g_feat3[p * 3], p1 = g_feat3[p * 3 + 1], p2 = g_feat3[p * 3 + 2];
            float q0 = g_feat3[q * 3], q1 = g_feat3[q * 3 + 1], q2 = g_feat3[q * 3 + 2];
            Af[0][tid] = q0 - p0; Af[1][tid] = q1 - p1; Af[2][tid] = q2 - p2;
            Af[3][tid] = p0;      Af[4][tid] = p1;      Af[5][tid] = p2;
        }
        __syncthreads();
        float acc[4][4] = {};
#pragma unroll
        for (int k = 0; k < 6; k++) {
            float4 a4 = *(const float4*)&Af[k][r4];
            float4 b4 = *(const float4*)&Bw[k][c4];
            float av[4] = {a4.x, a4.y, a4.z, a4.w};
            float bv[4] = {b4.x, b4.y, b4.z, b4.w};
#pragma unroll
            for (int ii = 0; ii < 4; ii++)
#pragma unroll
                for (int jj = 0; jj < 4; jj++)
                    acc[ii][jj] = fmaf(av[ii], bv[jj], acc[ii][jj]);
        }
#pragma unroll
        for (int ii = 0; ii < 4; ii++)
#pragma unroll
            for (int jj = 0; jj < 4; jj++)
                g_hA[(size_t)(e0 + r4 + ii) * 64 + c4 + jj] = acc[ii][jj];
#pragma unroll
        for (int jj = 0; jj < 4; jj++) {
            float s = 0.f, q = 0.f;
#pragma unroll
            for (int ii = 0; ii < 4; ii++) { float v = acc[ii][jj]; s += v; q = fmaf(v, v, q); }
            tps[jj] += s; tpq[jj] += q;
        }
    }
#pragma unroll
    for (int jj = 0; jj < 4; jj++) {
        tps[jj] += __shfl_down_sync(0xffffffffu, tps[jj], 16);
        tpq[jj] += __shfl_down_sync(0xffffffffu, tpq[jj], 16);
    }
    if ((tid & 31) < 16) {
#pragma unroll
        for (int jj = 0; jj < 4; jj++) {
            atomicAdd(&ssum[c4 + jj], (double)tps[jj]);
            atomicAdd(&ssq[c4 + jj], (double)tpq[jj]);
        }
    }
    __syncthreads();
    if (tid < 64) {
        int bank = (blockIdx.x & (NBANK - 1)) * 8192;
        atomicAdd(&g_sumB[bank + tid], ssum[tid]);
        atomicAdd(&g_sumsqB[bank + tid], ssq[tid]);
    }
}

// ---------------------------------------------------------------------------
// Edge layers 2/4: act_aslot(hA)[E,64] @ W^T[64,64] -> raw max/min pool(pair)
// + stats(oslot). No output tensor store. 128-row tile, 8x4/thread, k16.
// ---------------------------------------------------------------------------
__global__ __launch_bounds__(256) void k_edge128(const float* __restrict__ W,
                                                 int aslot, int oslot, int pair) {
    __shared__ __align__(16) float As[16][132];
    __shared__ __align__(16) float Bs[16][68];
    __shared__ float sS[64], sB[64];
    __shared__ double ssum[64], ssq[64];
    __shared__ unsigned sMx[512], sMn[512];
    int e0 = blockIdx.x << 7, tid = threadIdx.x;
    if (tid < 64) {
        sS[tid] = g_scale[aslot * 1024 + tid];
        sB[tid] = g_bias[aslot * 1024 + tid];
        ssum[tid] = 0.0; ssq[tid] = 0.0;
    }
    for (int l = tid; l < 512; l += 256) { sMx[l] = 0u; sMn[l] = 0xFFFFFFFFu; }
    int tx = tid & 15, ty = tid >> 4;
    int r8 = ty << 3, c4 = tx << 2;
    float acc[8][4] = {};
    for (int k0 = 0; k0 < 64; k0 += 16) {
        __syncthreads();
#pragma unroll
        for (int l = tid; l < 512; l += 256) {
            int r = l >> 2, kq = (l & 3) << 2;
            int c = k0 + kq;
            float4 av = *(const float4*)&g_hA[(size_t)(e0 + r) * 64 + c];
            As[kq + 0][r] = lrelu(av.x * sS[c + 0] + sB[c + 0]);
            As[kq + 1][r] = lrelu(av.y * sS[c + 1] + sB[c + 1]);
            As[kq + 2][r] = lrelu(av.z * sS[c + 2] + sB[c + 2]);
            As[kq + 3][r] = lrelu(av.w * sS[c + 3] + sB[c + 3]);
        }
        {
            int r = tid >> 2, kq = (tid & 3) << 2;
            float4 bv = *(const float4*)&W[(size_t)r * 64 + k0 + kq];
            Bs[kq + 0][r] = bv.x; Bs[kq + 1][r] = bv.y;
            Bs[kq + 2][r] = bv.z; Bs[kq + 3][r] = bv.w;
        }
        __syncthreads();
#pragma unroll
        for (int k = 0; k < 16; k++) {
            float a[8], bb[4];
            *(float4*)&a[0]  = *(const float4*)&As[k][r8];
            *(float4*)&a[4]  = *(const float4*)&As[k][r8 + 4];
            *(float4*)&bb[0] = *(const float4*)&Bs[k][c4];
#pragma unroll
            for (int ii = 0; ii < 8; ii++)
#pragma unroll
                for (int jj = 0; jj < 4; jj++)
                    acc[ii][jj] = fmaf(a[ii], bb[jj], acc[ii][jj]);
        }
    }
    float ps[4], pq[4];
#pragma unroll
    for (int jj = 0; jj < 4; jj++) {
        float s = 0.f, q = 0.f;
#pragma unroll
        for (int ii = 0; ii < 8; ii++) { float v = acc[ii][jj]; s += v; q = fmaf(v, v, q); }
        ps[jj] = s; pq[jj] = q;
    }
#pragma unroll
    for (int jj = 0; jj < 4; jj++) {
        ps[jj] += __shfl_down_sync(0xffffffffu, ps[jj], 16);
        pq[jj] += __shfl_down_sync(0xffffffffu, pq[jj], 16);
    }
    if ((tid & 31) < 16) {
#pragma unroll
        for (int jj = 0; jj < 4; jj++) {
            atomicAdd(&ssum[c4 + jj], (double)ps[jj]);
            atomicAdd(&ssq[c4 + jj], (double)pq[jj]);
        }
    }
    edge_pool_epilogue(acc, e0, r8, c4, tid, pair, sMx, sMn);
    if (tid < 64) {
        int bank = (blockIdx.x & (NBANK - 1)) * 8192;
        atomicAdd(&g_sumB[bank + oslot * 1024 + tid], ssum[tid]);
        atomicAdd(&g_sumsqB[bank + oslot * 1024 + tid], ssq[tid]);
    }
}

// ---------------------------------------------------------------------------
// Edge layers 3/5: gathered 128-dim edge feature @ W^T [64,128] + stats.
// doStore=1: write raw hA (L3). doStore=0: max/min pool to pair (L5).
// ---------------------------------------------------------------------------
__global__ __launch_bounds__(256) void k_edgeG128(const float* __restrict__ W,
                                                  int srcSel, int oslot,
                                                  int doStore, int pair) {
    __shared__ __align__(16) float As[16][132];
    __shared__ __align__(16) float Bs[16][68];
    __shared__ int sP[128], sQ[128];
    __shared__ double ssum[64], ssq[64];
    __shared__ unsigned sMx[512], sMn[512];
    const float* src = (srcSel == 1) ? g_x1 : g_x2;
    int e0 = blockIdx.x << 7, tid = threadIdx.x;
    if (tid < 64) { ssum[tid] = 0.0; ssq[tid] = 0.0; }
    for (int l = tid; l < 512; l += 256) { sMx[l] = 0u; sMn[l] = 0xFFFFFFFFu; }
    if (tid < 128) {
        int e = e0 + tid;
        int p = e / KNN;
        sP[tid] = p;
        sQ[tid] = (p >> 12) * NN + g_idx[e];
    }
    int tx = tid & 15, ty = tid >> 4;
    int r8 = ty << 3, c4 = tx << 2;
    float acc[8][4] = {};
    for (int k0 = 0; k0 < 128; k0 += 16) {
        __syncthreads();
#pragma unroll
        for (int l = tid; l < 512; l += 256) {
            int r = l >> 2, kq = (l & 3) << 2;
            int c = k0 + kq;
            float4 av;
            if (c < 64) {
                float4 aq = *(const float4*)&src[(size_t)sQ[r] * 64 + c];
                float4 ap = *(const float4*)&src[(size_t)sP[r] * 64 + c];
                av.x = aq.x - ap.x; av.y = aq.y - ap.y;
                av.z = aq.z - ap.z; av.w = aq.w - ap.w;
            } else {
                av = *(const float4*)&src[(size_t)sP[r] * 64 + (c - 64)];
            }
            As[kq + 0][r] = av.x; As[kq + 1][r] = av.y;
            As[kq + 2][r] = av.z; As[kq + 3][r] = av.w;
        }
        {
            int r = tid >> 2, kq = (tid & 3) << 2;
            float4 bv = *(const float4*)&W[(size_t)r * 128 + k0 + kq];
            Bs[kq + 0][r] = bv.x; Bs[kq + 1][r] = bv.y;
            Bs[kq + 2][r] = bv.z; Bs[kq + 3][r] = bv.w;
        }
        __syncthreads();
#pragma unroll
        for (int k = 0; k < 16; k++) {
            float a[8], bb[4];
            *(float4*)&a[0]  = *(const float4*)&As[k][r8];
            *(float4*)&a[4]  = *(const float4*)&As[k][r8 + 4];
            *(float4*)&bb[0] = *(const float4*)&Bs[k][c4];
#pragma unroll
            for (int ii = 0; ii < 8; ii++)
#pragma unroll
                for (int jj = 0; jj < 4; jj++)
                    acc[ii][jj] = fmaf(a[ii], bb[jj], acc[ii][jj]);
        }
    }
    if (doStore) {
#pragma unroll
        for (int ii = 0; ii < 8; ii++)
            *(float4*)&g_hA[(size_t)(e0 + r8 + ii) * 64 + c4] = *(float4*)&acc[ii][0];
    }
    float ps[4], pq[4];
#pragma unroll
    for (int jj = 0; jj < 4; jj++) {
        float s = 0.f, q = 0.f;
#pragma unroll
        for (int ii = 0; ii < 8; ii++) { float v = acc[ii][jj]; s += v; q = fmaf(v, v, q); }
        ps[jj] = s; pq[jj] = q;
    }
#pragma unroll
    for (int jj = 0; jj < 4; jj++) {
        ps[jj] += __shfl_down_sync(0xffffffffu, ps[jj], 16);
        pq[jj] += __shfl_down_sync(0xffffffffu, pq[jj], 16);
    }
    if ((tid & 31) < 16) {
#pragma unroll
        for (int jj = 0; jj < 4; jj++) {
            atomicAdd(&ssum[c4 + jj], (double)ps[jj]);
            atomicAdd(&ssq[c4 + jj], (double)pq[jj]);
        }
    }
    if (!doStore) {
        edge_pool_epilogue(acc, e0, r8, c4, tid, pair, sMx, sMn);
    } else {
        __syncthreads();
    }
    if (tid < 64) {
        int bank = (blockIdx.x & (NBANK - 1)) * 8192;
        atomicAdd(&g_sumB[bank + oslot * 1024 + tid], ssum[tid]);
        atomicAdd(&g_sumsqB[bank + oslot * 1024 + tid], ssq[tid]);
    }
}

// x{1,2,3}[p,c] = lrelu(sc * (sc>=0 ? rawmax : rawmin) + bi)
__global__ void k_maxfin(int pair, int slot, int outSel) {
    int t = blockIdx.x * 256 + threadIdx.x;
    if (t >= PT * 64) return;
    int c = t & 63;
    float sc = g_scale[slot * 1024 + c], bi = g_bias[slot * 1024 + c];
    unsigned u = (sc >= 0.f) ? g_emaxU[(size_t)pair * PT * 64 + t]
                             : g_eminU[(size_t)pair * PT * 64 + t];
    float* out = (outSel == 1) ? g_x1 : (outSel == 2 ? g_x2 : g_x3);
    out[t] = lrelu(sc * unford(u) + bi);
}

// ---------------------------------------------------------------------------
// Point GEMMs, 128x128 tile, 8x8/thread, k-sliced 16. Modes:
//   0: A=[x1,x2,x3](192) @ W6 -> NO store; per-(b,c) raw max/min + stats(5)
//   1: A=[x1,x2,x3](192) @ W7[:,1024:] + gcorr -> h7 (stats slot 6)
//   2: A=act6(h7)(512)   @ W8                  -> h8 (stats slot 7)
// ---------------------------------------------------------------------------
__global__ __launch_bounds__(256) void k_point128(const float* __restrict__ W,
                                                  int Cin, int Cout, int wstride,
                                                  int woff, int mode, int aslot,
                                                  int outSel) {
    __shared__ __align__(16) float As[16][132];
    __shared__ __align__(16) float Bs[16][132];
    __shared__ double ssum[128], ssq[128];
    __shared__ unsigned sMaxU[128], sMinU[128];
    int c0 = blockIdx.x << 7, r0 = blockIdx.y << 7;
    int tid = threadIdx.x, tx = tid & 15, ty = tid >> 4;
    int r8 = ty << 3, c8 = tx << 3;
    int b = r0 >> 12;
    if (tid < 128) {
        ssum[tid] = 0.0; ssq[tid] = 0.0;
        sMaxU[tid] = 0u; sMinU[tid] = 0xFFFFFFFFu;
    }
    float acc[8][8] = {};
    for (int k0 = 0; k0 < Cin; k0 += 16) {
        __syncthreads();
#pragma unroll
        for (int l = tid; l < 512; l += 256) {
            int r = l >> 2, kq = (l & 3) << 2;
            int c = k0 + kq, row = r0 + r;
            float4 av;
            if (mode != 2) {
                const float* sp = (c < 64) ? &g_x1[(size_t)row * 64 + c]
                               : (c < 128) ? &g_x2[(size_t)row * 64 + (c - 64)]
                                           : &g_x3[(size_t)row * 64 + (c - 128)];
                av = *(const float4*)sp;
            } else {
                av = *(const float4*)&g_h7[(size_t)row * 512 + c];
                av.x = lrelu(av.x * g_scale[aslot * 1024 + c + 0] + g_bias[aslot * 1024 + c + 0]);
                av.y = lrelu(av.y * g_scale[aslot * 1024 + c + 1] + g_bias[aslot * 1024 + c + 1]);
                av.z = lrelu(av.z * g_scale[aslot * 1024 + c + 2] + g_bias[aslot * 1024 + c + 2]);
                av.w = lrelu(av.w * g_scale[aslot * 1024 + c + 3] + g_bias[aslot * 1024 + c + 3]);
            }
            As[kq + 0][r] = av.x; As[kq + 1][r] = av.y;
            As[kq + 2][r] = av.z; As[kq + 3][r] = av.w;
            float4 bv = *(const float4*)&W[(size_t)(c0 + r) * wstride + woff + k0 + kq];
            Bs[kq + 0][r] = bv.x; Bs[kq + 1][r] = bv.y;
            Bs[kq + 2][r] = bv.z; Bs[kq + 3][r] = bv.w;
        }
        __syncthreads();
#pragma unroll
        for (int k = 0; k < 16; k++) {
            float a[8], bb[8];
            *(float4*)&a[0]  = *(const float4*)&As[k][r8];
            *(float4*)&a[4]  = *(const float4*)&As[k][r8 + 4];
            *(float4*)&bb[0] = *(const float4*)&Bs[k][c8];
            *(float4*)&bb[4] = *(const float4*)&Bs[k][c8 + 4];
#pragma unroll
            for (int ii = 0; ii < 8; ii++)
#pragma unroll
                for (int jj = 0; jj < 8; jj++)
                    acc[ii][jj] = fmaf(a[ii], bb[jj], acc[ii][jj]);
        }
    }
    if (mode == 1) {
#pragma unroll
        for (int jj = 0; jj < 8; jj++) {
            float gc = g_gcorr[b * 512 + c0 + c8 + jj];
#pragma unroll
            for (int ii = 0; ii < 8; ii++) acc[ii][jj] += gc;
        }
    }
    if (outSel != 0) {
        float* out = (outSel == 1) ? g_h7 : g_h8;
#pragma unroll
        for (int ii = 0; ii < 8; ii++) {
            float* dst = &out[(size_t)(r0 + r8 + ii) * Cout + c0 + c8];
            *(float4*)&dst[0] = *(float4*)&acc[ii][0];
            *(float4*)&dst[4] = *(float4*)&acc[ii][4];
        }
    }
    int slot = 5 + outSel;
    float ps[8], pq[8];
#pragma unroll
    for (int jj = 0; jj < 8; jj++) {
        float s = 0.f, q = 0.f;
#pragma unroll
        for (int ii = 0; ii < 8; ii++) { float v = acc[ii][jj]; s += v; q = fmaf(v, v, q); }
        ps[jj] = s; pq[jj] = q;
    }
#pragma unroll
    for (int jj = 0; jj < 8; jj++) {
        ps[jj] += __shfl_down_sync(0xffffffffu, ps[jj], 16);
        pq[jj] += __shfl_down_sync(0xffffffffu, pq[jj], 16);
    }
    if ((tid & 31) < 16) {
#pragma unroll
        for (int jj = 0; jj < 8; jj++) {
            atomicAdd(&ssum[c8 + jj], (double)ps[jj]);
            atomicAdd(&ssq[c8 + jj], (double)pq[jj]);
        }
    }
    if (outSel == 0) {
        float mx[8], mn[8];
#pragma unroll
        for (int jj = 0; jj < 8; jj++) {
            float a = acc[0][jj], c = acc[0][jj];
#pragma unroll
            for (int ii = 1; ii < 8; ii++) {
                a = fmaxf(a, acc[ii][jj]);
                c = fminf(c, acc[ii][jj]);
            }
            mx[jj] = a; mn[jj] = c;
        }
#pragma unroll
        for (int jj = 0; jj < 8; jj++) {
            mx[jj] = fmaxf(mx[jj], __shfl_down_sync(0xffffffffu, mx[jj], 16));
            mn[jj] = fminf(mn[jj], __shfl_down_sync(0xffffffffu, mn[jj], 16));
        }
        if ((tid & 31) < 16) {
#pragma unroll
            for (int jj = 0; jj < 8; jj++) {
                atomicMax(&sMaxU[c8 + jj], ford(mx[jj]));
                atomicMin(&sMinU[c8 + jj], ford(mn[jj]));
            }
        }
    }
    __syncthreads();
    if (tid < 128) {
        int bank = (blockIdx.y & (NBANK - 1)) * 8192;
        atomicAdd(&g_sumB[bank + slot * 1024 + c0 + tid], ssum[tid]);
        atomicAdd(&g_sumsqB[bank + slot * 1024 + c0 + tid], ssq[tid]);
        if (outSel == 0) {
            atomicMax(&g_hmaxU[b * 1024 + c0 + tid], sMaxU[tid]);
            atomicMin(&g_hminU[b * 1024 + c0 + tid], sMinU[tid]);
        }
    }
}

// gmax[b,c] = lrelu(sc * (sc>=0 ? hmax : hmin) + bi)   (monotone pooling)
__global__ void k_gmaxfin() {
    int t = blockIdx.x * 256 + threadIdx.x;
    if (t >= BB * 1024) return;
    int c = t & 1023;
    float sc = g_scale[5 * 1024 + c], bi = g_bias[5 * 1024 + c];
    unsigned u = (sc >= 0.f) ? g_hmaxU[t] : g_hminU[t];
    g_gmax[t] = lrelu(sc * unford(u) + bi);
}

// gcorr[b,o] = sum_c gmax[b,c] * W7[o,c]  (c < 1024); warp per output
__global__ void k_gcorr(const float* __restrict__ W7) {
    int b = blockIdx.y;
    int o = blockIdx.x * 8 + (threadIdx.x >> 5);
    int lane = threadIdx.x & 31;
    const float* gm = g_gmax + b * 1024;
    const float* w  = W7 + (size_t)o * 1216;
    float s = 0.f;
#pragma unroll 8
    for (int k = lane; k < 1024; k += 32) s = fmaf(gm[k], w[k], s);
#pragma unroll
    for (int off = 16; off; off >>= 1) s += __shfl_down_sync(0xffffffffu, s, off);
    if (lane == 0) g_gcorr[b * 512 + o] = s;
}

// fold (gamma, beta, mean, var) -> per-channel scale/bias (sums 16 banks)
__global__ void k_fin(int slot, int C, double invM,
                      const float* __restrict__ g, const float* __restrict__ b) {
    int c = blockIdx.x * 256 + threadIdx.x;
    if (c >= C) return;
    double sm = 0.0, sq = 0.0;
#pragma unroll
    for (int k = 0; k < NBANK; k++) {
        sm += g_sumB[k * 8192 + slot * 1024 + c];
        sq += g_sumsqB[k * 8192 + slot * 1024 + c];
    }
    double mean = sm * invM;
    double var  = sq * invM - mean * mean;
    float sc    = g[c] * rsqrtf((float)var + EPSBN);
    g_scale[slot * 1024 + c] = sc;
    g_bias[slot * 1024 + c]  = b[c] - (float)mean * sc;
}

// ---------------------------------------------------------------------------
// Final: out[P,9] = act7(h8) @ W9^T
// ---------------------------------------------------------------------------
__global__ void k_out9(const float* __restrict__ W9, float* __restrict__ out) {
    int t = blockIdx.x * 256 + threadIdx.x;
    if (t >= PT * 9) return;
    int p = t / 9, o = t - p * 9;
    const float* row = g_h8 + (size_t)p * 256;
    const float* w   = W9 + o * 256;
    float acc = 0.f;
#pragma unroll 4
    for (int k = 0; k < 256; k++) {
        float v = lrelu(row[k] * g_scale[7 * 1024 + k] + g_bias[7 * 1024 + k]);
        acc = fmaf(v, w[k], acc);
    }
    out[t] = acc;
}

// ---------------------------------------------------------------------------
// Host launcher
// ---------------------------------------------------------------------------
extern "C" void kernel_launch(void* const* d_in, const int* in_sizes, int n_in,
                              void* d_out, int out_size) {
    int base = (in_sizes[1] == 1) ? 2 : 1;
    const float* x = (const float*)d_in[0];
    const float* W[9];
    const float* G[8];
    const float* Bt[8];
    for (int i = 0; i < 9; i++) W[i] = (const float*)d_in[base + i];
    for (int i = 0; i < 8; i++) {
        G[i]  = (const float*)d_in[base + 9 + 2 * i];
        Bt[i] = (const float*)d_in[base + 10 + 2 * i];
    }
    float* out = (float*)d_out;

    const double invE = 1.0 / (double)ET;
    const double invP = 1.0 / (double)PT;

    k_zero<<<(NBANK * 8 * 1024) / 256, 256>>>();
    k_zmm<<<(3 * PT * 64 / 4 + 255) / 256, 256>>>();
    k_prep3<<<PT / 256, 256>>>(x);

    // ---- stage 1: fused knn on xyz, edge layers 1-2, maxpool -> x1 ----
    k_topk3<<<PT, 256>>>();
    k_edge1<<<ET / 256, 256>>>(W[0]);
    k_fin<<<1, 256>>>(0, 64, invE, G[0], Bt[0]);
    k_edge128<<<ET / 128, 256>>>(W[1], 0, 1, 0);
    k_fin<<<1, 256>>>(1, 64, invE, G[1], Bt[1]);
    k_maxfin<<<PT * 64 / 256, 256>>>(0, 1, 1);

    // ---- stage 2: knn on x1, edge layers 3-4, maxpool -> x2 ----
    k_xx64<<<PT * 32 / 256, 256>>>(1);
    k_dist128sym<<<dim3(528, BB), 256>>>(1);
    k_topk<<<PT, 256>>>();
    k_edgeG128<<<ET / 128, 256>>>(W[2], 1, 2, 1, 0);
    k_fin<<<1, 256>>>(2, 64, invE, G[2], Bt[2]);
    k_edge128<<<ET / 128, 256>>>(W[3], 2, 3, 1);
    k_fin<<<1, 256>>>(3, 64, invE, G[3], Bt[3]);
    k_maxfin<<<PT * 64 / 256, 256>>>(1, 3, 2);

    // ---- stage 3: knn on x2, edge layer 5, maxpool -> x3 ----
    k_xx64<<<PT * 32 / 256, 256>>>(2);
    k_dist128sym<<<dim3(528, BB), 256>>>(2);
    k_topk<<<PT, 256>>>();
    k_edgeG128<<<ET / 128, 256>>>(W[4], 2, 4, 0, 2);
    k_fin<<<1, 256>>>(4, 64, invE, G[4], Bt[4]);
    k_maxfin<<<PT * 64 / 256, 256>>>(2, 4, 3);

    // ---- point layers 6-9 ----
    k_point128<<<dim3(8, PT / 128), 256>>>(W[5], 192, 1024, 192, 0, 0, 0, 0);
    k_fin<<<4, 256>>>(5, 1024, invP, G[5], Bt[5]);
    k_gmaxfin<<<32, 256>>>();
    k_gcorr<<<dim3(64, BB), 256>>>(W[6]);
    k_point128<<<dim3(4, PT / 128), 256>>>(W[6], 192, 512, 1216, 1024, 1, 0, 1);
    k_fin<<<2, 256>>>(6, 512, invP, G[6], Bt[6]);
    k_point128<<<dim3(2, PT / 128), 256>>>(W[7], 512, 256, 512, 0, 2, 6, 2);
    k_fin<<<1, 256>>>(7, 256, invP, G[7], Bt[7]);
    k_out9<<<(PT * 9 + 255) / 256, 256>>>(W[8], out);
}

// round 17
// speedup vs baseline: 1.3007x; 1.1904x over previous
#include <cuda_runtime.h>

#define KNN   20
#define BB    8
#define NN    4096
#define PT    (BB * NN)          /* 32768  points */
#define ET    (PT * KNN)         /* 655360 edges  */
#define EPSBN 1e-5f
#define NBANK 16

// ---------------------------------------------------------------------------
// Static device scratch (no allocations anywhere)
// ---------------------------------------------------------------------------
static __device__ float  g_feat3[PT * 3];
static __device__ float  g_xx[PT];
static __device__ float  g_dist[(size_t)PT * NN];        // 512 MB
static __device__ int    g_idx[ET];
static __device__ float  g_hA[(size_t)ET * 64];          // 160 MB
static __device__ float  g_x1[PT * 64];
static __device__ float  g_x2[PT * 64];
static __device__ float  g_x3[PT * 64];
static __device__ float  g_h7[(size_t)PT * 512];
static __device__ float  g_h8[(size_t)PT * 256];
static __device__ unsigned g_emaxU[3 * (size_t)PT * 64]; // raw max per (p,c), 3 pools
static __device__ unsigned g_eminU[3 * (size_t)PT * 64]; // raw min per (p,c)
static __device__ unsigned g_hmaxU[BB * 1024];
static __device__ unsigned g_hminU[BB * 1024];
static __device__ float  g_gmax[BB * 1024];
static __device__ float  g_gcorr[BB * 512];
static __device__ double g_sumB[NBANK * 8 * 1024];       // banked stats
static __device__ double g_sumsqB[NBANK * 8 * 1024];
static __device__ float  g_scale[8 * 1024];
static __device__ float  g_bias[8 * 1024];

__device__ __forceinline__ float lrelu(float v) { return v > 0.f ? v : 0.2f * v; }

// monotone float -> unsigned transform (preserves total order)
__device__ __forceinline__ unsigned ford(float f) {
    unsigned u = __float_as_uint(f);
    return (u & 0x80000000u) ? ~u : (u | 0x80000000u);
}
__device__ __forceinline__ float unford(unsigned u) {
    return (u & 0x80000000u) ? __uint_as_float(u & 0x7FFFFFFFu)
                             : __uint_as_float(~u);
}

// ---------------------------------------------------------------------------
// Zero BN statistic accumulators + minmax accumulators (graph-replay safe)
// ---------------------------------------------------------------------------
__global__ void k_zero() {
    int t = blockIdx.x * 256 + threadIdx.x;
    if (t < NBANK * 8 * 1024) { g_sumB[t] = 0.0; g_sumsqB[t] = 0.0; }
    if (t < BB * 1024) { g_hmaxU[t] = 0u; g_hminU[t] = 0xFFFFFFFFu; }
}

// zero the 3 edge-pool max/min arrays (uint4 vectorized)
__global__ void k_zmm() {
    size_t t = (size_t)(blockIdx.x * 256 + threadIdx.x) * 4;
    if (t < 3 * (size_t)PT * 64) {
        *(uint4*)&g_emaxU[t] = make_uint4(0u, 0u, 0u, 0u);
        *(uint4*)&g_eminU[t] = make_uint4(0xFFFFFFFFu, 0xFFFFFFFFu, 0xFFFFFFFFu, 0xFFFFFFFFu);
    }
}

// ---------------------------------------------------------------------------
// Transpose x [B,3,N] -> feat3 [P,3] and squared norms
// ---------------------------------------------------------------------------
__global__ void k_prep3(const float* __restrict__ x) {
    int p = blockIdx.x * 256 + threadIdx.x;
    if (p >= PT) return;
    int b = p >> 12, n = p & (NN - 1);
    const float* xb = x + (size_t)b * 3 * NN;
    float a0 = xb[n], a1 = xb[NN + n], a2 = xb[2 * NN + n];
    g_feat3[p * 3 + 0] = a0;
    g_feat3[p * 3 + 1] = a1;
    g_feat3[p * 3 + 2] = a2;
    g_xx[p] = a0 * a0 + a1 * a1 + a2 * a2;
}

// squared norms of [P,64] feature arrays; warp per row
__global__ void k_xx64(int sel) {
    const float* f = (sel == 1) ? g_x1 : g_x2;
    int gt = blockIdx.x * 256 + threadIdx.x;
    int w = gt >> 5, lane = gt & 31;
    if (w >= PT) return;
    const float* r = f + ((size_t)w << 6);
    float v0 = r[lane], v1 = r[lane + 32];
    float s = v0 * v0 + v1 * v1;
#pragma unroll
    for (int o = 16; o; o >>= 1) s += __shfl_down_sync(0xffffffffu, s, o);
    if (lane == 0) g_xx[w] = s;
}

// ---------------------------------------------------------------------------
// Pairwise neg. squared distance, C=64, SYMMETRIC upper-triangle tiles.
// grid (528, B), 256 threads, 8x8 per thread, k-sliced 16
// ---------------------------------------------------------------------------
__global__ __launch_bounds__(256) void k_dist128sym(int sel) {
    __shared__ __align__(16) float As[16][132];
    __shared__ __align__(16) float Bs[16][132];
    __shared__ float sxi[128], sxj[128];
    const float* f = (sel == 1) ? g_x1 : g_x2;
    int b = blockIdx.y;
    int rem = blockIdx.x, ti = 0;
    while (rem >= 32 - ti) { rem -= 32 - ti; ti++; }
    int tj = ti + rem;
    int i0 = ti << 7, j0 = tj << 7;
    int tid = threadIdx.x, tx = tid & 15, ty = tid >> 4;
    int r8 = ty << 3, c8 = tx << 3;
    int bi = b * NN + i0, bj = b * NN + j0;
    if (tid < 128) sxi[tid] = g_xx[bi + tid];
    else           sxj[tid - 128] = g_xx[bj + tid - 128];
    float acc[8][8] = {};
    for (int k0 = 0; k0 < 64; k0 += 16) {
        __syncthreads();
#pragma unroll
        for (int l = tid; l < 512; l += 256) {
            int r = l >> 2, kq = (l & 3) << 2;
            float4 av = *(const float4*)&f[(size_t)(bi + r) * 64 + k0 + kq];
            As[kq + 0][r] = av.x; As[kq + 1][r] = av.y;
            As[kq + 2][r] = av.z; As[kq + 3][r] = av.w;
            float4 bv = *(const float4*)&f[(size_t)(bj + r) * 64 + k0 + kq];
            Bs[kq + 0][r] = bv.x; Bs[kq + 1][r] = bv.y;
            Bs[kq + 2][r] = bv.z; Bs[kq + 3][r] = bv.w;
        }
        __syncthreads();
#pragma unroll
        for (int k = 0; k < 16; k++) {
            float a[8], bb[8];
            *(float4*)&a[0]  = *(const float4*)&As[k][r8];
            *(float4*)&a[4]  = *(const float4*)&As[k][r8 + 4];
            *(float4*)&bb[0] = *(const float4*)&Bs[k][c8];
            *(float4*)&bb[4] = *(const float4*)&Bs[k][c8 + 4];
#pragma unroll
            for (int ii = 0; ii < 8; ii++)
#pragma unroll
                for (int jj = 0; jj < 8; jj++)
                    acc[ii][jj] = fmaf(a[ii], bb[jj], acc[ii][jj]);
        }
    }
    // i-rows: dist[i,j] = (2*acc - xxi) - xxj
#pragma unroll
    for (int ii = 0; ii < 8; ii++) {
        float xi = sxi[r8 + ii];
        float o[8];
#pragma unroll
        for (int jj = 0; jj < 8; jj++)
            o[jj] = 2.f * acc[ii][jj] - xi - sxj[c8 + jj];
        float* dst = &g_dist[(size_t)(b * NN + i0 + r8 + ii) * NN + j0 + c8];
        *(float4*)&dst[0] = *(float4*)&o[0];
        *(float4*)&dst[4] = *(float4*)&o[4];
    }
    // j-rows (transposed): dist[j,i] = (2*acc - xxj) - xxi  (row norm FIRST)
    if (ti != tj) {
#pragma unroll
        for (int jj = 0; jj < 8; jj++) {
            float xj = sxj[c8 + jj];
            float o[8];
#pragma unroll
            for (int ii = 0; ii < 8; ii++)
                o[ii] = 2.f * acc[ii][jj] - xj - sxi[r8 + ii];
            float* dst = &g_dist[(size_t)(b * NN + j0 + c8 + jj) * NN + i0 + r8];
            *(float4*)&dst[0] = *(float4*)&o[0];
            *(float4*)&dst[4] = *(float4*)&o[4];
        }
    }
}

// ---------------------------------------------------------------------------
// Top-K: 8 warps/row, 16 elems/lane, REDUX argmax + per-lane top-2 cache.
// A winning lane promotes its cached 2nd-best in O(1); full masked rescan
// (recomputing the top-2) only on a second win without refill. Exact.
// ---------------------------------------------------------------------------
__device__ __forceinline__ void topk_p1(float (&v)[16], int lane, int w,
                                        int wb, unsigned* cvu, int* ci) {
    float m1 = -3.0e38f, m2 = -3.0e38f;
    int   p1 = 0, p2 = 0;
#pragma unroll
    for (int i = 0; i < 16; i++) {
        float x = v[i];
        if (x > m1) { m2 = m1; p2 = p1; m1 = x; p1 = i; }
        else if (x > m2) { m2 = x; p2 = i; }
    }
    unsigned mask = 0u;
    bool have2 = true;
    for (int r = 0; r < KNN; r++) {
        unsigned fu = ford(m1);
        unsigned best = __reduce_max_sync(0xffffffffu, fu);
        unsigned bal  = __ballot_sync(0xffffffffu, fu == best);
        int wlane = __ffs(bal) - 1;
        int wpos  = __shfl_sync(0xffffffffu, p1, wlane);
        if (lane == r) {
            cvu[w * 20 + r] = best;
            ci[w * 20 + r]  = wb + ((wpos >> 2) << 7) + (wlane << 2) + (wpos & 3);
        }
        if (lane == wlane) {
            mask |= 1u << p1;
            if (have2) {
                m1 = m2; p1 = p2; have2 = false;
            } else {
                m1 = -3.0e38f; m2 = -3.0e38f; p1 = 0; p2 = 0;
#pragma unroll
                for (int i = 0; i < 16; i++) {
                    if ((mask >> i) & 1u) continue;
                    float x = v[i];
                    if (x > m1) { m2 = m1; p2 = p1; m1 = x; p1 = i; }
                    else if (x > m2) { m2 = x; p2 = i; }
                }
                have2 = true;
            }
        }
    }
}

__device__ __forceinline__ void topk_p2(int row, int lane, unsigned* cvu, int* ci) {
    unsigned uv[5];
#pragma unroll
    for (int u = 0; u < 5; u++)
        uv[u] = cvu[lane + 32 * u];
    // per-lane top-2 of the 5 candidates
    unsigned m1 = 0u, m2 = 0u; int p1 = 0, p2 = 0;
#pragma unroll
    for (int u = 0; u < 5; u++) {
        unsigned x = uv[u];
        if (x > m1) { m2 = m1; p2 = p1; m1 = x; p1 = u; }
        else if (x > m2) { m2 = x; p2 = u; }
    }
    unsigned mask = 0u;
    bool have2 = true;
    for (int r = 0; r < KNN; r++) {
        unsigned best = __reduce_max_sync(0xffffffffu, m1);
        unsigned bal  = __ballot_sync(0xffffffffu, m1 == best);
        int wl = __ffs(bal) - 1;
        int wu = __shfl_sync(0xffffffffu, p1, wl);
        if (lane == 0) g_idx[(size_t)row * KNN + r] = ci[wl + 32 * wu];
        if (lane == wl) {
            mask |= 1u << p1;
            if (have2) {
                m1 = m2; p1 = p2; have2 = false;
            } else {
                m1 = 0u; m2 = 0u; p1 = 0; p2 = 0;
#pragma unroll
                for (int u = 0; u < 5; u++) {
                    if ((mask >> u) & 1u) continue;
                    unsigned x = uv[u];
                    if (x > m1) { m2 = m1; p2 = p1; m1 = x; p1 = u; }
                    else if (x > m2) { m2 = x; p2 = u; }
                }
                have2 = true;
            }
        }
    }
}

// stages 2/3: read precomputed g_dist
__global__ __launch_bounds__(256) void k_topk() {
    __shared__ unsigned cvu[160];
    __shared__ int      ci[160];
    int row = blockIdx.x;
    int tid = threadIdx.x, lane = tid & 31, w = tid >> 5;
    int wb = w * 512;
    const float4* base = (const float4*)(g_dist + (size_t)row * NN + wb);
    float v[16];
#pragma unroll
    for (int q = 0; q < 4; q++) {
        float4 t4 = base[q * 32 + lane];
        v[4 * q + 0] = t4.x; v[4 * q + 1] = t4.y;
        v[4 * q + 2] = t4.z; v[4 * q + 3] = t4.w;
    }
    topk_p1(v, lane, w, wb, cvu, ci);
    __syncthreads();
    if (w == 0) topk_p2(row, lane, cvu, ci);
}

// stage 1: compute 3-D distances inline (no dist matrix round-trip)
__global__ __launch_bounds__(256) void k_topk3() {
    __shared__ unsigned cvu[160];
    __shared__ int      ci[160];
    int row = blockIdx.x;
    int tid = threadIdx.x, lane = tid & 31, w = tid >> 5;
    int b = row >> 12;
    int wb = w * 512;
    float xi0 = g_feat3[row * 3], xi1 = g_feat3[row * 3 + 1], xi2 = g_feat3[row * 3 + 2];
    float xxi = g_xx[row];
    float v[16];
#pragma unroll
    for (int q = 0; q < 4; q++) {
        int j0 = wb + q * 128 + lane * 4;
        const float4* fp = (const float4*)(g_feat3 + ((size_t)(b * NN) + j0) * 3);
        float4 f0 = fp[0], f1 = fp[1], f2 = fp[2];
        float arr[12] = {f0.x, f0.y, f0.z, f0.w, f1.x, f1.y, f1.z, f1.w,
                         f2.x, f2.y, f2.z, f2.w};
#pragma unroll
        for (int t = 0; t < 4; t++) {
            float a0 = arr[t * 3], a1 = arr[t * 3 + 1], a2 = arr[t * 3 + 2];
            float dot = fmaf(a0, xi0, fmaf(a1, xi1, a2 * xi2));
            float xxj = fmaf(a0, a0, fmaf(a1, a1, a2 * a2));
            v[4 * q + t] = 2.f * dot - xxi - xxj;
        }
    }
    topk_p1(v, lane, w, wb, cvu, ci);
    __syncthreads();
    if (w == 0) topk_p2(row, lane, cvu, ci);
}

// ---------------------------------------------------------------------------
// Max/min pooling epilogue helper: thread holds acc[8][4] for 8 consecutive
// edges (<=2 point groups) x 4 channels. Exact, order-independent.
// ---------------------------------------------------------------------------
__device__ __forceinline__ void edge_pool_epilogue(const float acc[8][4],
                                                   int e0, int r8, int c4,
                                                   int tid, int pair,
                                                   unsigned* sMx, unsigned* sMn) {
    int eA = e0 + r8;
    int pA = eA / KNN;
    int split = (pA + 1) * KNN - eA; if (split > 8) split = 8;
    int p0 = e0 / KNN;
    float mxA[4], mnA[4], mxB[4], mnB[4];
#pragma unroll
    for (int jj = 0; jj < 4; jj++) {
        mxA[jj] = -3.0e38f; mnA[jj] = 3.0e38f;
        mxB[jj] = -3.0e38f; mnB[jj] = 3.0e38f;
    }
#pragma unroll
    for (int ii = 0; ii < 8; ii++) {
        bool inA = ii < split;
#pragma unroll
        for (int jj = 0; jj < 4; jj++) {
            float v = acc[ii][jj];
            if (inA) { mxA[jj] = fmaxf(mxA[jj], v); mnA[jj] = fminf(mnA[jj], v); }
            else     { mxB[jj] = fmaxf(mxB[jj], v); mnB[jj] = fminf(mnB[jj], v); }
        }
    }
    int lpA = pA - p0;
#pragma unroll
    for (int jj = 0; jj < 4; jj++) {
        atomicMax(&sMx[lpA * 64 + c4 + jj], ford(mxA[jj]));
        atomicMin(&sMn[lpA * 64 + c4 + jj], ford(mnA[jj]));
    }
    if (split < 8) {
        int lpB = lpA + 1;
#pragma unroll
        for (int jj = 0; jj < 4; jj++) {
            atomicMax(&sMx[lpB * 64 + c4 + jj], ford(mxB[jj]));
            atomicMin(&sMn[lpB * 64 + c4 + jj], ford(mnB[jj]));
        }
    }
    __syncthreads();
    unsigned* gMx = g_emaxU + (size_t)pair * PT * 64;
    unsigned* gMn = g_eminU + (size_t)pair * PT * 64;
    for (int idx = tid; idx < 512; idx += 256) {
        int lp = idx >> 6, c = idx & 63;
        int p = p0 + lp;
        if (p < PT) {
            unsigned mx = sMx[idx], mn = sMn[idx];
            if (mx) atomicMax(&gMx[(size_t)p * 64 + c], mx);
            if (mn != 0xFFFFFFFFu) atomicMin(&gMn[(size_t)p * 64 + c], mn);
        }
    }
}

// ---------------------------------------------------------------------------
// Edge layer 1: gather [xj-xi, xi] (6 dims) @ W1^T -> raw hA [E,64] + stats(0)
// ---------------------------------------------------------------------------
__global__ __launch_bounds__(256) void k_edge1(const float* __restrict__ W1) {
    __shared__ __align__(16) float Af[6][68];
    __shared__ __align__(16) float Bw[6][68];
    __shared__ double ssum[64], ssq[64];
    int e00 = blockIdx.x << 8, tid = threadIdx.x;
    if (tid < 64) { ssum[tid] = 0.0; ssq[tid] = 0.0; }
    else if (tid < 128) {
        int o = tid - 64;
#pragma unroll
        for (int c = 0; c < 6; c++) Bw[c][o] = W1[o * 6 + c];
    }
    int tx = tid & 15, ty = tid >> 4;
    int r4 = ty << 2, c4 = tx << 2;
    float tps[4] = {}, tpq[4] = {};
    for (int t = 0; t < 4; t++) {
        int e0 = e00 + (t << 6);
        __syncthreads();
        if (tid < 64) {
            int e = e0 + tid;
            int p = e / KNN;
            int q = (p >> 12) * NN + g_idx[e];
            float p0 = g_feat3[p * 3], p1 = g_feat3[p * 3 + 1], p2 = g_feat3[p * 3 + 2];
            float q0 = g_feat3[q * 3], q1 = g_feat3[q * 3 + 1], q2 = g_feat3[q * 3 + 2];
            Af[0][tid] = q0 - p0; Af[1][tid] = q1 - p1; Af[2][tid] = q2 - p2;
            Af[3][tid] = p0;      Af[4][tid] = p1;      Af[5][tid] = p2;
        }
        __syncthreads();
        float acc[4][4] = {};
#pragma unroll
        for (int k = 0; k < 6; k++) {
            float4 a4 = *(const float4*)&Af[k][r4];
            float4 b4 = *(const float4*)&Bw[k][c4];
            float av[4] = {a4.x, a4.y, a4.z, a4.w};
            float bv[4] = {b4.x, b4.y, b4.z, b4.w};
#pragma unroll
            for (int ii = 0; ii < 4; ii++)
#pragma unroll
                for (int jj = 0; jj < 4; jj++)
                    acc[ii][jj] = fmaf(av[ii], bv[jj], acc[ii][jj]);
        }
#pragma unroll
        for (int ii = 0; ii < 4; ii++)
#pragma unroll
            for (int jj = 0; jj < 4; jj++)
                g_hA[(size_t)(e0 + r4 + ii) * 64 + c4 + jj] = acc[ii][jj];
#pragma unroll
        for (int jj = 0; jj < 4; jj++) {
            float s = 0.f, q = 0.f;
#pragma unroll
            for (int ii = 0; ii < 4; ii++) { float v = acc[ii][jj]; s += v; q = fmaf(v, v, q); }
            tps[jj] += s; tpq[jj] += q;
        }
    }
#pragma unroll
    for (int jj = 0; jj < 4; jj++) {
        tps[jj] += __shfl_down_sync(0xffffffffu, tps[jj], 16);
        tpq[jj] += __shfl_down_sync(0xffffffffu, tpq[jj], 16);
    }
    if ((tid & 31) < 16) {
#pragma unroll
        for (int jj = 0; jj < 4; jj++) {
            atomicAdd(&ssum[c4 + jj], (double)tps[jj]);
            atomicAdd(&ssq[c4 + jj], (double)tpq[jj]);
        }
    }
    __syncthreads();
    if (tid < 64) {
        int bank = (blockIdx.x & (NBANK - 1)) * 8192;
        atomicAdd(&g_sumB[bank + tid], ssum[tid]);
        atomicAdd(&g_sumsqB[bank + tid], ssq[tid]);
    }
}

// ---------------------------------------------------------------------------
// Edge layers 2/4: act_aslot(hA)[E,64] @ W^T[64,64] -> raw max/min pool(pair)
// + stats(oslot). No output tensor store. 128-row tile, 8x4/thread, k16.
// ---------------------------------------------------------------------------
__global__ __launch_bounds__(256) void k_edge128(const float* __restrict__ W,
                                                 int aslot, int oslot, int pair) {
    __shared__ __align__(16) float As[16][132];
    __shared__ __align__(16) float Bs[16][68];
    __shared__ float sS[64], sB[64];
    __shared__ double ssum[64], ssq[64];
    __shared__ unsigned sMx[512], sMn[512];
    int e0 = blockIdx.x << 7, tid = threadIdx.x;
    if (tid < 64) {
        sS[tid] = g_scale[aslot * 1024 + tid];
        sB[tid] = g_bias[aslot * 1024 + tid];
        ssum[tid] = 0.0; ssq[tid] = 0.0;
    }
    for (int l = tid; l < 512; l += 256) { sMx[l] = 0u; sMn[l] = 0xFFFFFFFFu; }
    int tx = tid & 15, ty = tid >> 4;
    int r8 = ty << 3, c4 = tx << 2;
    float acc[8][4] = {};
    for (int k0 = 0; k0 < 64; k0 += 16) {
        __syncthreads();
#pragma unroll
        for (int l = tid; l < 512; l += 256) {
            int r = l >> 2, kq = (l & 3) << 2;
            int c = k0 + kq;
            float4 av = *(const float4*)&g_hA[(size_t)(e0 + r) * 64 + c];
            As[kq + 0][r] = lrelu(av.x * sS[c + 0] + sB[c + 0]);
            As[kq + 1][r] = lrelu(av.y * sS[c + 1] + sB[c + 1]);
            As[kq + 2][r] = lrelu(av.z * sS[c + 2] + sB[c + 2]);
            As[kq + 3][r] = lrelu(av.w * sS[c + 3] + sB[c + 3]);
        }
        {
            int r = tid >> 2, kq = (tid & 3) << 2;
            float4 bv = *(const float4*)&W[(size_t)r * 64 + k0 + kq];
            Bs[kq + 0][r] = bv.x; Bs[kq + 1][r] = bv.y;
            Bs[kq + 2][r] = bv.z; Bs[kq + 3][r] = bv.w;
        }
        __syncthreads();
#pragma unroll
        for (int k = 0; k < 16; k++) {
            float a[8], bb[4];
            *(float4*)&a[0]  = *(const float4*)&As[k][r8];
            *(float4*)&a[4]  = *(const float4*)&As[k][r8 + 4];
            *(float4*)&bb[0] = *(const float4*)&Bs[k][c4];
#pragma unroll
            for (int ii = 0; ii < 8; ii++)
#pragma unroll
                for (int jj = 0; jj < 4; jj++)
                    acc[ii][jj] = fmaf(a[ii], bb[jj], acc[ii][jj]);
        }
    }
    float ps[4], pq[4];
#pragma unroll
    for (int jj = 0; jj < 4; jj++) {
        float s = 0.f, q = 0.f;
#pragma unroll
        for (int ii = 0; ii < 8; ii++) { float v = acc[ii][jj]; s += v; q = fmaf(v, v, q); }
        ps[jj] = s; pq[jj] = q;
    }
#pragma unroll
    for (int jj = 0; jj < 4; jj++) {
        ps[jj] += __shfl_down_sync(0xffffffffu, ps[jj], 16);
        pq[jj] += __shfl_down_sync(0xffffffffu, pq[jj], 16);
    }
    if ((tid & 31) < 16) {
#pragma unroll
        for (int jj = 0; jj < 4; jj++) {
            atomicAdd(&ssum[c4 + jj], (double)ps[jj]);
            atomicAdd(&ssq[c4 + jj], (double)pq[jj]);
        }
    }
    edge_pool_epilogue(acc, e0, r8, c4, tid, pair, sMx, sMn);
    if (tid < 64) {
        int bank = (blockIdx.x & (NBANK - 1)) * 8192;
        atomicAdd(&g_sumB[bank + oslot * 1024 + tid], ssum[tid]);
        atomicAdd(&g_sumsqB[bank + oslot * 1024 + tid], ssq[tid]);
    }
}

// ---------------------------------------------------------------------------
// Edge layers 3/5: gathered 128-dim edge feature @ W^T [64,128] + stats.
// doStore=1: write raw hA (L3). doStore=0: max/min pool to pair (L5).
// ---------------------------------------------------------------------------
__global__ __launch_bounds__(256) void k_edgeG128(const float* __restrict__ W,
                                                  int srcSel, int oslot,
                                                  int doStore, int pair) {
    __shared__ __align__(16) float As[16][132];
    __shared__ __align__(16) float Bs[16][68];
    __shared__ int sP[128], sQ[128];
    __shared__ double ssum[64], ssq[64];
    __shared__ unsigned sMx[512], sMn[512];
    const float* src = (srcSel == 1) ? g_x1 : g_x2;
    int e0 = blockIdx.x << 7, tid = threadIdx.x;
    if (tid < 64) { ssum[tid] = 0.0; ssq[tid] = 0.0; }
    for (int l = tid; l < 512; l += 256) { sMx[l] = 0u; sMn[l] = 0xFFFFFFFFu; }
    if (tid < 128) {
        int e = e0 + tid;
        int p = e / KNN;
        sP[tid] = p;
        sQ[tid] = (p >> 12) * NN + g_idx[e];
    }
    int tx = tid & 15, ty = tid >> 4;
    int r8 = ty << 3, c4 = tx << 2;
    float acc[8][4] = {};
    for (int k0 = 0; k0 < 128; k0 += 16) {
        __syncthreads();
#pragma unroll
        for (int l = tid; l < 512; l += 256) {
            int r = l >> 2, kq = (l & 3) << 2;
            int c = k0 + kq;
            float4 av;
            if (c < 64) {
                float4 aq = *(const float4*)&src[(size_t)sQ[r] * 64 + c];
                float4 ap = *(const float4*)&src[(size_t)sP[r] * 64 + c];
                av.x = aq.x - ap.x; av.y = aq.y - ap.y;
                av.z = aq.z - ap.z; av.w = aq.w - ap.w;
            } else {
                av = *(const float4*)&src[(size_t)sP[r] * 64 + (c - 64)];
            }
            As[kq + 0][r] = av.x; As[kq + 1][r] = av.y;
            As[kq + 2][r] = av.z; As[kq + 3][r] = av.w;
        }
        {
            int r = tid >> 2, kq = (tid & 3) << 2;
            float4 bv = *(const float4*)&W[(size_t)r * 128 + k0 + kq];
            Bs[kq + 0][r] = bv.x; Bs[kq + 1][r] = bv.y;
            Bs[kq + 2][r] = bv.z; Bs[kq + 3][r] = bv.w;
        }
        __syncthreads();
#pragma unroll
        for (int k = 0; k < 16; k++) {
            float a[8], bb[4];
            *(float4*)&a[0]  = *(const float4*)&As[k][r8];
            *(float4*)&a[4]  = *(const float4*)&As[k][r8 + 4];
            *(float4*)&bb[0] = *(const float4*)&Bs[k][c4];
#pragma unroll
            for (int ii = 0; ii < 8; ii++)
#pragma unroll
                for (int jj = 0; jj < 4; jj++)
                    acc[ii][jj] = fmaf(a[ii], bb[jj], acc[ii][jj]);
        }
    }
    if (doStore) {
#pragma unroll
        for (int ii = 0; ii < 8; ii++)
            *(float4*)&g_hA[(size_t)(e0 + r8 + ii) * 64 + c4] = *(float4*)&acc[ii][0];
    }
    float ps[4], pq[4];
#pragma unroll
    for (int jj = 0; jj < 4; jj++) {
        float s = 0.f, q = 0.f;
#pragma unroll
        for (int ii = 0; ii < 8; ii++) { float v = acc[ii][jj]; s += v; q = fmaf(v, v, q); }
        ps[jj] = s; pq[jj] = q;
    }
#pragma unroll
    for (int jj = 0; jj < 4; jj++) {
        ps[jj] += __shfl_down_sync(0xffffffffu, ps[jj], 16);
        pq[jj] += __shfl_down_sync(0xffffffffu, pq[jj], 16);
    }
    if ((tid & 31) < 16) {
#pragma unroll
        for (int jj = 0; jj < 4; jj++) {
            atomicAdd(&ssum[c4 + jj], (double)ps[jj]);
            atomicAdd(&ssq[c4 + jj], (double)pq[jj]);
        }
    }
    if (!doStore) {
        edge_pool_epilogue(acc, e0, r8, c4, tid, pair, sMx, sMn);
    } else {
        __syncthreads();
    }
    if (tid < 64) {
        int bank = (blockIdx.x & (NBANK - 1)) * 8192;
        atomicAdd(&g_sumB[bank + oslot * 1024 + tid], ssum[tid]);
        atomicAdd(&g_sumsqB[bank + oslot * 1024 + tid], ssq[tid]);
    }
}

// x{1,2,3}[p,c] = lrelu(sc * (sc>=0 ? rawmax : rawmin) + bi)
__global__ void k_maxfin(int pair, int slot, int outSel) {
    int t = blockIdx.x * 256 + threadIdx.x;
    if (t >= PT * 64) return;
    int c = t & 63;
    float sc = g_scale[slot * 1024 + c], bi = g_bias[slot * 1024 + c];
    unsigned u = (sc >= 0.f) ? g_emaxU[(size_t)pair * PT * 64 + t]
                             : g_eminU[(size_t)pair * PT * 64 + t];
    float* out = (outSel == 1) ? g_x1 : (outSel == 2 ? g_x2 : g_x3);
    out[t] = lrelu(sc * unford(u) + bi);
}

// ---------------------------------------------------------------------------
// Point GEMMs, 128x128 tile, 8x8/thread, k-sliced 16. Modes:
//   0: A=[x1,x2,x3](192) @ W6 -> NO store; per-(b,c) raw max/min + stats(5)
//   1: A=[x1,x2,x3](192) @ W7[:,1024:] + gcorr -> h7 (stats slot 6)
//   2: A=act6(h7)(512)   @ W8                  -> h8 (stats slot 7)
// ---------------------------------------------------------------------------
__global__ __launch_bounds__(256) void k_point128(const float* __restrict__ W,
                                                  int Cin, int Cout, int wstride,
                                                  int woff, int mode, int aslot,
                                                  int outSel) {
    __shared__ __align__(16) float As[16][132];
    __shared__ __align__(16) float Bs[16][132];
    __shared__ double ssum[128], ssq[128];
    __shared__ unsigned sMaxU[128], sMinU[128];
    int c0 = blockIdx.x << 7, r0 = blockIdx.y << 7;
    int tid = threadIdx.x, tx = tid & 15, ty = tid >> 4;
    int r8 = ty << 3, c8 = tx << 3;
    int b = r0 >> 12;
    if (tid < 128) {
        ssum[tid] = 0.0; ssq[tid] = 0.0;
        sMaxU[tid] = 0u; sMinU[tid] = 0xFFFFFFFFu;
    }
    float acc[8][8] = {};
    for (int k0 = 0; k0 < Cin; k0 += 16) {
        __syncthreads();
#pragma unroll
        for (int l = tid; l < 512; l += 256) {
            int r = l >> 2, kq = (l & 3) << 2;
            int c = k0 + kq, row = r0 + r;
            float4 av;
            if (mode != 2) {
                const float* sp = (c < 64) ? &g_x1[(size_t)row * 64 + c]
                               : (c < 128) ? &g_x2[(size_t)row * 64 + (c - 64)]
                                           : &g_x3[(size_t)row * 64 + (c - 128)];
                av = *(const float4*)sp;
            } else {
                av = *(const float4*)&g_h7[(size_t)row * 512 + c];
                av.x = lrelu(av.x * g_scale[aslot * 1024 + c + 0] + g_bias[aslot * 1024 + c + 0]);
                av.y = lrelu(av.y * g_scale[aslot * 1024 + c + 1] + g_bias[aslot * 1024 + c + 1]);
                av.z = lrelu(av.z * g_scale[aslot * 1024 + c + 2] + g_bias[aslot * 1024 + c + 2]);
                av.w = lrelu(av.w * g_scale[aslot * 1024 + c + 3] + g_bias[aslot * 1024 + c + 3]);
            }
            As[kq + 0][r] = av.x; As[kq + 1][r] = av.y;
            As[kq + 2][r] = av.z; As[kq + 3][r] = av.w;
            float4 bv = *(const float4*)&W[(size_t)(c0 + r) * wstride + woff + k0 + kq];
            Bs[kq + 0][r] = bv.x; Bs[kq + 1][r] = bv.y;
            Bs[kq + 2][r] = bv.z; Bs[kq + 3][r] = bv.w;
        }
        __syncthreads();
#pragma unroll
        for (int k = 0; k < 16; k++) {
            float a[8], bb[8];
            *(float4*)&a[0]  = *(const float4*)&As[k][r8];
            *(float4*)&a[4]  = *(const float4*)&As[k][r8 + 4];
            *(float4*)&bb[0] = *(const float4*)&Bs[k][c8];
            *(float4*)&bb[4] = *(const float4*)&Bs[k][c8 + 4];
#pragma unroll
            for (int ii = 0; ii < 8; ii++)
#pragma unroll
                for (int jj = 0; jj < 8; jj++)
                    acc[ii][jj] = fmaf(a[ii], bb[jj], acc[ii][jj]);
        }
    }
    if (mode == 1) {
#pragma unroll
        for (int jj = 0; jj < 8; jj++) {
            float gc = g_gcorr[b * 512 + c0 + c8 + jj];
#pragma unroll
            for (int ii = 0; ii < 8; ii++) acc[ii][jj] += gc;
        }
    }
    if (outSel != 0) {
        float* out = (outSel == 1) ? g_h7 : g_h8;
#pragma unroll
        for (int ii = 0; ii < 8; ii++) {
            float* dst = &out[(size_t)(r0 + r8 + ii) * Cout + c0 + c8];
            *(float4*)&dst[0] = *(float4*)&acc[ii][0];
            *(float4*)&dst[4] = *(float4*)&acc[ii][4];
        }
    }
    int slot = 5 + outSel;
    float ps[8], pq[8];
#pragma unroll
    for (int jj = 0; jj < 8; jj++) {
        float s = 0.f, q = 0.f;
#pragma unroll
        for (int ii = 0; ii < 8; ii++) { float v = acc[ii][jj]; s += v; q = fmaf(v, v, q); }
        ps[jj] = s; pq[jj] = q;
    }
#pragma unroll
    for (int jj = 0; jj < 8; jj++) {
        ps[jj] += __shfl_down_sync(0xffffffffu, ps[jj], 16);
        pq[jj] += __shfl_down_sync(0xffffffffu, pq[jj], 16);
    }
    if ((tid & 31) < 16) {
#pragma unroll
        for (int jj = 0; jj < 8; jj++) {
            atomicAdd(&ssum[c8 + jj], (double)ps[jj]);
            atomicAdd(&ssq[c8 + jj], (double)pq[jj]);
        }
    }
    if (outSel == 0) {
        float mx[8], mn[8];
#pragma unroll
        for (int jj = 0; jj < 8; jj++) {
            float a = acc[0][jj], c = acc[0][jj];
#pragma unroll
            for (int ii = 1; ii < 8; ii++) {
                a = fmaxf(a, acc[ii][jj]);
                c = fminf(c, acc[ii][jj]);
            }
            mx[jj] = a; mn[jj] = c;
        }
#pragma unroll
        for (int jj = 0; jj < 8; jj++) {
            mx[jj] = fmaxf(mx[jj], __shfl_down_sync(0xffffffffu, mx[jj], 16));
            mn[jj] = fminf(mn[jj], __shfl_down_sync(0xffffffffu, mn[jj], 16));
        }
        if ((tid & 31) < 16) {
#pragma unroll
            for (int jj = 0; jj < 8; jj++) {
                atomicMax(&sMaxU[c8 + jj], ford(mx[jj]));
                atomicMin(&sMinU[c8 + jj], ford(mn[jj]));
            }
        }
    }
    __syncthreads();
    if (tid < 128) {
        int bank = (blockIdx.y & (NBANK - 1)) * 8192;
        atomicAdd(&g_sumB[bank + slot * 1024 + c0 + tid], ssum[tid]);
        atomicAdd(&g_sumsqB[bank + slot * 1024 + c0 + tid], ssq[tid]);
        if (outSel == 0) {
            atomicMax(&g_hmaxU[b * 1024 + c0 + tid], sMaxU[tid]);
            atomicMin(&g_hminU[b * 1024 + c0 + tid], sMinU[tid]);
        }
    }
}

// gmax[b,c] = lrelu(sc * (sc>=0 ? hmax : hmin) + bi)   (monotone pooling)
__global__ void k_gmaxfin() {
    int t = blockIdx.x * 256 + threadIdx.x;
    if (t >= BB * 1024) return;
    int c = t & 1023;
    float sc = g_scale[5 * 1024 + c], bi = g_bias[5 * 1024 + c];
    unsigned u = (sc >= 0.f) ? g_hmaxU[t] : g_hminU[t];
    g_gmax[t] = lrelu(sc * unford(u) + bi);
}

// gcorr[b,o] = sum_c gmax[b,c] * W7[o,c]  (c < 1024); warp per output
__global__ void k_gcorr(const float* __restrict__ W7) {
    int b = blockIdx.y;
    int o = blockIdx.x * 8 + (threadIdx.x >> 5);
    int lane = threadIdx.x & 31;
    const float* gm = g_gmax + b * 1024;
    const float* w  = W7 + (size_t)o * 1216;
    float s = 0.f;
#pragma unroll 8
    for (int k = lane; k < 1024; k += 32) s = fmaf(gm[k], w[k], s);
#pragma unroll
    for (int off = 16; off; off >>= 1) s += __shfl_down_sync(0xffffffffu, s, off);
    if (lane == 0) g_gcorr[b * 512 + o] = s;
}

// fold (gamma, beta, mean, var) -> per-channel scale/bias (sums 16 banks)
__global__ void k_fin(int slot, int C, double invM,
                      const float* __restrict__ g, const float* __restrict__ b) {
    int c = blockIdx.x * 256 + threadIdx.x;
    if (c >= C) return;
    double sm = 0.0, sq = 0.0;
#pragma unroll
    for (int k = 0; k < NBANK; k++) {
        sm += g_sumB[k * 8192 + slot * 1024 + c];
        sq += g_sumsqB[k * 8192 + slot * 1024 + c];
    }
    double mean = sm * invM;
    double var  = sq * invM - mean * mean;
    float sc    = g[c] * rsqrtf((float)var + EPSBN);
    g_scale[slot * 1024 + c] = sc;
    g_bias[slot * 1024 + c]  = b[c] - (float)mean * sc;
}

// ---------------------------------------------------------------------------
// Final: out[P,9] = act7(h8) @ W9^T
// ---------------------------------------------------------------------------
__global__ void k_out9(const float* __restrict__ W9, float* __restrict__ out) {
    int t = blockIdx.x * 256 + threadIdx.x;
    if (t >= PT * 9) return;
    int p = t / 9, o = t - p * 9;
    const float* row = g_h8 + (size_t)p * 256;
    const float* w   = W9 + o * 256;
    float acc = 0.f;
#pragma unroll 4
    for (int k = 0; k < 256; k++) {
        float v = lrelu(row[k] * g_scale[7 * 1024 + k] + g_bias[7 * 1024 + k]);
        acc = fmaf(v, w[k], acc);
    }
    out[t] = acc;
}

// ---------------------------------------------------------------------------
// Host launcher
// ---------------------------------------------------------------------------
extern "C" void kernel_launch(void* const* d_in, const int* in_sizes, int n_in,
                              void* d_out, int out_size) {
    int base = (in_sizes[1] == 1) ? 2 : 1;
    const float* x = (const float*)d_in[0];
    const float* W[9];
    const float* G[8];
    const float* Bt[8];
    for (int i = 0; i < 9; i++) W[i] = (const float*)d_in[base + i];
    for (int i = 0; i < 8; i++) {
        G[i]  = (const float*)d_in[base + 9 + 2 * i];
        Bt[i] = (const float*)d_in[base + 10 + 2 * i];
    }
    float* out = (float*)d_out;

    const double invE = 1.0 / (double)ET;
    const double invP = 1.0 / (double)PT;

    k_zero<<<(NBANK * 8 * 1024) / 256, 256>>>();
    k_zmm<<<(3 * PT * 64 / 4 + 255) / 256, 256>>>();
    k_prep3<<<PT / 256, 256>>>(x);

    // ---- stage 1: fused knn on xyz, edge layers 1-2, maxpool -> x1 ----
    k_topk3<<<PT, 256>>>();
    k_edge1<<<ET / 256, 256>>>(W[0]);
    k_fin<<<1, 256>>>(0, 64, invE, G[0], Bt[0]);
    k_edge128<<<ET / 128, 256>>>(W[1], 0, 1, 0);
    k_fin<<<1, 256>>>(1, 64, invE, G[1], Bt[1]);
    k_maxfin<<<PT * 64 / 256, 256>>>(0, 1, 1);

    // ---- stage 2: knn on x1, edge layers 3-4, maxpool -> x2 ----
    k_xx64<<<PT * 32 / 256, 256>>>(1);
    k_dist128sym<<<dim3(528, BB), 256>>>(1);
    k_topk<<<PT, 256>>>();
    k_edgeG128<<<ET / 128, 256>>>(W[2], 1, 2, 1, 0);
    k_fin<<<1, 256>>>(2, 64, invE, G[2], Bt[2]);
    k_edge128<<<ET / 128, 256>>>(W[3], 2, 3, 1);
    k_fin<<<1, 256>>>(3, 64, invE, G[3], Bt[3]);
    k_maxfin<<<PT * 64 / 256, 256>>>(1, 3, 2);

    // ---- stage 3: knn on x2, edge layer 5, maxpool -> x3 ----
    k_xx64<<<PT * 32 / 256, 256>>>(2);
    k_dist128sym<<<dim3(528, BB), 256>>>(2);
    k_topk<<<PT, 256>>>();
    k_edgeG128<<<ET / 128, 256>>>(W[4], 2, 4, 0, 2);
    k_fin<<<1, 256>>>(4, 64, invE, G[4], Bt[4]);
    k_maxfin<<<PT * 64 / 256, 256>>>(2, 4, 3);

    // ---- point layers 6-9 ----
    k_point128<<<dim3(8, PT / 128), 256>>>(W[5], 192, 1024, 192, 0, 0, 0, 0);
    k_fin<<<4, 256>>>(5, 1024, invP, G[5], Bt[5]);
    k_gmaxfin<<<32, 256>>>();
    k_gcorr<<<dim3(64, BB), 256>>>(W[6]);
    k_point128<<<dim3(4, PT / 128), 256>>>(W[6], 192, 512, 1216, 1024, 1, 0, 1);
    k_fin<<<2, 256>>>(6, 512, invP, G[6], Bt[6]);
    k_point128<<<dim3(2, PT / 128), 256>>>(W[7], 512, 256, 512, 0, 2, 6, 2);
    k_fin<<<1, 256>>>(7, 256, invP, G[7], Bt[7]);
    k_out9<<<(PT * 9 + 255) / 256, 256>>>(W[8], out);
}